// round 1
// baseline (speedup 1.0000x reference)
#include <cuda_runtime.h>
#include <math.h>

#define BB 4
#define CC 64
#define NNq 4096   // N = H*W

// ---------------- device scratch (sanctioned __device__ globals) ----------------
__device__ float g_q[BB*CC*NNq];            // 4 MB
__device__ float g_k[BB*CC*NNq];            // 4 MB
__device__ float g_v[BB*CC*NNq];            // 4 MB
__device__ float g_m[BB*NNq];               // 64 KB
__device__ float g_E[(size_t)BB*NNq*NNq];   // 256 MiB: exp(qk)
__device__ float g_rowsum[BB*NNq];
__device__ float g_invrs[BB*NNq];
__device__ float g_qsum[BB*CC];
__device__ float g_ksum[BB*CC];

// fast exp: x -> 2^(x*log2e), degree-4 poly on [-0.5,0.5], rel err ~4e-5
__device__ __forceinline__ float fexp(float v){
    float y = v * 1.44269504088896341f;
    float t = y + 12582912.0f;                 // round-to-nearest int (magic)
    int   e = __float_as_int(t) - 0x4B400000;  // integer part
    float f = y - (t - 12582912.0f);           // frac in [-0.5, 0.5]
    float p = 0.00961804886f;
    p = p*f + 0.05550410866f;
    p = p*f + 0.24022650696f;
    p = p*f + 0.69314718056f;
    p = p*f + 1.0f;
    return __int_as_float(__float_as_int(p) + (e << 23));
}

// ---------------- K0: zero accumulators (must re-zero every graph replay) ------
__global__ void DNL_k0_zero(){
    int i = blockIdx.x*blockDim.x + threadIdx.x;
    if (i < BB*NNq) g_rowsum[i] = 0.0f;
    if (i < BB*CC){ g_qsum[i] = 0.0f; g_ksum[i] = 0.0f; }
}

// helper: 64x64 weight (smem, row stride 65) times x tile (smem [64][128])
__device__ __forceinline__ void conv_acc(const float* __restrict__ wsm,
                                         const float* __restrict__ xs,
                                         const float* __restrict__ bias,
                                         int o0, int n0, float acc[4][8]){
    #pragma unroll
    for (int i=0;i<4;i++){
        float bv = bias[o0+i];
        #pragma unroll
        for (int j=0;j<8;j++) acc[i][j] = bv;
    }
    #pragma unroll 8
    for (int c=0;c<64;c++){
        float4 x0 = *(const float4*)(xs + (c<<7) + n0);
        float4 x1 = *(const float4*)(xs + (c<<7) + n0 + 4);
        #pragma unroll
        for (int i=0;i<4;i++){
            float w = wsm[(o0+i)*65 + c];
            acc[i][0] += w*x0.x; acc[i][1] += w*x0.y;
            acc[i][2] += w*x0.z; acc[i][3] += w*x0.w;
            acc[i][4] += w*x1.x; acc[i][5] += w*x1.y;
            acc[i][6] += w*x1.z; acc[i][7] += w*x1.w;
        }
    }
}

// ---------------- K1: q,k,v,m and BN(wx) -> out; mean partial sums -------------
// grid (32 n-tiles, 4 b), 256 threads, dyn smem = 24960 floats
__global__ __launch_bounds__(256) void DNL_k1(
    const float* __restrict__ x,
    const float* __restrict__ qw, const float* __restrict__ qb,
    const float* __restrict__ kw, const float* __restrict__ kb,
    const float* __restrict__ mw, const float* __restrict__ mb,
    const float* __restrict__ vw, const float* __restrict__ vb,
    const float* __restrict__ ww, const float* __restrict__ wb,
    const float* __restrict__ bng, const float* __restrict__ bnb,
    const float* __restrict__ bnrm, const float* __restrict__ bnrv,
    float* __restrict__ out)
{
    extern __shared__ float sm[];
    float* xs  = sm;               // 64*128
    float* wq  = xs  + 64*128;     // 64*65 each
    float* wk  = wq  + 64*65;
    float* wv  = wk  + 64*65;
    float* wwt = wv  + 64*65;
    float* qs  = wwt + 64*65;      // 64
    float* ks  = qs  + 64;         // 64

    int b = blockIdx.y, nt = blockIdx.x;
    int nb = nt << 7;
    int tid = threadIdx.x;

    if (tid < 64){ qs[tid] = 0.0f; ks[tid] = 0.0f; }
    for (int idx = tid; idx < 64*128; idx += 256){
        int c = idx >> 7, pos = idx & 127;
        xs[idx] = x[(((b<<6)+c)<<12) + nb + pos];
    }
    for (int idx = tid; idx < 64*64; idx += 256){
        int o = idx >> 6, c = idx & 63;
        int so = o*65 + c;
        wq[so] = qw[idx]; wk[so] = kw[idx]; wv[so] = vw[idx]; wwt[so] = ww[idx];
    }
    __syncthreads();

    // m branch (1 output channel)
    if (tid < 128){
        float a = mb[0];
        #pragma unroll 8
        for (int c=0;c<64;c++) a += mw[c]*xs[(c<<7) + tid];
        g_m[(b<<12) + nb + tid] = a;
    }

    int tx = tid & 15, ty = tid >> 4;
    int n0 = tx << 3, o0 = ty << 2;
    float acc[4][8];

    // Q
    conv_acc(wq, xs, qb, o0, n0, acc);
    #pragma unroll
    for (int i=0;i<4;i++){
        float* dst = g_q + ((((size_t)(b<<6)+o0+i)<<12) + nb + n0);
        *(float4*)dst     = make_float4(acc[i][0],acc[i][1],acc[i][2],acc[i][3]);
        *(float4*)(dst+4) = make_float4(acc[i][4],acc[i][5],acc[i][6],acc[i][7]);
        float s = acc[i][0]+acc[i][1]+acc[i][2]+acc[i][3]
                 +acc[i][4]+acc[i][5]+acc[i][6]+acc[i][7];
        atomicAdd(&qs[o0+i], s);
    }
    // K
    conv_acc(wk, xs, kb, o0, n0, acc);
    #pragma unroll
    for (int i=0;i<4;i++){
        float* dst = g_k + ((((size_t)(b<<6)+o0+i)<<12) + nb + n0);
        *(float4*)dst     = make_float4(acc[i][0],acc[i][1],acc[i][2],acc[i][3]);
        *(float4*)(dst+4) = make_float4(acc[i][4],acc[i][5],acc[i][6],acc[i][7]);
        float s = acc[i][0]+acc[i][1]+acc[i][2]+acc[i][3]
                 +acc[i][4]+acc[i][5]+acc[i][6]+acc[i][7];
        atomicAdd(&ks[o0+i], s);
    }
    // V
    conv_acc(wv, xs, vb, o0, n0, acc);
    #pragma unroll
    for (int i=0;i<4;i++){
        float* dst = g_v + ((((size_t)(b<<6)+o0+i)<<12) + nb + n0);
        *(float4*)dst     = make_float4(acc[i][0],acc[i][1],acc[i][2],acc[i][3]);
        *(float4*)(dst+4) = make_float4(acc[i][4],acc[i][5],acc[i][6],acc[i][7]);
    }
    // W + BatchNorm (eval) -> initialize out with residual path
    conv_acc(wwt, xs, wb, o0, n0, acc);
    #pragma unroll
    for (int i=0;i<4;i++){
        int o = o0 + i;
        float sc = bng[o] * rsqrtf(bnrv[o] + 1e-5f);
        float sh = bnb[o] - bnrm[o]*sc;
        float* dst = out + (((size_t)(b<<6)+o)<<12) + nb + n0;
        *(float4*)dst     = make_float4(acc[i][0]*sc+sh, acc[i][1]*sc+sh,
                                        acc[i][2]*sc+sh, acc[i][3]*sc+sh);
        *(float4*)(dst+4) = make_float4(acc[i][4]*sc+sh, acc[i][5]*sc+sh,
                                        acc[i][6]*sc+sh, acc[i][7]*sc+sh);
    }
    __syncthreads();
    if (tid < 64){
        atomicAdd(&g_qsum[(b<<6)+tid], qs[tid]);
        atomicAdd(&g_ksum[(b<<6)+tid], ks[tid]);
    }
}

// ---------------- K2: subtract per-(b,c) means ----------------------------------
__global__ void DNL_k2_whiten(){
    int i = blockIdx.x*blockDim.x + threadIdx.x;   // BB*CC*NNq = 1,048,576
    if (i < BB*CC*NNq){
        int bc = i >> 12;
        g_k[i] -= g_ksum[bc] * (1.0f/NNq);
        g_q[i] -= g_qsum[bc] * (1.0f/NNq);
    }
}

// ---------------- K3: E = exp(K^T Q) + rowsums ----------------------------------
// grid (jt=32, it=32, b=4), 256 threads, dyn smem = 18432 floats
__global__ __launch_bounds__(256) void DNL_k3(){
    extern __shared__ float sm[];
    float* Kt = sm;               // 64*128
    float* Qt = Kt + 8192;        // 64*128
    float* rp = Qt + 8192;        // 128*16
    int jt = blockIdx.x, it = blockIdx.y, b = blockIdx.z;
    int tid = threadIdx.x;

    for (int idx = tid; idx < 8192; idx += 256){
        int c = idx >> 7, pos = idx & 127;
        Kt[idx] = g_k[(((b<<6)+c)<<12) + (it<<7) + pos];
        Qt[idx] = g_q[(((b<<6)+c)<<12) + (jt<<7) + pos];
    }
    __syncthreads();

    int tx = tid & 15, ty = tid >> 4;
    int j0 = tx << 3, i0 = ty << 3;
    float acc[8][8];
    #pragma unroll
    for (int i=0;i<8;i++)
        #pragma unroll
        for (int j=0;j<8;j++) acc[i][j] = 0.0f;

    #pragma unroll 4
    for (int c=0;c<64;c++){
        float4 ka = *(const float4*)(Kt + (c<<7) + i0);
        float4 kb4= *(const float4*)(Kt + (c<<7) + i0 + 4);
        float4 qa = *(const float4*)(Qt + (c<<7) + j0);
        float4 qb4= *(const float4*)(Qt + (c<<7) + j0 + 4);
        float kk[8] = {ka.x,ka.y,ka.z,ka.w,kb4.x,kb4.y,kb4.z,kb4.w};
        float qq[8] = {qa.x,qa.y,qa.z,qa.w,qb4.x,qb4.y,qb4.z,qb4.w};
        #pragma unroll
        for (int i=0;i<8;i++)
            #pragma unroll
            for (int j=0;j<8;j++) acc[i][j] += kk[i]*qq[j];
    }

    float* Eb = g_E + ((size_t)b << 24);   // N*N = 2^24
    #pragma unroll
    for (int r=0;r<8;r++){
        float pv[8]; float s = 0.0f;
        #pragma unroll
        for (int j=0;j<8;j++){ float p = fexp(acc[r][j]); pv[j] = p; s += p; }
        int row = (it<<7) + i0 + r;
        float* dst = Eb + (((size_t)row)<<12) + (jt<<7) + j0;
        *(float4*)dst     = make_float4(pv[0],pv[1],pv[2],pv[3]);
        *(float4*)(dst+4) = make_float4(pv[4],pv[5],pv[6],pv[7]);
        rp[((i0+r)<<4) + tx] = s;
    }
    __syncthreads();
    if (tid < 128){
        float s = 0.0f;
        #pragma unroll
        for (int t=0;t<16;t++) s += rp[(tid<<4)+t];
        atomicAdd(&g_rowsum[(b<<12) + (it<<7) + tid], s);
    }
}

// ---------------- K3b: reciprocal row sums --------------------------------------
__global__ void DNL_k3b(){
    int i = blockIdx.x*blockDim.x + threadIdx.x;
    if (i < BB*NNq) g_invrs[i] = 1.0f / g_rowsum[i];
}

// ---------------- K4: fused F = softmax(qk) + softmax_b(mm); y += V*F ----------
// grid (mt=64, nc=8), 256 threads, batches fused; dyn smem = 33792 floats
__global__ __launch_bounds__(256) void DNL_k4(float* __restrict__ out){
    extern __shared__ float sm[];
    float* Ft  = sm;              // 4*4096
    float* Vt  = Ft + 16384;      // 4*64*65
    float* mvm = Vt + 16640;      // 256
    float* mvn = mvm + 256;       // 256
    float* irs = mvn + 256;       // 256

    int mt = blockIdx.x, nc = blockIdx.y;
    int tid = threadIdx.x;
    int mbase = mt << 6;

    { int bb = tid >> 6, j = tid & 63; mvm[tid] = g_m[(bb<<12) + mbase + j]; }

    int g  = tid >> 6;            // batch handled in GEMM phase
    int t  = tid & 63;
    int m0 = (t & 7) << 3, c0 = (t >> 3) << 3;
    float acc[8][8];
    #pragma unroll
    for (int i=0;i<8;i++)
        #pragma unroll
        for (int j=0;j<8;j++) acc[i][j] = 0.0f;

    for (int ntile = 0; ntile < 8; ntile++){
        int nbase = ((nc<<3) + ntile) << 6;
        { int bb = tid >> 6, ii = tid & 63;
          mvn[tid] = g_m[(bb<<12) + nbase + ii];
          irs[tid] = g_invrs[(bb<<12) + nbase + ii]; }
        for (int idx = tid; idx < 4*4096; idx += 256){
            int bb = idx >> 12, rem = idx & 4095;
            int c = rem >> 6, nn2 = rem & 63;
            Vt[bb*4160 + c*65 + nn2] = g_v[(((bb<<6)+c)<<12) + nbase + nn2];
        }
        __syncthreads();

        // F tiles for all 4 batches (shares the mm exps + denominator)
        for (int p = tid; p < 4096; p += 256){
            int nn2 = p >> 6, mm2 = p & 63;
            float e0 = fexp(mvn[nn2]      * mvm[mm2]);
            float e1 = fexp(mvn[64+nn2]   * mvm[64+mm2]);
            float e2 = fexp(mvn[128+nn2]  * mvm[128+mm2]);
            float e3 = fexp(mvn[192+nn2]  * mvm[192+mm2]);
            float Di = 1.0f/(e0+e1+e2+e3);
            size_t eb = (((size_t)(nbase+nn2))<<12) + mbase + mm2;
            Ft[p]         = g_E[eb]               * irs[nn2]      + e0*Di;
            Ft[4096 + p]  = g_E[(1ULL<<24) + eb]  * irs[64+nn2]   + e1*Di;
            Ft[8192 + p]  = g_E[(2ULL<<24) + eb]  * irs[128+nn2]  + e2*Di;
            Ft[12288 + p] = g_E[(3ULL<<24) + eb]  * irs[192+nn2]  + e3*Di;
        }
        __syncthreads();

        // y_g[c0..+7, m0..+7] += V_g * F_g over this 64-wide n tile
        const float* Fg = Ft + (g << 12);
        const float* Vg = Vt + g*4160;
        #pragma unroll 4
        for (int nn2=0; nn2<64; nn2++){
            float4 f0 = *(const float4*)(Fg + (nn2<<6) + m0);
            float4 f1 = *(const float4*)(Fg + (nn2<<6) + m0 + 4);
            float ff[8] = {f0.x,f0.y,f0.z,f0.w,f1.x,f1.y,f1.z,f1.w};
            float vv[8];
            #pragma unroll
            for (int i=0;i<8;i++) vv[i] = Vg[(c0+i)*65 + nn2];
            #pragma unroll
            for (int i=0;i<8;i++)
                #pragma unroll
                for (int j=0;j<8;j++) acc[i][j] += vv[i]*ff[j];
        }
        __syncthreads();
    }

    #pragma unroll
    for (int i=0;i<8;i++)
        #pragma unroll
        for (int j=0;j<8;j++)
            atomicAdd(&out[(((size_t)(g<<6)+c0+i)<<12) + mbase + m0 + j], acc[i][j]);
}

// ---------------- host launcher -------------------------------------------------
extern "C" void kernel_launch(void* const* d_in, const int* in_sizes, int n_in,
                              void* d_out, int out_size)
{
    const float* x    = (const float*)d_in[0];
    const float* qw   = (const float*)d_in[1];
    const float* qb   = (const float*)d_in[2];
    const float* kw   = (const float*)d_in[3];
    const float* kb   = (const float*)d_in[4];
    const float* mw   = (const float*)d_in[5];
    const float* mb   = (const float*)d_in[6];
    const float* vw   = (const float*)d_in[7];
    const float* vb   = (const float*)d_in[8];
    const float* ww   = (const float*)d_in[9];
    const float* wb   = (const float*)d_in[10];
    const float* bng  = (const float*)d_in[11];
    const float* bnb  = (const float*)d_in[12];
    const float* bnrm = (const float*)d_in[13];
    const float* bnrv = (const float*)d_in[14];
    float* out = (float*)d_out;

    const int SM1 = 24960*4;   // ~99.8 KB
    const int SM3 = 18432*4;   // 72 KB
    const int SM4 = 33792*4;   // 132 KB
    cudaFuncSetAttribute(DNL_k1, cudaFuncAttributeMaxDynamicSharedMemorySize, SM1);
    cudaFuncSetAttribute(DNL_k3, cudaFuncAttributeMaxDynamicSharedMemorySize, SM3);
    cudaFuncSetAttribute(DNL_k4, cudaFuncAttributeMaxDynamicSharedMemorySize, SM4);

    DNL_k0_zero<<<64, 256>>>();
    DNL_k1<<<dim3(32,4), 256, SM1>>>(x, qw,qb, kw,kb, mw,mb, vw,vb, ww,wb,
                                     bng,bnb,bnrm,bnrv, out);
    DNL_k2_whiten<<<4096, 256>>>();
    DNL_k3<<<dim3(32,32,4), 256, SM3>>>();
    DNL_k3b<<<64, 256>>>();
    DNL_k4<<<dim3(64,8), 256, SM4>>>(out);
}

// round 3
// speedup vs baseline: 1.0196x; 1.0196x over previous
#include <cuda_runtime.h>
#include <math.h>

#define BB 4
#define CC 64
#define NNq 4096   // N = H*W

// ---------------- device scratch (sanctioned __device__ globals) ----------------
__device__ float g_q[BB*CC*NNq];            // 4 MB
__device__ float g_k[BB*CC*NNq];            // 4 MB
__device__ float g_v[BB*CC*NNq];            // 4 MB
__device__ float g_m[BB*NNq];               // 64 KB
__device__ float g_E[(size_t)BB*NNq*NNq];   // 256 MiB: exp(qk)
__device__ float g_Dinv[(size_t)NNq*NNq];   // 64 MiB: 1/sum_b exp(mm)
__device__ float g_rowsum[BB*NNq];
__device__ float g_invrs[BB*NNq];
__device__ float g_qsum[BB*CC];
__device__ float g_ksum[BB*CC];

// fast exp: x -> 2^(x*log2e), degree-4 poly on [-0.5,0.5], rel err ~4e-5
__device__ __forceinline__ float fexp(float v){
    float y = v * 1.44269504088896341f;
    float t = y + 12582912.0f;                 // round-to-nearest int (magic)
    int   e = __float_as_int(t) - 0x4B400000;  // integer part
    float f = y - (t - 12582912.0f);           // frac in [-0.5, 0.5]
    float p = 0.00961804886f;
    p = p*f + 0.05550410866f;
    p = p*f + 0.24022650696f;
    p = p*f + 0.69314718056f;
    p = p*f + 1.0f;
    return __int_as_float(__float_as_int(p) + (e << 23));
}

// ---------------- K0: zero accumulators (must re-zero every graph replay) ------
__global__ void DNL_k0_zero(){
    int i = blockIdx.x*blockDim.x + threadIdx.x;
    if (i < BB*NNq) g_rowsum[i] = 0.0f;
    if (i < BB*CC){ g_qsum[i] = 0.0f; g_ksum[i] = 0.0f; }
}

// helper: 64x64 weight (smem, row stride 65) times x tile (smem [64][128])
__device__ __forceinline__ void conv_acc(const float* __restrict__ wsm,
                                         const float* __restrict__ xs,
                                         const float* __restrict__ bias,
                                         int o0, int n0, float acc[4][8]){
    #pragma unroll
    for (int i=0;i<4;i++){
        float bv = bias[o0+i];
        #pragma unroll
        for (int j=0;j<8;j++) acc[i][j] = bv;
    }
    #pragma unroll 8
    for (int c=0;c<64;c++){
        float4 x0 = *(const float4*)(xs + (c<<7) + n0);
        float4 x1 = *(const float4*)(xs + (c<<7) + n0 + 4);
        #pragma unroll
        for (int i=0;i<4;i++){
            float w = wsm[(o0+i)*65 + c];
            acc[i][0] += w*x0.x; acc[i][1] += w*x0.y;
            acc[i][2] += w*x0.z; acc[i][3] += w*x0.w;
            acc[i][4] += w*x1.x; acc[i][5] += w*x1.y;
            acc[i][6] += w*x1.z; acc[i][7] += w*x1.w;
        }
    }
}

// ---------------- K1: q,k,v,m and BN(wx) -> out; mean partial sums -------------
// grid (32 n-tiles, 4 b), 256 threads, dyn smem = 24960 floats
__global__ __launch_bounds__(256) void DNL_k1(
    const float* __restrict__ x,
    const float* __restrict__ qw, const float* __restrict__ qb,
    const float* __restrict__ kw, const float* __restrict__ kb,
    const float* __restrict__ mw, const float* __restrict__ mb,
    const float* __restrict__ vw, const float* __restrict__ vb,
    const float* __restrict__ ww, const float* __restrict__ wb,
    const float* __restrict__ bng, const float* __restrict__ bnb,
    const float* __restrict__ bnrm, const float* __restrict__ bnrv,
    float* __restrict__ out)
{
    extern __shared__ float sm[];
    float* xs  = sm;               // 64*128
    float* wq  = xs  + 64*128;     // 64*65 each
    float* wk  = wq  + 64*65;
    float* wv  = wk  + 64*65;
    float* wwt = wv  + 64*65;
    float* qs  = wwt + 64*65;      // 64
    float* ks  = qs  + 64;         // 64

    int b = blockIdx.y, nt = blockIdx.x;
    int nb = nt << 7;
    int tid = threadIdx.x;

    if (tid < 64){ qs[tid] = 0.0f; ks[tid] = 0.0f; }
    for (int idx = tid; idx < 64*128; idx += 256){
        int c = idx >> 7, pos = idx & 127;
        xs[idx] = x[(((b<<6)+c)<<12) + nb + pos];
    }
    for (int idx = tid; idx < 64*64; idx += 256){
        int o = idx >> 6, c = idx & 63;
        int so = o*65 + c;
        wq[so] = qw[idx]; wk[so] = kw[idx]; wv[so] = vw[idx]; wwt[so] = ww[idx];
    }
    __syncthreads();

    // m branch (1 output channel)
    if (tid < 128){
        float a = mb[0];
        #pragma unroll 8
        for (int c=0;c<64;c++) a += mw[c]*xs[(c<<7) + tid];
        g_m[(b<<12) + nb + tid] = a;
    }

    int tx = tid & 15, ty = tid >> 4;
    int n0 = tx << 3, o0 = ty << 2;
    float acc[4][8];

    // Q
    conv_acc(wq, xs, qb, o0, n0, acc);
    #pragma unroll
    for (int i=0;i<4;i++){
        float* dst = g_q + ((((size_t)(b<<6)+o0+i)<<12) + nb + n0);
        *(float4*)dst     = make_float4(acc[i][0],acc[i][1],acc[i][2],acc[i][3]);
        *(float4*)(dst+4) = make_float4(acc[i][4],acc[i][5],acc[i][6],acc[i][7]);
        float s = acc[i][0]+acc[i][1]+acc[i][2]+acc[i][3]
                 +acc[i][4]+acc[i][5]+acc[i][6]+acc[i][7];
        atomicAdd(&qs[o0+i], s);
    }
    // K
    conv_acc(wk, xs, kb, o0, n0, acc);
    #pragma unroll
    for (int i=0;i<4;i++){
        float* dst = g_k + ((((size_t)(b<<6)+o0+i)<<12) + nb + n0);
        *(float4*)dst     = make_float4(acc[i][0],acc[i][1],acc[i][2],acc[i][3]);
        *(float4*)(dst+4) = make_float4(acc[i][4],acc[i][5],acc[i][6],acc[i][7]);
        float s = acc[i][0]+acc[i][1]+acc[i][2]+acc[i][3]
                 +acc[i][4]+acc[i][5]+acc[i][6]+acc[i][7];
        atomicAdd(&ks[o0+i], s);
    }
    // V
    conv_acc(wv, xs, vb, o0, n0, acc);
    #pragma unroll
    for (int i=0;i<4;i++){
        float* dst = g_v + ((((size_t)(b<<6)+o0+i)<<12) + nb + n0);
        *(float4*)dst     = make_float4(acc[i][0],acc[i][1],acc[i][2],acc[i][3]);
        *(float4*)(dst+4) = make_float4(acc[i][4],acc[i][5],acc[i][6],acc[i][7]);
    }
    // W + BatchNorm (eval) -> initialize out with residual path
    conv_acc(wwt, xs, wb, o0, n0, acc);
    #pragma unroll
    for (int i=0;i<4;i++){
        int o = o0 + i;
        float sc = bng[o] * rsqrtf(bnrv[o] + 1e-5f);
        float sh = bnb[o] - bnrm[o]*sc;
        float* dst = out + (((size_t)(b<<6)+o)<<12) + nb + n0;
        *(float4*)dst     = make_float4(acc[i][0]*sc+sh, acc[i][1]*sc+sh,
                                        acc[i][2]*sc+sh, acc[i][3]*sc+sh);
        *(float4*)(dst+4) = make_float4(acc[i][4]*sc+sh, acc[i][5]*sc+sh,
                                        acc[i][6]*sc+sh, acc[i][7]*sc+sh);
    }
    __syncthreads();
    if (tid < 64){
        atomicAdd(&g_qsum[(b<<6)+tid], qs[tid]);
        atomicAdd(&g_ksum[(b<<6)+tid], ks[tid]);
    }
}

// ---------------- K3: E = exp(K_w^T Q_w) + rowsums (whiten fused in loads) ------
// grid (jt=32, it=32, b=4), 256 threads, dyn smem = 18560 floats
__global__ __launch_bounds__(256) void DNL_k3(){
    extern __shared__ float sm[];
    float* Kt = sm;               // 64*128
    float* Qt = Kt + 8192;        // 64*128
    float* rp = Qt + 8192;        // 128*16
    float* kmean = rp + 2048;     // 64
    float* qmean = kmean + 64;    // 64
    int jt = blockIdx.x, it = blockIdx.y, b = blockIdx.z;
    int tid = threadIdx.x;

    if (tid < 64){
        kmean[tid] = g_ksum[(b<<6)+tid] * (1.0f/NNq);
        qmean[tid] = g_qsum[(b<<6)+tid] * (1.0f/NNq);
    }
    __syncthreads();
    for (int idx = tid; idx < 8192; idx += 256){
        int c = idx >> 7, pos = idx & 127;
        Kt[idx] = g_k[(((b<<6)+c)<<12) + (it<<7) + pos] - kmean[c];
        Qt[idx] = g_q[(((b<<6)+c)<<12) + (jt<<7) + pos] - qmean[c];
    }
    __syncthreads();

    int tx = tid & 15, ty = tid >> 4;
    int j0 = tx << 3, i0 = ty << 3;
    float acc[8][8];
    #pragma unroll
    for (int i=0;i<8;i++)
        #pragma unroll
        for (int j=0;j<8;j++) acc[i][j] = 0.0f;

    #pragma unroll 4
    for (int c=0;c<64;c++){
        float4 ka = *(const float4*)(Kt + (c<<7) + i0);
        float4 kb4= *(const float4*)(Kt + (c<<7) + i0 + 4);
        float4 qa = *(const float4*)(Qt + (c<<7) + j0);
        float4 qb4= *(const float4*)(Qt + (c<<7) + j0 + 4);
        float kk[8] = {ka.x,ka.y,ka.z,ka.w,kb4.x,kb4.y,kb4.z,kb4.w};
        float qq[8] = {qa.x,qa.y,qa.z,qa.w,qb4.x,qb4.y,qb4.z,qb4.w};
        #pragma unroll
        for (int i=0;i<8;i++)
            #pragma unroll
            for (int j=0;j<8;j++) acc[i][j] += kk[i]*qq[j];
    }

    float* Eb = g_E + ((size_t)b << 24);   // N*N = 2^24
    #pragma unroll
    for (int r=0;r<8;r++){
        float pv[8]; float s = 0.0f;
        #pragma unroll
        for (int j=0;j<8;j++){ float p = fexp(acc[r][j]); pv[j] = p; s += p; }
        int row = (it<<7) + i0 + r;
        float* dst = Eb + (((size_t)row)<<12) + (jt<<7) + j0;
        *(float4*)dst     = make_float4(pv[0],pv[1],pv[2],pv[3]);
        *(float4*)(dst+4) = make_float4(pv[4],pv[5],pv[6],pv[7]);
        rp[((i0+r)<<4) + tx] = s;
    }
    __syncthreads();
    if (tid < 128){
        float s = 0.0f;
        #pragma unroll
        for (int t=0;t<16;t++) s += rp[(tid<<4)+t];
        atomicAdd(&g_rowsum[(b<<12) + (it<<7) + tid], s);
    }
}

// ---------------- K3b: reciprocal row sums --------------------------------------
__global__ void DNL_k3b(){
    int i = blockIdx.x*blockDim.x + threadIdx.x;
    if (i < BB*NNq) g_invrs[i] = 1.0f / g_rowsum[i];
}

// ---------------- K3c: Dinv[n,m] = 1 / sum_b exp(m_b[n]*m_b[m]) -----------------
// grid 65536 x 256
__global__ __launch_bounds__(256) void DNL_k3c(){
    size_t t = ((size_t)blockIdx.x << 8) + threadIdx.x;   // 16M
    int n = (int)(t >> 12), mm = (int)(t & 4095);
    float a0 = g_m[n]        , b0 = g_m[mm];
    float a1 = g_m[4096 + n] , b1 = g_m[4096 + mm];
    float a2 = g_m[8192 + n] , b2 = g_m[8192 + mm];
    float a3 = g_m[12288 + n], b3 = g_m[12288 + mm];
    float s = fexp(a0*b0) + fexp(a1*b1) + fexp(a2*b2) + fexp(a3*b3);
    g_Dinv[t] = 1.0f / s;
}

// ---------------- K4: F = E*irs + exp(mm)*Dinv; out += V*F ----------------------
// grid (mt=32, b=4) = 128 blocks (one wave), 256 threads, smem 12544 floats
__global__ __launch_bounds__(256) void DNL_k4(float* __restrict__ out){
    extern __shared__ float sm[];
    float* Ft  = sm;              // 64*128 = 8192
    float* Vt  = Ft + 8192;       // 64*64  = 4096  ([c][n])
    float* mvM = Vt + 4096;       // 128
    float* irs = mvM + 128;       // 64
    float* mvN = irs + 64;        // 64

    int mt = blockIdx.x, b = blockIdx.y;
    int tid = threadIdx.x;
    int mbase = mt << 7;

    if (tid < 128) mvM[tid] = g_m[(b<<12) + mbase + tid];

    int tx = tid & 31, ty = tid >> 5;
    int m0 = tx << 2, c0 = ty << 3;    // 8c x 4m microtile; warp-uniform c0
    float acc[8][4];
    #pragma unroll
    for (int i=0;i<8;i++){ acc[i][0]=0.f; acc[i][1]=0.f; acc[i][2]=0.f; acc[i][3]=0.f; }

    const float* Eb = g_E + ((size_t)b << 24);

    for (int nt = 0; nt < 64; nt++){
        int nbase = nt << 6;
        __syncthreads();   // previous GEMM done with Ft/Vt
        if (tid < 64){
            irs[tid] = g_invrs[(b<<12) + nbase + tid];
            mvN[tid] = g_m[(b<<12) + nbase + tid];
        }
        for (int idx = tid; idx < 4096; idx += 256){
            int c = idx >> 6, nn = idx & 63;
            Vt[idx] = g_v[(((b<<6)+c)<<12) + nbase + nn];
        }
        __syncthreads();   // irs/mvN ready

        // construct F tile [64n][128m]
        #pragma unroll 4
        for (int p = tid; p < 8192; p += 256){
            int nn = p >> 7, mm = p & 127;
            size_t off = (((size_t)(nbase+nn))<<12) + mbase + mm;
            float e = Eb[off];
            float d = g_Dinv[off];
            Ft[p] = e * irs[nn] + fexp(mvN[nn]*mvM[mm]) * d;
        }
        __syncthreads();   // Ft ready

        // out_tile += V[c, n] * F[n, m]
        #pragma unroll 4
        for (int nn = 0; nn < 64; nn++){
            float4 f = *(const float4*)(Ft + (nn<<7) + m0);
            #pragma unroll
            for (int i=0;i<8;i++){
                float v = Vt[((c0+i)<<6) + nn];     // warp-broadcast
                acc[i][0] += v*f.x; acc[i][1] += v*f.y;
                acc[i][2] += v*f.z; acc[i][3] += v*f.w;
            }
        }
    }

    #pragma unroll
    for (int i=0;i<8;i++){
        float* dst = out + (((size_t)(b<<6)+c0+i)<<12) + mbase + m0;
        float4 o = *(const float4*)dst;   // BN residual from K1
        o.x += acc[i][0]; o.y += acc[i][1]; o.z += acc[i][2]; o.w += acc[i][3];
        *(float4*)dst = o;
    }
}

// ---------------- host launcher -------------------------------------------------
extern "C" void kernel_launch(void* const* d_in, const int* in_sizes, int n_in,
                              void* d_out, int out_size)
{
    const float* x    = (const float*)d_in[0];
    const float* qw   = (const float*)d_in[1];
    const float* qb   = (const float*)d_in[2];
    const float* kw   = (const float*)d_in[3];
    const float* kb   = (const float*)d_in[4];
    const float* mw   = (const float*)d_in[5];
    const float* mb   = (const float*)d_in[6];
    const float* vw   = (const float*)d_in[7];
    const float* vb   = (const float*)d_in[8];
    const float* ww   = (const float*)d_in[9];
    const float* wb   = (const float*)d_in[10];
    const float* bng  = (const float*)d_in[11];
    const float* bnb  = (const float*)d_in[12];
    const float* bnrm = (const float*)d_in[13];
    const float* bnrv = (const float*)d_in[14];
    float* out = (float*)d_out;

    const int SM1 = 24960*4;   // ~99.8 KB
    const int SM3 = 18560*4;   // ~74.2 KB
    const int SM4 = 12544*4;   // ~50.2 KB
    cudaFuncSetAttribute(DNL_k1, cudaFuncAttributeMaxDynamicSharedMemorySize, SM1);
    cudaFuncSetAttribute(DNL_k3, cudaFuncAttributeMaxDynamicSharedMemorySize, SM3);
    cudaFuncSetAttribute(DNL_k4, cudaFuncAttributeMaxDynamicSharedMemorySize, SM4);

    DNL_k0_zero<<<64, 256>>>();
    DNL_k1<<<dim3(32,4), 256, SM1>>>(x, qw,qb, kw,kb, mw,mb, vw,vb, ww,wb,
                                     bng,bnb,bnrm,bnrv, out);
    DNL_k3<<<dim3(32,32,4), 256, SM3>>>();
    DNL_k3b<<<64, 256>>>();
    DNL_k3c<<<65536, 256>>>();
    DNL_k4<<<dim3(32,4), 256, SM4>>>(out);
}

// round 4
// speedup vs baseline: 1.0283x; 1.0086x over previous
#include <cuda_runtime.h>
#include <math.h>

#define BB 4
#define CC 64
#define NNq 4096   // N = H*W

// ---------------- device scratch (sanctioned __device__ globals) ----------------
__device__ float g_q[BB*CC*NNq];            // 4 MB
__device__ float g_k[BB*CC*NNq];            // 4 MB
__device__ float g_v[BB*CC*NNq];            // 4 MB
__device__ float g_m[BB*NNq];               // 64 KB
__device__ float g_E[(size_t)BB*NNq*NNq];   // 256 MiB: exp(qk)
__device__ float g_Dinv[(size_t)NNq*NNq];   // 64 MiB: 1/sum_b exp(mm)
__device__ float g_rowsum[BB*NNq];
__device__ float g_invrs[BB*NNq];
__device__ float g_qsum[BB*CC];
__device__ float g_ksum[BB*CC];

// fast exp: x -> 2^(x*log2e), degree-4 poly on [-0.5,0.5], rel err ~4e-5
__device__ __forceinline__ float fexp(float v){
    float y = v * 1.44269504088896341f;
    float t = y + 12582912.0f;                 // round-to-nearest int (magic)
    int   e = __float_as_int(t) - 0x4B400000;  // integer part
    float f = y - (t - 12582912.0f);           // frac in [-0.5, 0.5]
    float p = 0.00961804886f;
    p = p*f + 0.05550410866f;
    p = p*f + 0.24022650696f;
    p = p*f + 0.69314718056f;
    p = p*f + 1.0f;
    return __int_as_float(__float_as_int(p) + (e << 23));
}

// ---------------- K0: zero accumulators (must re-zero every graph replay) ------
__global__ void DNL_k0_zero(){
    int i = blockIdx.x*blockDim.x + threadIdx.x;
    if (i < BB*NNq) g_rowsum[i] = 0.0f;
    if (i < BB*CC){ g_qsum[i] = 0.0f; g_ksum[i] = 0.0f; }
}

// helper: 64x64 weight (smem, row stride 65) times x tile (smem [64][128])
__device__ __forceinline__ void conv_acc(const float* __restrict__ wsm,
                                         const float* __restrict__ xs,
                                         const float* __restrict__ bias,
                                         int o0, int n0, float acc[4][8]){
    #pragma unroll
    for (int i=0;i<4;i++){
        float bv = bias[o0+i];
        #pragma unroll
        for (int j=0;j<8;j++) acc[i][j] = bv;
    }
    #pragma unroll 8
    for (int c=0;c<64;c++){
        float4 x0 = *(const float4*)(xs + (c<<7) + n0);
        float4 x1 = *(const float4*)(xs + (c<<7) + n0 + 4);
        #pragma unroll
        for (int i=0;i<4;i++){
            float w = wsm[(o0+i)*65 + c];
            acc[i][0] += w*x0.x; acc[i][1] += w*x0.y;
            acc[i][2] += w*x0.z; acc[i][3] += w*x0.w;
            acc[i][4] += w*x1.x; acc[i][5] += w*x1.y;
            acc[i][6] += w*x1.z; acc[i][7] += w*x1.w;
        }
    }
}

// ---------------- K1: q,k,v,m and BN(wx) -> out; mean partial sums -------------
// grid (32 n-tiles, 4 b), 256 threads, dyn smem = 24960 floats
__global__ __launch_bounds__(256) void DNL_k1(
    const float* __restrict__ x,
    const float* __restrict__ qw, const float* __restrict__ qb,
    const float* __restrict__ kw, const float* __restrict__ kb,
    const float* __restrict__ mw, const float* __restrict__ mb,
    const float* __restrict__ vw, const float* __restrict__ vb,
    const float* __restrict__ ww, const float* __restrict__ wb,
    const float* __restrict__ bng, const float* __restrict__ bnb,
    const float* __restrict__ bnrm, const float* __restrict__ bnrv,
    float* __restrict__ out)
{
    extern __shared__ float sm[];
    float* xs  = sm;               // 64*128
    float* wq  = xs  + 64*128;     // 64*65 each
    float* wk  = wq  + 64*65;
    float* wv  = wk  + 64*65;
    float* wwt = wv  + 64*65;
    float* qs  = wwt + 64*65;      // 64
    float* ks  = qs  + 64;         // 64

    int b = blockIdx.y, nt = blockIdx.x;
    int nb = nt << 7;
    int tid = threadIdx.x;

    if (tid < 64){ qs[tid] = 0.0f; ks[tid] = 0.0f; }
    for (int idx = tid; idx < 64*128; idx += 256){
        int c = idx >> 7, pos = idx & 127;
        xs[idx] = x[(((b<<6)+c)<<12) + nb + pos];
    }
    for (int idx = tid; idx < 64*64; idx += 256){
        int o = idx >> 6, c = idx & 63;
        int so = o*65 + c;
        wq[so] = qw[idx]; wk[so] = kw[idx]; wv[so] = vw[idx]; wwt[so] = ww[idx];
    }
    __syncthreads();

    // m branch (1 output channel)
    if (tid < 128){
        float a = mb[0];
        #pragma unroll 8
        for (int c=0;c<64;c++) a += mw[c]*xs[(c<<7) + tid];
        g_m[(b<<12) + nb + tid] = a;
    }

    int tx = tid & 15, ty = tid >> 4;
    int n0 = tx << 3, o0 = ty << 2;
    float acc[4][8];

    // Q
    conv_acc(wq, xs, qb, o0, n0, acc);
    #pragma unroll
    for (int i=0;i<4;i++){
        float* dst = g_q + ((((size_t)(b<<6)+o0+i)<<12) + nb + n0);
        *(float4*)dst     = make_float4(acc[i][0],acc[i][1],acc[i][2],acc[i][3]);
        *(float4*)(dst+4) = make_float4(acc[i][4],acc[i][5],acc[i][6],acc[i][7]);
        float s = acc[i][0]+acc[i][1]+acc[i][2]+acc[i][3]
                 +acc[i][4]+acc[i][5]+acc[i][6]+acc[i][7];
        atomicAdd(&qs[o0+i], s);
    }
    // K
    conv_acc(wk, xs, kb, o0, n0, acc);
    #pragma unroll
    for (int i=0;i<4;i++){
        float* dst = g_k + ((((size_t)(b<<6)+o0+i)<<12) + nb + n0);
        *(float4*)dst     = make_float4(acc[i][0],acc[i][1],acc[i][2],acc[i][3]);
        *(float4*)(dst+4) = make_float4(acc[i][4],acc[i][5],acc[i][6],acc[i][7]);
        float s = acc[i][0]+acc[i][1]+acc[i][2]+acc[i][3]
                 +acc[i][4]+acc[i][5]+acc[i][6]+acc[i][7];
        atomicAdd(&ks[o0+i], s);
    }
    // V
    conv_acc(wv, xs, vb, o0, n0, acc);
    #pragma unroll
    for (int i=0;i<4;i++){
        float* dst = g_v + ((((size_t)(b<<6)+o0+i)<<12) + nb + n0);
        *(float4*)dst     = make_float4(acc[i][0],acc[i][1],acc[i][2],acc[i][3]);
        *(float4*)(dst+4) = make_float4(acc[i][4],acc[i][5],acc[i][6],acc[i][7]);
    }
    // W + BatchNorm (eval) -> initialize out with residual path
    conv_acc(wwt, xs, wb, o0, n0, acc);
    #pragma unroll
    for (int i=0;i<4;i++){
        int o = o0 + i;
        float sc = bng[o] * rsqrtf(bnrv[o] + 1e-5f);
        float sh = bnb[o] - bnrm[o]*sc;
        float* dst = out + (((size_t)(b<<6)+o)<<12) + nb + n0;
        *(float4*)dst     = make_float4(acc[i][0]*sc+sh, acc[i][1]*sc+sh,
                                        acc[i][2]*sc+sh, acc[i][3]*sc+sh);
        *(float4*)(dst+4) = make_float4(acc[i][4]*sc+sh, acc[i][5]*sc+sh,
                                        acc[i][6]*sc+sh, acc[i][7]*sc+sh);
    }
    __syncthreads();
    if (tid < 64){
        atomicAdd(&g_qsum[(b<<6)+tid], qs[tid]);
        atomicAdd(&g_ksum[(b<<6)+tid], ks[tid]);
    }
}

// ---------------- K3: E = exp(K_w^T Q_w) + rowsums (whiten fused in loads) ------
// grid (jt=32, it=32, b=4), 256 threads, dyn smem = 18560 floats
__global__ __launch_bounds__(256) void DNL_k3(){
    extern __shared__ float sm[];
    float* Kt = sm;               // 64*128
    float* Qt = Kt + 8192;        // 64*128
    float* rp = Qt + 8192;        // 128*16
    float* kmean = rp + 2048;     // 64
    float* qmean = kmean + 64;    // 64
    int jt = blockIdx.x, it = blockIdx.y, b = blockIdx.z;
    int tid = threadIdx.x;

    if (tid < 64){
        kmean[tid] = g_ksum[(b<<6)+tid] * (1.0f/NNq);
        qmean[tid] = g_qsum[(b<<6)+tid] * (1.0f/NNq);
    }
    __syncthreads();
    for (int idx = tid; idx < 8192; idx += 256){
        int c = idx >> 7, pos = idx & 127;
        Kt[idx] = g_k[(((b<<6)+c)<<12) + (it<<7) + pos] - kmean[c];
        Qt[idx] = g_q[(((b<<6)+c)<<12) + (jt<<7) + pos] - qmean[c];
    }
    __syncthreads();

    int tx = tid & 15, ty = tid >> 4;
    int j0 = tx << 3, i0 = ty << 3;
    float acc[8][8];
    #pragma unroll
    for (int i=0;i<8;i++)
        #pragma unroll
        for (int j=0;j<8;j++) acc[i][j] = 0.0f;

    #pragma unroll 4
    for (int c=0;c<64;c++){
        float4 ka = *(const float4*)(Kt + (c<<7) + i0);
        float4 kb4= *(const float4*)(Kt + (c<<7) + i0 + 4);
        float4 qa = *(const float4*)(Qt + (c<<7) + j0);
        float4 qb4= *(const float4*)(Qt + (c<<7) + j0 + 4);
        float kk[8] = {ka.x,ka.y,ka.z,ka.w,kb4.x,kb4.y,kb4.z,kb4.w};
        float qq[8] = {qa.x,qa.y,qa.z,qa.w,qb4.x,qb4.y,qb4.z,qb4.w};
        #pragma unroll
        for (int i=0;i<8;i++)
            #pragma unroll
            for (int j=0;j<8;j++) acc[i][j] += kk[i]*qq[j];
    }

    float* Eb = g_E + ((size_t)b << 24);   // N*N = 2^24
    #pragma unroll
    for (int r=0;r<8;r++){
        float pv[8]; float s = 0.0f;
        #pragma unroll
        for (int j=0;j<8;j++){ float p = fexp(acc[r][j]); pv[j] = p; s += p; }
        int row = (it<<7) + i0 + r;
        float* dst = Eb + (((size_t)row)<<12) + (jt<<7) + j0;
        *(float4*)dst     = make_float4(pv[0],pv[1],pv[2],pv[3]);
        *(float4*)(dst+4) = make_float4(pv[4],pv[5],pv[6],pv[7]);
        rp[((i0+r)<<4) + tx] = s;
    }
    __syncthreads();
    if (tid < 128){
        float s = 0.0f;
        #pragma unroll
        for (int t=0;t<16;t++) s += rp[(tid<<4)+t];
        atomicAdd(&g_rowsum[(b<<12) + (it<<7) + tid], s);
    }
}

// ---------------- K3b: reciprocal row sums --------------------------------------
__global__ void DNL_k3b(){
    int i = blockIdx.x*blockDim.x + threadIdx.x;
    if (i < BB*NNq) g_invrs[i] = 1.0f / g_rowsum[i];
}

// ---------------- K3c: Dinv[n,m] = 1 / sum_b exp(m_b[n]*m_b[m]) -----------------
// grid 65536 x 256
__global__ __launch_bounds__(256) void DNL_k3c(){
    size_t t = ((size_t)blockIdx.x << 8) + threadIdx.x;   // 16M
    int n = (int)(t >> 12), mm = (int)(t & 4095);
    float a0 = g_m[n]        , b0 = g_m[mm];
    float a1 = g_m[4096 + n] , b1 = g_m[4096 + mm];
    float a2 = g_m[8192 + n] , b2 = g_m[8192 + mm];
    float a3 = g_m[12288 + n], b3 = g_m[12288 + mm];
    float s = fexp(a0*b0) + fexp(a1*b1) + fexp(a2*b2) + fexp(a3*b3);
    g_Dinv[t] = 1.0f / s;
}

// ---------------- K4: F = E*irs + exp(mm)*Dinv; out += V*F ----------------------
// grid (mt=32, b=4) = 128 blocks (one wave), 256 threads, smem 12544 floats
__global__ __launch_bounds__(256) void DNL_k4(float* __restrict__ out){
    extern __shared__ float sm[];
    float* Ft  = sm;              // 64*128 = 8192
    float* Vt  = Ft + 8192;       // 64*64  = 4096  ([c][n])
    float* mvM = Vt + 4096;       // 128
    float* irs = mvM + 128;       // 64
    float* mvN = irs + 64;        // 64

    int mt = blockIdx.x, b = blockIdx.y;
    int tid = threadIdx.x;
    int mbase = mt << 7;

    if (tid < 128) mvM[tid] = g_m[(b<<12) + mbase + tid];

    int tx = tid & 31, ty = tid >> 5;
    int m0 = tx << 2, c0 = ty << 3;    // 8c x 4m microtile; warp-uniform c0
    float acc[8][4];
    #pragma unroll
    for (int i=0;i<8;i++){ acc[i][0]=0.f; acc[i][1]=0.f; acc[i][2]=0.f; acc[i][3]=0.f; }

    const float* Eb = g_E + ((size_t)b << 24);

    for (int nt = 0; nt < 64; nt++){
        int nbase = nt << 6;
        __syncthreads();   // previous GEMM done with Ft/Vt
        if (tid < 64){
            irs[tid] = g_invrs[(b<<12) + nbase + tid];
            mvN[tid] = g_m[(b<<12) + nbase + tid];
        }
        for (int idx = tid; idx < 4096; idx += 256){
            int c = idx >> 6, nn = idx & 63;
            Vt[idx] = g_v[(((b<<6)+c)<<12) + nbase + nn];
        }
        __syncthreads();   // irs/mvN ready

        // construct F tile [64n][128m]
        #pragma unroll 4
        for (int p = tid; p < 8192; p += 256){
            int nn = p >> 7, mm = p & 127;
            size_t off = (((size_t)(nbase+nn))<<12) + mbase + mm;
            float e = Eb[off];
            float d = g_Dinv[off];
            Ft[p] = e * irs[nn] + fexp(mvN[nn]*mvM[mm]) * d;
        }
        __syncthreads();   // Ft ready

        // out_tile += V[c, n] * F[n, m]
        #pragma unroll 4
        for (int nn = 0; nn < 64; nn++){
            float4 f = *(const float4*)(Ft + (nn<<7) + m0);
            #pragma unroll
            for (int i=0;i<8;i++){
                float v = Vt[((c0+i)<<6) + nn];     // warp-broadcast
                acc[i][0] += v*f.x; acc[i][1] += v*f.y;
                acc[i][2] += v*f.z; acc[i][3] += v*f.w;
            }
        }
    }

    #pragma unroll
    for (int i=0;i<8;i++){
        float* dst = out + (((size_t)(b<<6)+c0+i)<<12) + mbase + m0;
        float4 o = *(const float4*)dst;   // BN residual from K1
        o.x += acc[i][0]; o.y += acc[i][1]; o.z += acc[i][2]; o.w += acc[i][3];
        *(float4*)dst = o;
    }
}

// ---------------- host launcher -------------------------------------------------
extern "C" void kernel_launch(void* const* d_in, const int* in_sizes, int n_in,
                              void* d_out, int out_size)
{
    const float* x    = (const float*)d_in[0];
    const float* qw   = (const float*)d_in[1];
    const float* qb   = (const float*)d_in[2];
    const float* kw   = (const float*)d_in[3];
    const float* kb   = (const float*)d_in[4];
    const float* mw   = (const float*)d_in[5];
    const float* mb   = (const float*)d_in[6];
    const float* vw   = (const float*)d_in[7];
    const float* vb   = (const float*)d_in[8];
    const float* ww   = (const float*)d_in[9];
    const float* wb   = (const float*)d_in[10];
    const float* bng  = (const float*)d_in[11];
    const float* bnb  = (const float*)d_in[12];
    const float* bnrm = (const float*)d_in[13];
    const float* bnrv = (const float*)d_in[14];
    float* out = (float*)d_out;

    const int SM1 = 24960*4;   // ~99.8 KB
    const int SM3 = 18560*4;   // ~74.2 KB
    const int SM4 = 12544*4;   // ~50.2 KB
    cudaFuncSetAttribute(DNL_k1, cudaFuncAttributeMaxDynamicSharedMemorySize, SM1);
    cudaFuncSetAttribute(DNL_k3, cudaFuncAttributeMaxDynamicSharedMemorySize, SM3);
    cudaFuncSetAttribute(DNL_k4, cudaFuncAttributeMaxDynamicSharedMemorySize, SM4);

    DNL_k0_zero<<<64, 256>>>();
    DNL_k1<<<dim3(32,4), 256, SM1>>>(x, qw,qb, kw,kb, mw,mb, vw,vb, ww,wb,
                                     bng,bnb,bnrm,bnrv, out);
    DNL_k3<<<dim3(32,32,4), 256, SM3>>>();
    DNL_k3b<<<64, 256>>>();
    DNL_k3c<<<65536, 256>>>();
    DNL_k4<<<dim3(32,4), 256, SM4>>>(out);
}

// round 6
// speedup vs baseline: 2.0650x; 2.0081x over previous
#include <cuda_runtime.h>
#include <cuda_bf16.h>
#include <stdint.h>

#define BB 4
#define NNq 4096

// ---------------- device scratch ----------------
__device__ float g_q[BB*64*NNq];
__device__ float g_k[BB*64*NNq];
__device__ float g_v[BB*64*NNq];
__device__ float g_m[BB*NNq];
__device__ __align__(16) __nv_bfloat16 g_qTb[(size_t)BB*NNq*64];  // [b][n][c] whitened
__device__ __align__(16) __nv_bfloat16 g_kTb[(size_t)BB*NNq*64];  // [b][n][c] whitened
__device__ float g_Et[(size_t)BB*NNq*NNq];   // 256 MiB: exp(qk) stored [b][m][n]
__device__ float g_Dinv[(size_t)NNq*NNq];    // 64 MiB, symmetric
__device__ float g_rowsum[BB*NNq];
__device__ float g_invrs[BB*NNq];
__device__ float g_qsum[BB*64];
__device__ float g_ksum[BB*64];

// ---------------- helpers ----------------
__device__ __forceinline__ float fexp(float v){
    float y = v * 1.44269504088896341f;
    float t = y + 12582912.0f;
    int   e = __float_as_int(t) - 0x4B400000;
    float f = y - (t - 12582912.0f);
    float p = 0.00961804886f;
    p = p*f + 0.05550410866f;
    p = p*f + 0.24022650696f;
    p = p*f + 0.69314718056f;
    p = p*f + 1.0f;
    return __int_as_float(__float_as_int(p) + (e << 23));
}

// m16n8k16 bf16 mma, D=f32, A row-major, B "col" (n-major rows w/ k contiguous)
__device__ __forceinline__ void mma16816(float c[4], const uint32_t a[4],
                                         uint32_t b0, uint32_t b1){
    asm volatile(
        "mma.sync.aligned.m16n8k16.row.col.f32.bf16.bf16.f32 "
        "{%0,%1,%2,%3}, {%4,%5,%6,%7}, {%8,%9}, {%0,%1,%2,%3};"
        : "+f"(c[0]), "+f"(c[1]), "+f"(c[2]), "+f"(c[3])
        : "r"(a[0]), "r"(a[1]), "r"(a[2]), "r"(a[3]), "r"(b0), "r"(b1));
}

// ---------------- K0: zero accumulators ----------------
__global__ void DNL_k0_zero(){
    int i = blockIdx.x*blockDim.x + threadIdx.x;
    if (i < BB*NNq) g_rowsum[i] = 0.0f;
    if (i < BB*64){ g_qsum[i] = 0.0f; g_ksum[i] = 0.0f; }
}

// ---------------- K1: q,k,v,m and BN(wx) -> out; mean partial sums -------------
__device__ __forceinline__ void conv_acc(const float* __restrict__ wsm,
                                         const float* __restrict__ xs,
                                         const float* __restrict__ bias,
                                         int o0, int n0, float acc[4][8]){
    #pragma unroll
    for (int i=0;i<4;i++){
        float bv = bias[o0+i];
        #pragma unroll
        for (int j=0;j<8;j++) acc[i][j] = bv;
    }
    #pragma unroll 8
    for (int c=0;c<64;c++){
        float4 x0 = *(const float4*)(xs + (c<<7) + n0);
        float4 x1 = *(const float4*)(xs + (c<<7) + n0 + 4);
        #pragma unroll
        for (int i=0;i<4;i++){
            float w = wsm[(o0+i)*65 + c];
            acc[i][0] += w*x0.x; acc[i][1] += w*x0.y;
            acc[i][2] += w*x0.z; acc[i][3] += w*x0.w;
            acc[i][4] += w*x1.x; acc[i][5] += w*x1.y;
            acc[i][6] += w*x1.z; acc[i][7] += w*x1.w;
        }
    }
}

__global__ __launch_bounds__(256) void DNL_k1(
    const float* __restrict__ x,
    const float* __restrict__ qw, const float* __restrict__ qb,
    const float* __restrict__ kw, const float* __restrict__ kb,
    const float* __restrict__ mw, const float* __restrict__ mb,
    const float* __restrict__ vw, const float* __restrict__ vb,
    const float* __restrict__ ww, const float* __restrict__ wb,
    const float* __restrict__ bng, const float* __restrict__ bnb,
    const float* __restrict__ bnrm, const float* __restrict__ bnrv,
    float* __restrict__ out)
{
    extern __shared__ float sm[];
    float* xs  = sm;
    float* wq  = xs  + 64*128;
    float* wk  = wq  + 64*65;
    float* wv  = wk  + 64*65;
    float* wwt = wv  + 64*65;
    float* qs  = wwt + 64*65;
    float* ks  = qs  + 64;

    int b = blockIdx.y, nt = blockIdx.x;
    int nb = nt << 7;
    int tid = threadIdx.x;

    if (tid < 64){ qs[tid] = 0.0f; ks[tid] = 0.0f; }
    for (int idx = tid; idx < 64*128; idx += 256){
        int c = idx >> 7, pos = idx & 127;
        xs[idx] = x[(((b<<6)+c)<<12) + nb + pos];
    }
    for (int idx = tid; idx < 64*64; idx += 256){
        int o = idx >> 6, c = idx & 63;
        int so = o*65 + c;
        wq[so] = qw[idx]; wk[so] = kw[idx]; wv[so] = vw[idx]; wwt[so] = ww[idx];
    }
    __syncthreads();

    if (tid < 128){
        float a = mb[0];
        #pragma unroll 8
        for (int c=0;c<64;c++) a += mw[c]*xs[(c<<7) + tid];
        g_m[(b<<12) + nb + tid] = a;
    }

    int tx = tid & 15, ty = tid >> 4;
    int n0 = tx << 3, o0 = ty << 2;
    float acc[4][8];

    conv_acc(wq, xs, qb, o0, n0, acc);
    #pragma unroll
    for (int i=0;i<4;i++){
        float* dst = g_q + ((((size_t)(b<<6)+o0+i)<<12) + nb + n0);
        *(float4*)dst     = make_float4(acc[i][0],acc[i][1],acc[i][2],acc[i][3]);
        *(float4*)(dst+4) = make_float4(acc[i][4],acc[i][5],acc[i][6],acc[i][7]);
        float s = acc[i][0]+acc[i][1]+acc[i][2]+acc[i][3]
                 +acc[i][4]+acc[i][5]+acc[i][6]+acc[i][7];
        atomicAdd(&qs[o0+i], s);
    }
    conv_acc(wk, xs, kb, o0, n0, acc);
    #pragma unroll
    for (int i=0;i<4;i++){
        float* dst = g_k + ((((size_t)(b<<6)+o0+i)<<12) + nb + n0);
        *(float4*)dst     = make_float4(acc[i][0],acc[i][1],acc[i][2],acc[i][3]);
        *(float4*)(dst+4) = make_float4(acc[i][4],acc[i][5],acc[i][6],acc[i][7]);
        float s = acc[i][0]+acc[i][1]+acc[i][2]+acc[i][3]
                 +acc[i][4]+acc[i][5]+acc[i][6]+acc[i][7];
        atomicAdd(&ks[o0+i], s);
    }
    conv_acc(wv, xs, vb, o0, n0, acc);
    #pragma unroll
    for (int i=0;i<4;i++){
        float* dst = g_v + ((((size_t)(b<<6)+o0+i)<<12) + nb + n0);
        *(float4*)dst     = make_float4(acc[i][0],acc[i][1],acc[i][2],acc[i][3]);
        *(float4*)(dst+4) = make_float4(acc[i][4],acc[i][5],acc[i][6],acc[i][7]);
    }
    conv_acc(wwt, xs, wb, o0, n0, acc);
    #pragma unroll
    for (int i=0;i<4;i++){
        int o = o0 + i;
        float sc = bng[o] * rsqrtf(bnrv[o] + 1e-5f);
        float sh = bnb[o] - bnrm[o]*sc;
        float* dst = out + (((size_t)(b<<6)+o)<<12) + nb + n0;
        *(float4*)dst     = make_float4(acc[i][0]*sc+sh, acc[i][1]*sc+sh,
                                        acc[i][2]*sc+sh, acc[i][3]*sc+sh);
        *(float4*)(dst+4) = make_float4(acc[i][4]*sc+sh, acc[i][5]*sc+sh,
                                        acc[i][6]*sc+sh, acc[i][7]*sc+sh);
    }
    __syncthreads();
    if (tid < 64){
        atomicAdd(&g_qsum[(b<<6)+tid], qs[tid]);
        atomicAdd(&g_ksum[(b<<6)+tid], ks[tid]);
    }
}

// ---------------- K2b: whiten + transpose + bf16 -------------------------------
__global__ __launch_bounds__(256) void DNL_k2b(){
    __shared__ float sq[64*65], sk[64*65], mq[64], mk[64];
    int b = blockIdx.y, nt = blockIdx.x, tid = threadIdx.x;
    if (tid<64){ mq[tid]=g_qsum[(b<<6)+tid]*(1.f/NNq); mk[tid]=g_ksum[(b<<6)+tid]*(1.f/NNq); }
    for (int i=tid;i<4096;i+=256){
        int c=i>>6, n=i&63;
        sq[c*65+n]=g_q[(((size_t)(b<<6)+c)<<12)+(nt<<6)+n];
        sk[c*65+n]=g_k[(((size_t)(b<<6)+c)<<12)+(nt<<6)+n];
    }
    __syncthreads();
    for (int i=tid;i<2048;i+=256){
        int n=i>>5, c=(i&31)<<1;
        size_t row = (size_t)(b<<12)+(nt<<6)+n;
        __nv_bfloat162 hq = __floats2bfloat162_rn(sq[c*65+n]-mq[c], sq[(c+1)*65+n]-mq[c+1]);
        __nv_bfloat162 hk = __floats2bfloat162_rn(sk[c*65+n]-mk[c], sk[(c+1)*65+n]-mk[c+1]);
        *(__nv_bfloat162*)(g_qTb + row*64 + c) = hq;
        *(__nv_bfloat162*)(g_kTb + row*64 + c) = hk;
    }
}

// ---------------- K3: mma.sync  Et[b][m][n] = exp(qk), rowsums ------------------
// grid (it=32, jt=32, b=4), 256 threads (8 warps), dyn smem 36864 B
__global__ __launch_bounds__(256) void DNL_k3(){
    extern __shared__ char s3[];
    char* As = s3;              // Q tile [128 m][72] bf16 (row-major, k=c contiguous)
    char* Bs = s3 + 18432;      // K tile [128 n][72] bf16
    int it=blockIdx.x, jt=blockIdx.y, b=blockIdx.z;
    int tid=threadIdx.x;

    for (int i=tid;i<2048;i+=256){
        int r=i>>4, u=i&15;
        *(uint2*)(As + r*144 + u*8) =
            *((const uint2*)(g_qTb + ((size_t)(b<<12)+(jt<<7)+r)*64) + u);
        *(uint2*)(Bs + r*144 + u*8) =
            *((const uint2*)(g_kTb + ((size_t)(b<<12)+(it<<7)+r)*64) + u);
    }
    __syncthreads();

    int w = tid>>5, lane = tid&31, g = lane>>2, t = lane&3;
    int wm = (w&1)<<6, wn = (w>>1)<<5;   // warp tile: 64 m x 32 n
    float acc[4][4][4];
    #pragma unroll
    for (int r=0;r<4;r++)
        #pragma unroll
        for (int c=0;c<4;c++)
            #pragma unroll
            for (int q=0;q<4;q++) acc[r][c][q]=0.f;

    #pragma unroll
    for (int kc=0;kc<4;kc++){
        int K0 = kc<<4;
        uint32_t af[4][4], bf2[4][2];
        #pragma unroll
        for (int r=0;r<4;r++){
            const char* p = As + (wm + (r<<4) + g)*144 + (K0 + 2*t)*2;
            af[r][0] = *(const uint32_t*)p;
            af[r][1] = *(const uint32_t*)(p + 8*144);
            af[r][2] = *(const uint32_t*)(p + 16);
            af[r][3] = *(const uint32_t*)(p + 8*144 + 16);
        }
        #pragma unroll
        for (int c=0;c<4;c++){
            const char* p = Bs + (wn + (c<<3) + g)*144 + (K0 + 2*t)*2;
            bf2[c][0] = *(const uint32_t*)p;
            bf2[c][1] = *(const uint32_t*)(p + 16);
        }
        #pragma unroll
        for (int r=0;r<4;r++)
            #pragma unroll
            for (int c=0;c<4;c++)
                mma16816(acc[r][c], af[r], bf2[c][0], bf2[c][1]);
    }

    // epilogue: exp + store Et[m][n] + rowsum over m
    int Mb = (jt<<7) + wm + g;
    int Nb = (it<<7) + wn;
    float* Eb = g_Et + ((size_t)b<<24);
    float rs0[4], rs1[4];
    #pragma unroll
    for (int c=0;c<4;c++){ rs0[c]=0.f; rs1[c]=0.f; }
    #pragma unroll
    for (int r=0;r<4;r++){
        int m0 = Mb + (r<<4);
        #pragma unroll
        for (int c=0;c<4;c++){
            int n0 = Nb + (c<<3) + 2*t;
            float e0=fexp(acc[r][c][0]), e1=fexp(acc[r][c][1]);
            float e2=fexp(acc[r][c][2]), e3=fexp(acc[r][c][3]);
            *(float2*)(Eb + (((size_t)m0)<<12) + n0)     = make_float2(e0,e1);
            *(float2*)(Eb + (((size_t)(m0+8))<<12) + n0) = make_float2(e2,e3);
            rs0[c] += e0+e2; rs1[c] += e1+e3;
        }
    }
    #pragma unroll
    for (int c=0;c<4;c++){
        #pragma unroll
        for (int q=4;q<32;q<<=1){
            rs0[c] += __shfl_xor_sync(0xffffffffu, rs0[c], q);
            rs1[c] += __shfl_xor_sync(0xffffffffu, rs1[c], q);
        }
        if (lane < 4){
            atomicAdd(&g_rowsum[(b<<12) + Nb + (c<<3) + 2*t    ], rs0[c]);
            atomicAdd(&g_rowsum[(b<<12) + Nb + (c<<3) + 2*t + 1], rs1[c]);
        }
    }
}

// ---------------- K3b: reciprocal row sums --------------------------------------
__global__ void DNL_k3b(){
    int i = blockIdx.x*blockDim.x + threadIdx.x;
    if (i < BB*NNq) g_invrs[i] = 1.0f / g_rowsum[i];
}

// ---------------- K3c: Dinv[n,m] = 1 / sum_b exp(m_b[n]*m_b[m]) -----------------
__global__ __launch_bounds__(256) void DNL_k3c(){
    size_t t = ((size_t)blockIdx.x << 8) + threadIdx.x;   // 16M
    int n = (int)(t >> 12), mm = (int)(t & 4095);
    float s = fexp(g_m[n]*g_m[mm]) + fexp(g_m[4096+n]*g_m[4096+mm])
            + fexp(g_m[8192+n]*g_m[8192+mm]) + fexp(g_m[12288+n]*g_m[12288+mm]);
    g_Dinv[t] = __fdividef(1.0f, s);
}

// ---------------- K4: mma.sync split-bf16  out += V * F -------------------------
// grid (mt=64, b=4) = 256 blocks, 256 threads, dyn smem 37632 B
__global__ __launch_bounds__(256) void DNL_k4(float* __restrict__ out){
    extern __shared__ char s4[];
    float* mvM = (float*)s4;            // 64
    float* irs = (float*)(s4+256);      // 64
    float* mvN = (float*)(s4+512);      // 64
    char* Ahi = s4 + 768;               // V hi [64 c][72] bf16
    char* Alo = Ahi + 9216;
    char* Bhi = Alo + 9216;             // F hi [64 m][72] bf16 (k=n contiguous)
    char* Blo = Bhi + 9216;
    int mt=blockIdx.x, b=blockIdx.y, tid=threadIdx.x;
    int mbase = mt<<6;
    int w=tid>>5, lane=tid&31, g=lane>>2, t=lane&3;
    int wc = (w&1)<<5, wmm = (w>>1)<<4;   // warp tile: 32 c x 16 m

    if (tid<64) mvM[tid] = g_m[(b<<12)+mbase+tid];
    float acc[2][2][4];
    #pragma unroll
    for (int r=0;r<2;r++)
        #pragma unroll
        for (int c=0;c<2;c++)
            #pragma unroll
            for (int q=0;q<4;q++) acc[r][c][q]=0.f;

    const float* Eb = g_Et + ((size_t)b<<24);

    for (int ch=0; ch<64; ch++){
        int nbase = ch<<6;
        if (tid<64){ irs[tid]=g_invrs[(b<<12)+nbase+tid]; mvN[tid]=g_m[(b<<12)+nbase+tid]; }
        __syncthreads();   // also separates prev MMA from tile overwrite

        // V tiles hi/lo [64 c][64 n]
        #pragma unroll
        for (int i=0;i<8;i++){
            int idx = tid + (i<<8);
            int c = idx>>5, n2 = idx&31;
            float2 v = *(const float2*)(g_v + (((size_t)(b<<6)+c)<<12) + nbase + 2*n2);
            __nv_bfloat16 h0=__float2bfloat16(v.x), h1=__float2bfloat16(v.y);
            __nv_bfloat162 hi; hi.x=h0; hi.y=h1;
            __nv_bfloat162 lo = __floats2bfloat162_rn(v.x-__bfloat162float(h0),
                                                      v.y-__bfloat162float(h1));
            int off = (c*72 + 2*n2)*2;
            *(__nv_bfloat162*)(Ahi+off) = hi;
            *(__nv_bfloat162*)(Alo+off) = lo;
        }
        // F tiles hi/lo: F[m][n] = Et[m][n]*irs[n] + exp(mvN*mvM)*Dinv[m][n]
        #pragma unroll
        for (int i=0;i<4;i++){
            int idx = tid + (i<<8);
            int m = idx>>4, n4 = idx&15;
            size_t go = (((size_t)(mbase+m))<<12) + nbase + 4*n4;
            float4 e = *(const float4*)(Eb + go);
            float4 d = *(const float4*)(g_Dinv + go);
            float mm = mvM[m];
            int n0 = 4*n4;
            float f0 = e.x*irs[n0]   + fexp(mvN[n0]*mm)*d.x;
            float f1 = e.y*irs[n0+1] + fexp(mvN[n0+1]*mm)*d.y;
            float f2 = e.z*irs[n0+2] + fexp(mvN[n0+2]*mm)*d.z;
            float f3 = e.w*irs[n0+3] + fexp(mvN[n0+3]*mm)*d.w;
            __nv_bfloat16 a0=__float2bfloat16(f0), a1=__float2bfloat16(f1),
                          a2=__float2bfloat16(f2), a3=__float2bfloat16(f3);
            __nv_bfloat162 h01; h01.x=a0; h01.y=a1;
            __nv_bfloat162 h23; h23.x=a2; h23.y=a3;
            __nv_bfloat162 l01 = __floats2bfloat162_rn(f0-__bfloat162float(a0),
                                                       f1-__bfloat162float(a1));
            __nv_bfloat162 l23 = __floats2bfloat162_rn(f2-__bfloat162float(a2),
                                                       f3-__bfloat162float(a3));
            int off = (m*72 + 4*n4)*2;
            *(__nv_bfloat162*)(Bhi+off)   = h01;
            *(__nv_bfloat162*)(Bhi+off+4) = h23;
            *(__nv_bfloat162*)(Blo+off)   = l01;
            *(__nv_bfloat162*)(Blo+off+4) = l23;
        }
        __syncthreads();

        #pragma unroll
        for (int kc=0;kc<4;kc++){
            int K0 = kc<<4;
            uint32_t ah[2][4], al[2][4], bh[2][2], bl[2][2];
            #pragma unroll
            for (int r=0;r<2;r++){
                int ro = (wc + (r<<4) + g)*144 + (K0 + 2*t)*2;
                ah[r][0] = *(const uint32_t*)(Ahi+ro);
                ah[r][1] = *(const uint32_t*)(Ahi+ro+8*144);
                ah[r][2] = *(const uint32_t*)(Ahi+ro+16);
                ah[r][3] = *(const uint32_t*)(Ahi+ro+8*144+16);
                al[r][0] = *(const uint32_t*)(Alo+ro);
                al[r][1] = *(const uint32_t*)(Alo+ro+8*144);
                al[r][2] = *(const uint32_t*)(Alo+ro+16);
                al[r][3] = *(const uint32_t*)(Alo+ro+8*144+16);
            }
            #pragma unroll
            for (int c=0;c<2;c++){
                int ro = (wmm + (c<<3) + g)*144 + (K0 + 2*t)*2;
                bh[c][0] = *(const uint32_t*)(Bhi+ro);
                bh[c][1] = *(const uint32_t*)(Bhi+ro+16);
                bl[c][0] = *(const uint32_t*)(Blo+ro);
                bl[c][1] = *(const uint32_t*)(Blo+ro+16);
            }
            #pragma unroll
            for (int r=0;r<2;r++)
                #pragma unroll
                for (int c=0;c<2;c++){
                    mma16816(acc[r][c], ah[r], bh[c][0], bh[c][1]);
                    mma16816(acc[r][c], al[r], bh[c][0], bh[c][1]);
                    mma16816(acc[r][c], ah[r], bl[c][0], bl[c][1]);
                }
        }
    }

    // epilogue: RMW onto BN residual
    #pragma unroll
    for (int r=0;r<2;r++)
        #pragma unroll
        for (int c=0;c<2;c++){
            int cg = wc + (r<<4) + g;
            int mg = mbase + wmm + (c<<3) + 2*t;
            float* d0 = out + (((size_t)(b<<6)+cg)<<12) + mg;
            float2 o0 = *(const float2*)d0;
            o0.x += acc[r][c][0]; o0.y += acc[r][c][1];
            *(float2*)d0 = o0;
            float* d1 = out + (((size_t)(b<<6)+cg+8)<<12) + mg;
            float2 o1 = *(const float2*)d1;
            o1.x += acc[r][c][2]; o1.y += acc[r][c][3];
            *(float2*)d1 = o1;
        }
}

// ---------------- host launcher -------------------------------------------------
extern "C" void kernel_launch(void* const* d_in, const int* in_sizes, int n_in,
                              void* d_out, int out_size)
{
    const float* x    = (const float*)d_in[0];
    const float* qw   = (const float*)d_in[1];
    const float* qb   = (const float*)d_in[2];
    const float* kw   = (const float*)d_in[3];
    const float* kb   = (const float*)d_in[4];
    const float* mw   = (const float*)d_in[5];
    const float* mb   = (const float*)d_in[6];
    const float* vw   = (const float*)d_in[7];
    const float* vb   = (const float*)d_in[8];
    const float* ww   = (const float*)d_in[9];
    const float* wb   = (const float*)d_in[10];
    const float* bng  = (const float*)d_in[11];
    const float* bnb  = (const float*)d_in[12];
    const float* bnrm = (const float*)d_in[13];
    const float* bnrv = (const float*)d_in[14];
    float* out = (float*)d_out;

    const int SM1 = 24960*4;
    const int SM3 = 36864;
    const int SM4 = 37632;
    cudaFuncSetAttribute(DNL_k1, cudaFuncAttributeMaxDynamicSharedMemorySize, SM1);
    cudaFuncSetAttribute(DNL_k3, cudaFuncAttributeMaxDynamicSharedMemorySize, SM3);
    cudaFuncSetAttribute(DNL_k4, cudaFuncAttributeMaxDynamicSharedMemorySize, SM4);

    DNL_k0_zero<<<64, 256>>>();
    DNL_k1<<<dim3(32,4), 256, SM1>>>(x, qw,qb, kw,kb, mw,mb, vw,vb, ww,wb,
                                     bng,bnb,bnrm,bnrv, out);
    DNL_k2b<<<dim3(64,4), 256>>>();
    DNL_k3<<<dim3(32,32,4), 256, SM3>>>();
    DNL_k3b<<<64, 256>>>();
    DNL_k3c<<<65536, 256>>>();
    DNL_k4<<<dim3(64,4), 256, SM4>>>(out);
}

// round 7
// speedup vs baseline: 2.5310x; 1.2257x over previous
#include <cuda_runtime.h>
#include <cuda_bf16.h>
#include <stdint.h>

#define BB 4
#define NNq 4096

// ---------------- device scratch ----------------
__device__ float g_q[BB*64*NNq];
__device__ float g_k[BB*64*NNq];
__device__ float g_v[BB*64*NNq];
__device__ float g_m[BB*NNq];
__device__ __align__(16) __nv_bfloat16 g_qTb[(size_t)BB*NNq*64];  // [b][n][c] whitened
__device__ __align__(16) __nv_bfloat16 g_kTb[(size_t)BB*NNq*64];  // [b][n][c] whitened
__device__ float g_Dinv[(size_t)NNq*NNq];    // 64 MiB, symmetric
__device__ float g_rowsum[BB*NNq];
__device__ float g_invrs[BB*NNq];
__device__ float g_qsum[BB*64];
__device__ float g_ksum[BB*64];

// ---------------- helpers ----------------
__device__ __forceinline__ float fexp(float v){
    float y = v * 1.44269504088896341f;
    float t = y + 12582912.0f;
    int   e = __float_as_int(t) - 0x4B400000;
    float f = y - (t - 12582912.0f);
    float p = 0.00961804886f;
    p = p*f + 0.05550410866f;
    p = p*f + 0.24022650696f;
    p = p*f + 0.69314718056f;
    p = p*f + 1.0f;
    return __int_as_float(__float_as_int(p) + (e << 23));
}

// m16n8k16 bf16 mma, D=f32
__device__ __forceinline__ void mma16816(float c[4], const uint32_t a[4],
                                         uint32_t b0, uint32_t b1){
    asm volatile(
        "mma.sync.aligned.m16n8k16.row.col.f32.bf16.bf16.f32 "
        "{%0,%1,%2,%3}, {%4,%5,%6,%7}, {%8,%9}, {%0,%1,%2,%3};"
        : "+f"(c[0]), "+f"(c[1]), "+f"(c[2]), "+f"(c[3])
        : "r"(a[0]), "r"(a[1]), "r"(a[2]), "r"(a[3]), "r"(b0), "r"(b1));
}

// ---------------- K0: zero accumulators ----------------
__global__ void DNL_k0_zero(){
    int i = blockIdx.x*blockDim.x + threadIdx.x;
    if (i < BB*NNq) g_rowsum[i] = 0.0f;
    if (i < BB*64){ g_qsum[i] = 0.0f; g_ksum[i] = 0.0f; }
}

// ---------------- K1: q,k,v,m and BN(wx) -> out; mean partial sums -------------
__device__ __forceinline__ void conv_acc(const float* __restrict__ wsm,
                                         const float* __restrict__ xs,
                                         const float* __restrict__ bias,
                                         int o0, int n0, float acc[4][8]){
    #pragma unroll
    for (int i=0;i<4;i++){
        float bv = bias[o0+i];
        #pragma unroll
        for (int j=0;j<8;j++) acc[i][j] = bv;
    }
    #pragma unroll 8
    for (int c=0;c<64;c++){
        float4 x0 = *(const float4*)(xs + (c<<7) + n0);
        float4 x1 = *(const float4*)(xs + (c<<7) + n0 + 4);
        #pragma unroll
        for (int i=0;i<4;i++){
            float w = wsm[(o0+i)*65 + c];
            acc[i][0] += w*x0.x; acc[i][1] += w*x0.y;
            acc[i][2] += w*x0.z; acc[i][3] += w*x0.w;
            acc[i][4] += w*x1.x; acc[i][5] += w*x1.y;
            acc[i][6] += w*x1.z; acc[i][7] += w*x1.w;
        }
    }
}

__global__ __launch_bounds__(256) void DNL_k1(
    const float* __restrict__ x,
    const float* __restrict__ qw, const float* __restrict__ qb,
    const float* __restrict__ kw, const float* __restrict__ kb,
    const float* __restrict__ mw, const float* __restrict__ mb,
    const float* __restrict__ vw, const float* __restrict__ vb,
    const float* __restrict__ ww, const float* __restrict__ wb,
    const float* __restrict__ bng, const float* __restrict__ bnb,
    const float* __restrict__ bnrm, const float* __restrict__ bnrv,
    float* __restrict__ out)
{
    extern __shared__ float sm[];
    float* xs  = sm;
    float* wq  = xs  + 64*128;
    float* wk  = wq  + 64*65;
    float* wv  = wk  + 64*65;
    float* wwt = wv  + 64*65;
    float* qs  = wwt + 64*65;
    float* ks  = qs  + 64;

    int b = blockIdx.y, nt = blockIdx.x;
    int nb = nt << 7;
    int tid = threadIdx.x;

    if (tid < 64){ qs[tid] = 0.0f; ks[tid] = 0.0f; }
    for (int idx = tid; idx < 64*128; idx += 256){
        int c = idx >> 7, pos = idx & 127;
        xs[idx] = x[(((b<<6)+c)<<12) + nb + pos];
    }
    for (int idx = tid; idx < 64*64; idx += 256){
        int o = idx >> 6, c = idx & 63;
        int so = o*65 + c;
        wq[so] = qw[idx]; wk[so] = kw[idx]; wv[so] = vw[idx]; wwt[so] = ww[idx];
    }
    __syncthreads();

    if (tid < 128){
        float a = mb[0];
        #pragma unroll 8
        for (int c=0;c<64;c++) a += mw[c]*xs[(c<<7) + tid];
        g_m[(b<<12) + nb + tid] = a;
    }

    int tx = tid & 15, ty = tid >> 4;
    int n0 = tx << 3, o0 = ty << 2;
    float acc[4][8];

    conv_acc(wq, xs, qb, o0, n0, acc);
    #pragma unroll
    for (int i=0;i<4;i++){
        float* dst = g_q + ((((size_t)(b<<6)+o0+i)<<12) + nb + n0);
        *(float4*)dst     = make_float4(acc[i][0],acc[i][1],acc[i][2],acc[i][3]);
        *(float4*)(dst+4) = make_float4(acc[i][4],acc[i][5],acc[i][6],acc[i][7]);
        float s = acc[i][0]+acc[i][1]+acc[i][2]+acc[i][3]
                 +acc[i][4]+acc[i][5]+acc[i][6]+acc[i][7];
        atomicAdd(&qs[o0+i], s);
    }
    conv_acc(wk, xs, kb, o0, n0, acc);
    #pragma unroll
    for (int i=0;i<4;i++){
        float* dst = g_k + ((((size_t)(b<<6)+o0+i)<<12) + nb + n0);
        *(float4*)dst     = make_float4(acc[i][0],acc[i][1],acc[i][2],acc[i][3]);
        *(float4*)(dst+4) = make_float4(acc[i][4],acc[i][5],acc[i][6],acc[i][7]);
        float s = acc[i][0]+acc[i][1]+acc[i][2]+acc[i][3]
                 +acc[i][4]+acc[i][5]+acc[i][6]+acc[i][7];
        atomicAdd(&ks[o0+i], s);
    }
    conv_acc(wv, xs, vb, o0, n0, acc);
    #pragma unroll
    for (int i=0;i<4;i++){
        float* dst = g_v + ((((size_t)(b<<6)+o0+i)<<12) + nb + n0);
        *(float4*)dst     = make_float4(acc[i][0],acc[i][1],acc[i][2],acc[i][3]);
        *(float4*)(dst+4) = make_float4(acc[i][4],acc[i][5],acc[i][6],acc[i][7]);
    }
    conv_acc(wwt, xs, wb, o0, n0, acc);
    #pragma unroll
    for (int i=0;i<4;i++){
        int o = o0 + i;
        float sc = bng[o] * rsqrtf(bnrv[o] + 1e-5f);
        float sh = bnb[o] - bnrm[o]*sc;
        float* dst = out + (((size_t)(b<<6)+o)<<12) + nb + n0;
        *(float4*)dst     = make_float4(acc[i][0]*sc+sh, acc[i][1]*sc+sh,
                                        acc[i][2]*sc+sh, acc[i][3]*sc+sh);
        *(float4*)(dst+4) = make_float4(acc[i][4]*sc+sh, acc[i][5]*sc+sh,
                                        acc[i][6]*sc+sh, acc[i][7]*sc+sh);
    }
    __syncthreads();
    if (tid < 64){
        atomicAdd(&g_qsum[(b<<6)+tid], qs[tid]);
        atomicAdd(&g_ksum[(b<<6)+tid], ks[tid]);
    }
}

// ---------------- K2b: whiten + transpose + bf16 -------------------------------
__global__ __launch_bounds__(256) void DNL_k2b(){
    __shared__ float sq[64*65], sk[64*65], mq[64], mk[64];
    int b = blockIdx.y, nt = blockIdx.x, tid = threadIdx.x;
    if (tid<64){ mq[tid]=g_qsum[(b<<6)+tid]*(1.f/NNq); mk[tid]=g_ksum[(b<<6)+tid]*(1.f/NNq); }
    for (int i=tid;i<4096;i+=256){
        int c=i>>6, n=i&63;
        sq[c*65+n]=g_q[(((size_t)(b<<6)+c)<<12)+(nt<<6)+n];
        sk[c*65+n]=g_k[(((size_t)(b<<6)+c)<<12)+(nt<<6)+n];
    }
    __syncthreads();
    for (int i=tid;i<2048;i+=256){
        int n=i>>5, c=(i&31)<<1;
        size_t row = (size_t)(b<<12)+(nt<<6)+n;
        __nv_bfloat162 hq = __floats2bfloat162_rn(sq[c*65+n]-mq[c], sq[(c+1)*65+n]-mq[c+1]);
        __nv_bfloat162 hk = __floats2bfloat162_rn(sk[c*65+n]-mk[c], sk[(c+1)*65+n]-mk[c+1]);
        *(__nv_bfloat162*)(g_qTb + row*64 + c) = hq;
        *(__nv_bfloat162*)(g_kTb + row*64 + c) = hk;
    }
}

// ---------------- K3r: rowsums only (no E store) --------------------------------
// grid (jh=2, it=32, b=4), 256 threads, dyn smem 36864 B
__global__ __launch_bounds__(256) void DNL_k3r(){
    extern __shared__ char s3[];
    char* Ks = s3;              // K tile [128 n][72] bf16
    char* Qs = s3 + 18432;      // Q chunk [128 m][72] bf16
    int jh=blockIdx.x, it=blockIdx.y, b=blockIdx.z;
    int tid=threadIdx.x;
    int w = tid>>5, lane = tid&31, g = lane>>2, t = lane&3;
    int wn = w<<4;              // warp covers 16 n rows

    for (int i=tid;i<2048;i+=256){
        int r=i>>4, u=i&15;
        *(uint2*)(Ks + r*144 + u*8) =
            *((const uint2*)(g_kTb + ((size_t)(b<<12)+(it<<7)+r)*64) + u);
    }

    float rs0=0.f, rs1=0.f;     // rows wn+g, wn+g+8
    for (int mc2=0; mc2<16; mc2++){
        __syncthreads();        // prev mma done (and Ks loaded on first iter)
        for (int i=tid;i<2048;i+=256){
            int r=i>>4, u=i&15;
            *(uint2*)(Qs + r*144 + u*8) =
                *((const uint2*)(g_qTb + ((size_t)(b<<12)+(jh<<11)+(mc2<<7)+r)*64) + u);
        }
        __syncthreads();

        float a[16][4];
        #pragma unroll
        for (int cs=0;cs<16;cs++){ a[cs][0]=0.f; a[cs][1]=0.f; a[cs][2]=0.f; a[cs][3]=0.f; }
        #pragma unroll
        for (int k=0;k<4;k++){
            int ko = (k*16 + 2*t)*2;
            uint32_t af[4];
            const char* pa = Ks + (wn+g)*144 + ko;
            af[0] = *(const uint32_t*)pa;
            af[1] = *(const uint32_t*)(pa + 8*144);
            af[2] = *(const uint32_t*)(pa + 16);
            af[3] = *(const uint32_t*)(pa + 8*144 + 16);
            #pragma unroll
            for (int cs=0;cs<16;cs++){
                const char* pb = Qs + (cs*8+g)*144 + ko;
                uint32_t b0 = *(const uint32_t*)pb;
                uint32_t b1 = *(const uint32_t*)(pb + 16);
                mma16816(a[cs], af, b0, b1);
            }
        }
        #pragma unroll
        for (int cs=0;cs<16;cs++){
            rs0 += fexp(a[cs][0]) + fexp(a[cs][1]);
            rs1 += fexp(a[cs][2]) + fexp(a[cs][3]);
        }
    }
    rs0 += __shfl_xor_sync(0xffffffffu, rs0, 1);
    rs0 += __shfl_xor_sync(0xffffffffu, rs0, 2);
    rs1 += __shfl_xor_sync(0xffffffffu, rs1, 1);
    rs1 += __shfl_xor_sync(0xffffffffu, rs1, 2);
    if (t == 0){
        atomicAdd(&g_rowsum[(b<<12)+(it<<7)+wn+g],   rs0);
        atomicAdd(&g_rowsum[(b<<12)+(it<<7)+wn+g+8], rs1);
    }
}

// ---------------- K3b: reciprocal row sums --------------------------------------
__global__ void DNL_k3b(){
    int i = blockIdx.x*blockDim.x + threadIdx.x;
    if (i < BB*NNq) g_invrs[i] = 1.0f / g_rowsum[i];
}

// ---------------- K3c: Dinv[n,m] = 1 / sum_b exp(m_b[n]*m_b[m]) -----------------
__global__ __launch_bounds__(256) void DNL_k3c(){
    size_t t = ((size_t)blockIdx.x << 8) + threadIdx.x;   // 16M
    int n = (int)(t >> 12), mm = (int)(t & 4095);
    float s = fexp(g_m[n]*g_m[mm]) + fexp(g_m[4096+n]*g_m[4096+mm])
            + fexp(g_m[8192+n]*g_m[8192+mm]) + fexp(g_m[12288+n]*g_m[12288+mm]);
    g_Dinv[t] = __fdividef(1.0f, s);
}

// ---------------- K4r: fused recompute S -> F -> out += V*F ---------------------
// grid (b=4 fastest, mt=64), 256 threads, dyn smem 73472 B
#define SQ   0
#define SK   9216
#define SVH  18432
#define SVL  27648
#define SFH  36864
#define SFL  46080
#define SDS  55296
#define SMM  72704
#define SMN  72960
#define SIR  73216

__global__ __launch_bounds__(256) void DNL_k4r(float* __restrict__ out){
    extern __shared__ char s4[];
    float* mMv = (float*)(s4+SMM);
    float* mNv = (float*)(s4+SMN);
    float* irs = (float*)(s4+SIR);
    float* Ds  = (float*)(s4+SDS);   // [64 n][68] f32
    int b = blockIdx.x, mt = blockIdx.y;
    int mbase = mt<<6;
    int tid = threadIdx.x;
    int w = tid>>5, lane = tid&31, g = lane>>2, t = lane&3;
    int wn = (w&3)<<4;    // mma1: 16 n rows per warp   / mma2: 16 c rows
    int wm = (w>>2)<<5;   // 32 m cols per warp

    // Q tile (once per block)
    for (int i=tid;i<1024;i+=256){
        int r=i>>4, u=i&15;
        *(uint2*)(s4 + SQ + r*144 + u*8) =
            *((const uint2*)(g_qTb + ((size_t)(b<<12)+mbase+r)*64) + u);
    }
    if (tid<64) mMv[tid] = g_m[(b<<12)+mbase+tid];

    float acc2[4][4];
    #pragma unroll
    for (int mc=0;mc<4;mc++){ acc2[mc][0]=0.f; acc2[mc][1]=0.f; acc2[mc][2]=0.f; acc2[mc][3]=0.f; }

    for (int ch=0; ch<64; ch++){
        int nbase = ch<<6;
        __syncthreads();   // prev mma2 done; smem tiles free (also Qs ready on iter 0)

        // K tile [64 n][72] bf16
        for (int i=tid;i<1024;i+=256){
            int r=i>>4, u=i&15;
            *(uint2*)(s4 + SK + r*144 + u*8) =
                *((const uint2*)(g_kTb + ((size_t)(b<<12)+nbase+r)*64) + u);
        }
        // V tiles hi/lo [64 c][72]
        #pragma unroll
        for (int i0=0;i0<4;i0++){
            int idx = tid + (i0<<8);
            int c = idx>>4, p4 = idx&15;
            float4 v = *(const float4*)(g_v + (((size_t)(b<<6)+c)<<12) + nbase + 4*p4);
            __nv_bfloat16 h0=__float2bfloat16(v.x), h1=__float2bfloat16(v.y),
                          h2=__float2bfloat16(v.z), h3=__float2bfloat16(v.w);
            __nv_bfloat162 hA; hA.x=h0; hA.y=h1;
            __nv_bfloat162 hB; hB.x=h2; hB.y=h3;
            __nv_bfloat162 lA = __floats2bfloat162_rn(v.x-__bfloat162float(h0),
                                                      v.y-__bfloat162float(h1));
            __nv_bfloat162 lB = __floats2bfloat162_rn(v.z-__bfloat162float(h2),
                                                      v.w-__bfloat162float(h3));
            int off = c*144 + p4*8;
            *(__nv_bfloat162*)(s4+SVH+off)   = hA;
            *(__nv_bfloat162*)(s4+SVH+off+4) = hB;
            *(__nv_bfloat162*)(s4+SVL+off)   = lA;
            *(__nv_bfloat162*)(s4+SVL+off+4) = lB;
        }
        // Dinv tile [64 n][68] f32 (coalesced rows)
        #pragma unroll
        for (int i0=0;i0<4;i0++){
            int idx = tid + (i0<<8);
            int n = idx>>4, p4 = idx&15;
            float4 d = *(const float4*)(g_Dinv + (((size_t)(nbase+n))<<12) + mbase + 4*p4);
            *(float4*)(Ds + n*68 + 4*p4) = d;
        }
        if (tid<64){ irs[tid]=g_invrs[(b<<12)+nbase+tid]; mNv[tid]=g_m[(b<<12)+nbase+tid]; }
        __syncthreads();

        // ---- mma1 per mc, construct F, store hi/lo transposed [m][n] ----
        int nl0 = wn+g, nl1 = nl0+8;
        float ir0 = irs[nl0], ir1 = irs[nl1];
        float mn0 = mNv[nl0], mn1 = mNv[nl1];
        #pragma unroll
        for (int mc=0;mc<4;mc++){
            float a1[4] = {0.f,0.f,0.f,0.f};
            #pragma unroll
            for (int k=0;k<4;k++){
                int ko = (k*16 + 2*t)*2;
                uint32_t af[4];
                const char* pa = s4 + SK + nl0*144 + ko;
                af[0] = *(const uint32_t*)pa;
                af[1] = *(const uint32_t*)(pa + 8*144);
                af[2] = *(const uint32_t*)(pa + 16);
                af[3] = *(const uint32_t*)(pa + 8*144 + 16);
                const char* pb = s4 + SQ + (wm+mc*8+g)*144 + ko;
                uint32_t b0 = *(const uint32_t*)pb;
                uint32_t b1 = *(const uint32_t*)(pb + 16);
                mma16816(a1, af, b0, b1);
            }
            int ml = wm + mc*8 + 2*t;
            float2 d0 = *(const float2*)(Ds + nl0*68 + ml);
            float2 d1 = *(const float2*)(Ds + nl1*68 + ml);
            float mm0 = mMv[ml], mm1 = mMv[ml+1];
            float f0 = fexp(a1[0])*ir0 + fexp(mn0*mm0)*d0.x;
            float f1 = fexp(a1[1])*ir0 + fexp(mn0*mm1)*d0.y;
            float f2 = fexp(a1[2])*ir1 + fexp(mn1*mm0)*d1.x;
            float f3 = fexp(a1[3])*ir1 + fexp(mn1*mm1)*d1.y;
            __nv_bfloat16 h0=__float2bfloat16(f0), h1=__float2bfloat16(f1),
                          h2=__float2bfloat16(f2), h3=__float2bfloat16(f3);
            __nv_bfloat16* FH = (__nv_bfloat16*)(s4+SFH);
            __nv_bfloat16* FL = (__nv_bfloat16*)(s4+SFL);
            FH[ml*72     + nl0] = h0;
            FH[(ml+1)*72 + nl0] = h1;
            FH[ml*72     + nl1] = h2;
            FH[(ml+1)*72 + nl1] = h3;
            FL[ml*72     + nl0] = __float2bfloat16(f0-__bfloat162float(h0));
            FL[(ml+1)*72 + nl0] = __float2bfloat16(f1-__bfloat162float(h1));
            FL[ml*72     + nl1] = __float2bfloat16(f2-__bfloat162float(h2));
            FL[(ml+1)*72 + nl1] = __float2bfloat16(f3-__bfloat162float(h3));
        }
        __syncthreads();

        // ---- mma2: acc2 += V * F (hi*hi + lo*hi + hi*lo) ----
        #pragma unroll
        for (int k=0;k<4;k++){
            int ko = (k*16 + 2*t)*2;
            uint32_t ah[4], al[4];
            const char* pa = s4 + SVH + (wn+g)*144 + ko;
            ah[0] = *(const uint32_t*)pa;
            ah[1] = *(const uint32_t*)(pa + 8*144);
            ah[2] = *(const uint32_t*)(pa + 16);
            ah[3] = *(const uint32_t*)(pa + 8*144 + 16);
            const char* pl = s4 + SVL + (wn+g)*144 + ko;
            al[0] = *(const uint32_t*)pl;
            al[1] = *(const uint32_t*)(pl + 8*144);
            al[2] = *(const uint32_t*)(pl + 16);
            al[3] = *(const uint32_t*)(pl + 8*144 + 16);
            #pragma unroll
            for (int mc=0;mc<4;mc++){
                const char* pbh = s4 + SFH + (wm+mc*8+g)*144 + ko;
                uint32_t bh0 = *(const uint32_t*)pbh;
                uint32_t bh1 = *(const uint32_t*)(pbh + 16);
                const char* pbl = s4 + SFL + (wm+mc*8+g)*144 + ko;
                uint32_t bl0 = *(const uint32_t*)pbl;
                uint32_t bl1 = *(const uint32_t*)(pbl + 16);
                mma16816(acc2[mc], ah, bh0, bh1);
                mma16816(acc2[mc], al, bh0, bh1);
                mma16816(acc2[mc], ah, bl0, bl1);
            }
        }
    }

    // epilogue: RMW onto BN residual
    #pragma unroll
    for (int mc=0;mc<4;mc++){
        int cg = wn + g;
        int mg = mbase + wm + mc*8 + 2*t;
        float* d0 = out + (((size_t)(b<<6)+cg)<<12) + mg;
        float2 o0 = *(const float2*)d0;
        o0.x += acc2[mc][0]; o0.y += acc2[mc][1];
        *(float2*)d0 = o0;
        float* d1 = out + (((size_t)(b<<6)+cg+8)<<12) + mg;
        float2 o1 = *(const float2*)d1;
        o1.x += acc2[mc][2]; o1.y += acc2[mc][3];
        *(float2*)d1 = o1;
    }
}

// ---------------- host launcher -------------------------------------------------
extern "C" void kernel_launch(void* const* d_in, const int* in_sizes, int n_in,
                              void* d_out, int out_size)
{
    const float* x    = (const float*)d_in[0];
    const float* qw   = (const float*)d_in[1];
    const float* qb   = (const float*)d_in[2];
    const float* kw   = (const float*)d_in[3];
    const float* kb   = (const float*)d_in[4];
    const float* mw   = (const float*)d_in[5];
    const float* mb   = (const float*)d_in[6];
    const float* vw   = (const float*)d_in[7];
    const float* vb   = (const float*)d_in[8];
    const float* ww   = (const float*)d_in[9];
    const float* wb   = (const float*)d_in[10];
    const float* bng  = (const float*)d_in[11];
    const float* bnb  = (const float*)d_in[12];
    const float* bnrm = (const float*)d_in[13];
    const float* bnrv = (const float*)d_in[14];
    float* out = (float*)d_out;

    const int SM1 = 24960*4;
    const int SM3 = 36864;
    const int SM4 = 73472;
    cudaFuncSetAttribute(DNL_k1,  cudaFuncAttributeMaxDynamicSharedMemorySize, SM1);
    cudaFuncSetAttribute(DNL_k3r, cudaFuncAttributeMaxDynamicSharedMemorySize, SM3);
    cudaFuncSetAttribute(DNL_k4r, cudaFuncAttributeMaxDynamicSharedMemorySize, SM4);

    DNL_k0_zero<<<64, 256>>>();
    DNL_k1<<<dim3(32,4), 256, SM1>>>(x, qw,qb, kw,kb, mw,mb, vw,vb, ww,wb,
                                     bng,bnb,bnrm,bnrv, out);
    DNL_k2b<<<dim3(64,4), 256>>>();
    DNL_k3r<<<dim3(2,32,4), 256, SM3>>>();
    DNL_k3b<<<64, 256>>>();
    DNL_k3c<<<65536, 256>>>();
    DNL_k4r<<<dim3(4,64), 256, SM4>>>(out);
}

// round 8
// speedup vs baseline: 2.8868x; 1.1406x over previous
#include <cuda_runtime.h>
#include <cuda_bf16.h>
#include <stdint.h>

#define BB 4
#define NNq 4096

// ---------------- device scratch ----------------
__device__ float g_q[BB*64*NNq];
__device__ float g_k[BB*64*NNq];
__device__ float g_v[BB*64*NNq];
__device__ float g_m[BB*NNq];
__device__ __align__(16) __nv_bfloat16 g_qTb[(size_t)BB*NNq*64];  // [b][n][c] whitened
__device__ __align__(16) __nv_bfloat16 g_kTb[(size_t)BB*NNq*64];  // [b][n][c] whitened
__device__ float g_Dinv[(size_t)NNq*NNq];    // 64 MiB, symmetric
__device__ float g_rowsum[BB*NNq];
__device__ float g_invrs[BB*NNq];
__device__ float g_qsum[BB*64];
__device__ float g_ksum[BB*64];

// ---------------- helpers ----------------
__device__ __forceinline__ float fexp(float v){
    float y = v * 1.44269504088896341f;
    float t = y + 12582912.0f;
    int   e = __float_as_int(t) - 0x4B400000;
    float f = y - (t - 12582912.0f);
    float p = 0.00961804886f;
    p = p*f + 0.05550410866f;
    p = p*f + 0.24022650696f;
    p = p*f + 0.69314718056f;
    p = p*f + 1.0f;
    return __int_as_float(__float_as_int(p) + (e << 23));
}

__device__ __forceinline__ void mma16816(float c[4], const uint32_t a[4],
                                         uint32_t b0, uint32_t b1){
    asm volatile(
        "mma.sync.aligned.m16n8k16.row.col.f32.bf16.bf16.f32 "
        "{%0,%1,%2,%3}, {%4,%5,%6,%7}, {%8,%9}, {%0,%1,%2,%3};"
        : "+f"(c[0]), "+f"(c[1]), "+f"(c[2]), "+f"(c[3])
        : "r"(a[0]), "r"(a[1]), "r"(a[2]), "r"(a[3]), "r"(b0), "r"(b1));
}

__device__ __forceinline__ void ldsm_x4(uint32_t r[4], uint32_t addr){
    asm volatile("ldmatrix.sync.aligned.m8n8.x4.shared.b16 {%0,%1,%2,%3}, [%4];"
        : "=r"(r[0]), "=r"(r[1]), "=r"(r[2]), "=r"(r[3]) : "r"(addr));
}

// ---------------- K0: zero accumulators ----------------
__global__ void DNL_k0_zero(){
    int i = blockIdx.x*blockDim.x + threadIdx.x;
    if (i < BB*NNq) g_rowsum[i] = 0.0f;
    if (i < BB*64){ g_qsum[i] = 0.0f; g_ksum[i] = 0.0f; }
}

// ---------------- K1: q,k,v,m and BN(wx) -> out; mean partial sums -------------
__device__ __forceinline__ void conv_acc(const float* __restrict__ wsm,
                                         const float* __restrict__ xs,
                                         const float* __restrict__ bias,
                                         int o0, int n0, float acc[4][8]){
    #pragma unroll
    for (int i=0;i<4;i++){
        float bv = bias[o0+i];
        #pragma unroll
        for (int j=0;j<8;j++) acc[i][j] = bv;
    }
    #pragma unroll 8
    for (int c=0;c<64;c++){
        float4 x0 = *(const float4*)(xs + (c<<7) + n0);
        float4 x1 = *(const float4*)(xs + (c<<7) + n0 + 4);
        #pragma unroll
        for (int i=0;i<4;i++){
            float w = wsm[(o0+i)*65 + c];
            acc[i][0] += w*x0.x; acc[i][1] += w*x0.y;
            acc[i][2] += w*x0.z; acc[i][3] += w*x0.w;
            acc[i][4] += w*x1.x; acc[i][5] += w*x1.y;
            acc[i][6] += w*x1.z; acc[i][7] += w*x1.w;
        }
    }
}

__global__ __launch_bounds__(256) void DNL_k1(
    const float* __restrict__ x,
    const float* __restrict__ qw, const float* __restrict__ qb,
    const float* __restrict__ kw, const float* __restrict__ kb,
    const float* __restrict__ mw, const float* __restrict__ mb,
    const float* __restrict__ vw, const float* __restrict__ vb,
    const float* __restrict__ ww, const float* __restrict__ wb,
    const float* __restrict__ bng, const float* __restrict__ bnb,
    const float* __restrict__ bnrm, const float* __restrict__ bnrv,
    float* __restrict__ out)
{
    extern __shared__ float sm[];
    float* xs  = sm;
    float* wq  = xs  + 64*128;
    float* wk  = wq  + 64*65;
    float* wv  = wk  + 64*65;
    float* wwt = wv  + 64*65;
    float* qs  = wwt + 64*65;
    float* ks  = qs  + 64;

    int b = blockIdx.y, nt = blockIdx.x;
    int nb = nt << 7;
    int tid = threadIdx.x;

    if (tid < 64){ qs[tid] = 0.0f; ks[tid] = 0.0f; }
    for (int idx = tid; idx < 64*128; idx += 256){
        int c = idx >> 7, pos = idx & 127;
        xs[idx] = x[(((b<<6)+c)<<12) + nb + pos];
    }
    for (int idx = tid; idx < 64*64; idx += 256){
        int o = idx >> 6, c = idx & 63;
        int so = o*65 + c;
        wq[so] = qw[idx]; wk[so] = kw[idx]; wv[so] = vw[idx]; wwt[so] = ww[idx];
    }
    __syncthreads();

    if (tid < 128){
        float a = mb[0];
        #pragma unroll 8
        for (int c=0;c<64;c++) a += mw[c]*xs[(c<<7) + tid];
        g_m[(b<<12) + nb + tid] = a;
    }

    int tx = tid & 15, ty = tid >> 4;
    int n0 = tx << 3, o0 = ty << 2;
    float acc[4][8];

    conv_acc(wq, xs, qb, o0, n0, acc);
    #pragma unroll
    for (int i=0;i<4;i++){
        float* dst = g_q + ((((size_t)(b<<6)+o0+i)<<12) + nb + n0);
        *(float4*)dst     = make_float4(acc[i][0],acc[i][1],acc[i][2],acc[i][3]);
        *(float4*)(dst+4) = make_float4(acc[i][4],acc[i][5],acc[i][6],acc[i][7]);
        float s = acc[i][0]+acc[i][1]+acc[i][2]+acc[i][3]
                 +acc[i][4]+acc[i][5]+acc[i][6]+acc[i][7];
        atomicAdd(&qs[o0+i], s);
    }
    conv_acc(wk, xs, kb, o0, n0, acc);
    #pragma unroll
    for (int i=0;i<4;i++){
        float* dst = g_k + ((((size_t)(b<<6)+o0+i)<<12) + nb + n0);
        *(float4*)dst     = make_float4(acc[i][0],acc[i][1],acc[i][2],acc[i][3]);
        *(float4*)(dst+4) = make_float4(acc[i][4],acc[i][5],acc[i][6],acc[i][7]);
        float s = acc[i][0]+acc[i][1]+acc[i][2]+acc[i][3]
                 +acc[i][4]+acc[i][5]+acc[i][6]+acc[i][7];
        atomicAdd(&ks[o0+i], s);
    }
    conv_acc(wv, xs, vb, o0, n0, acc);
    #pragma unroll
    for (int i=0;i<4;i++){
        float* dst = g_v + ((((size_t)(b<<6)+o0+i)<<12) + nb + n0);
        *(float4*)dst     = make_float4(acc[i][0],acc[i][1],acc[i][2],acc[i][3]);
        *(float4*)(dst+4) = make_float4(acc[i][4],acc[i][5],acc[i][6],acc[i][7]);
    }
    conv_acc(wwt, xs, wb, o0, n0, acc);
    #pragma unroll
    for (int i=0;i<4;i++){
        int o = o0 + i;
        float sc = bng[o] * rsqrtf(bnrv[o] + 1e-5f);
        float sh = bnb[o] - bnrm[o]*sc;
        float* dst = out + (((size_t)(b<<6)+o)<<12) + nb + n0;
        *(float4*)dst     = make_float4(acc[i][0]*sc+sh, acc[i][1]*sc+sh,
                                        acc[i][2]*sc+sh, acc[i][3]*sc+sh);
        *(float4*)(dst+4) = make_float4(acc[i][4]*sc+sh, acc[i][5]*sc+sh,
                                        acc[i][6]*sc+sh, acc[i][7]*sc+sh);
    }
    __syncthreads();
    if (tid < 64){
        atomicAdd(&g_qsum[(b<<6)+tid], qs[tid]);
        atomicAdd(&g_ksum[(b<<6)+tid], ks[tid]);
    }
}

// ---------------- K2b: whiten + transpose + bf16 -------------------------------
__global__ __launch_bounds__(256) void DNL_k2b(){
    __shared__ float sq[64*65], sk[64*65], mq[64], mk[64];
    int b = blockIdx.y, nt = blockIdx.x, tid = threadIdx.x;
    if (tid<64){ mq[tid]=g_qsum[(b<<6)+tid]*(1.f/NNq); mk[tid]=g_ksum[(b<<6)+tid]*(1.f/NNq); }
    for (int i=tid;i<4096;i+=256){
        int c=i>>6, n=i&63;
        sq[c*65+n]=g_q[(((size_t)(b<<6)+c)<<12)+(nt<<6)+n];
        sk[c*65+n]=g_k[(((size_t)(b<<6)+c)<<12)+(nt<<6)+n];
    }
    __syncthreads();
    for (int i=tid;i<2048;i+=256){
        int n=i>>5, c=(i&31)<<1;
        size_t row = (size_t)(b<<12)+(nt<<6)+n;
        __nv_bfloat162 hq = __floats2bfloat162_rn(sq[c*65+n]-mq[c], sq[(c+1)*65+n]-mq[c+1]);
        __nv_bfloat162 hk = __floats2bfloat162_rn(sk[c*65+n]-mk[c], sk[(c+1)*65+n]-mk[c+1]);
        *(__nv_bfloat162*)(g_qTb + row*64 + c) = hq;
        *(__nv_bfloat162*)(g_kTb + row*64 + c) = hk;
    }
}

// ---------------- K3r: rowsums only, ldmatrix fragments -------------------------
// grid (jh=4, it=32, b=4) = 512 blocks, 256 threads, dyn smem 36864 B
__global__ __launch_bounds__(256) void DNL_k3r(){
    extern __shared__ char s3[];
    char* Ks = s3;              // K tile [128 n][72] bf16
    char* Qs = s3 + 18432;      // Q chunk [128 m][72] bf16
    int jh=blockIdx.x, it=blockIdx.y, b=blockIdx.z;
    int tid=threadIdx.x;
    int w = tid>>5, lane = tid&31, g = lane>>2, t = lane&3;
    int wn = w<<4;              // warp covers 16 n rows

    uint32_t ksA = (uint32_t)__cvta_generic_to_shared(Ks);
    uint32_t qsA = (uint32_t)__cvta_generic_to_shared(Qs);
    // A-fragment lane address (Ks rows wn..wn+15)
    uint32_t aAddr = ksA + (uint32_t)((wn + (lane&7) + ((lane>>3)&1)*8)*144
                                      + ((lane>>4)&1)*16);
    // B-fragment lane address (Qs cs-pair block of 16 rows)
    uint32_t bAddr = qsA + (uint32_t)(((lane&7) + (lane>>4)*8)*144
                                      + ((lane>>3)&1)*16);

    for (int i=tid;i<2048;i+=256){
        int r=i>>4, u=i&15;
        *(uint2*)(Ks + r*144 + u*8) =
            *((const uint2*)(g_kTb + ((size_t)(b<<12)+(it<<7)+r)*64) + u);
    }

    float rs0=0.f, rs1=0.f;     // rows wn+g, wn+g+8
    for (int mc2=0; mc2<8; mc2++){
        __syncthreads();        // prev mma done (and Ks loaded on first iter)
        for (int i=tid;i<2048;i+=256){
            int r=i>>4, u=i&15;
            *(uint2*)(Qs + r*144 + u*8) =
                *((const uint2*)(g_qTb + ((size_t)(b<<12)+(jh<<10)+(mc2<<7)+r)*64) + u);
        }
        __syncthreads();

        float a[16][4];
        #pragma unroll
        for (int cs=0;cs<16;cs++){ a[cs][0]=0.f; a[cs][1]=0.f; a[cs][2]=0.f; a[cs][3]=0.f; }
        #pragma unroll
        for (int k=0;k<4;k++){
            uint32_t af[4];
            ldsm_x4(af, aAddr + k*32);
            #pragma unroll
            for (int u=0;u<8;u++){
                uint32_t bf[4];
                ldsm_x4(bf, bAddr + u*(16*144) + k*32);
                mma16816(a[2*u],   af, bf[0], bf[1]);
                mma16816(a[2*u+1], af, bf[2], bf[3]);
            }
        }
        #pragma unroll
        for (int cs=0;cs<16;cs++){
            rs0 += fexp(a[cs][0]) + fexp(a[cs][1]);
            rs1 += fexp(a[cs][2]) + fexp(a[cs][3]);
        }
    }
    rs0 += __shfl_xor_sync(0xffffffffu, rs0, 1);
    rs0 += __shfl_xor_sync(0xffffffffu, rs0, 2);
    rs1 += __shfl_xor_sync(0xffffffffu, rs1, 1);
    rs1 += __shfl_xor_sync(0xffffffffu, rs1, 2);
    if (t == 0){
        atomicAdd(&g_rowsum[(b<<12)+(it<<7)+wn+g],   rs0);
        atomicAdd(&g_rowsum[(b<<12)+(it<<7)+wn+g+8], rs1);
    }
}

// ---------------- K3b: reciprocal row sums --------------------------------------
__global__ void DNL_k3b(){
    int i = blockIdx.x*blockDim.x + threadIdx.x;
    if (i < BB*NNq) g_invrs[i] = 1.0f / g_rowsum[i];
}

// ---------------- K3c: Dinv[n,m] = 1 / sum_b exp(m_b[n]*m_b[m]) -----------------
__global__ __launch_bounds__(256) void DNL_k3c(){
    size_t t = ((size_t)blockIdx.x << 8) + threadIdx.x;   // 16M
    int n = (int)(t >> 12), mm = (int)(t & 4095);
    float s = fexp(g_m[n]*g_m[mm]) + fexp(g_m[4096+n]*g_m[4096+mm])
            + fexp(g_m[8192+n]*g_m[8192+mm]) + fexp(g_m[12288+n]*g_m[12288+mm]);
    g_Dinv[t] = __fdividef(1.0f, s);
}

// ---------------- K4r: fused recompute S -> F -> out += V*F ---------------------
// grid (b=4 fastest, mt=64), 256 threads, dyn smem 73472 B
#define SQ   0
#define SK   9216
#define SVH  18432
#define SVL  27648
#define SFH  36864
#define SFL  46080
#define SDS  55296
#define SMM  72704
#define SMN  72960
#define SIR  73216

__global__ __launch_bounds__(256) void DNL_k4r(float* __restrict__ out){
    extern __shared__ char s4[];
    float* mMv = (float*)(s4+SMM);
    float* mNv = (float*)(s4+SMN);
    float* irs = (float*)(s4+SIR);
    float* Ds  = (float*)(s4+SDS);   // [64 n][68] f32
    int b = blockIdx.x, mt = blockIdx.y;
    int mbase = mt<<6;
    int tid = threadIdx.x;
    int w = tid>>5, lane = tid&31, g = lane>>2, t = lane&3;
    int wn = (w&3)<<4;    // mma1: 16 n rows per warp   / mma2: 16 c rows
    int wm = (w>>2)<<5;   // 32 m cols per warp

    uint32_t sA = (uint32_t)__cvta_generic_to_shared(s4);
    // A-fragment lane offsets (16-row blocks at wn)
    uint32_t aRow = (uint32_t)((wn + (lane&7) + ((lane>>3)&1)*8)*144
                               + ((lane>>4)&1)*16);
    // B-fragment lane offsets (16-row pair blocks at wm)
    uint32_t bRow = (uint32_t)((wm + (lane&7) + (lane>>4)*8)*144
                               + ((lane>>3)&1)*16);
    uint32_t aK  = sA + SK  + aRow;
    uint32_t aVH = sA + SVH + aRow;
    uint32_t aVL = sA + SVL + aRow;
    uint32_t bQ  = sA + SQ  + bRow;
    uint32_t bFH = sA + SFH + bRow;
    uint32_t bFL = sA + SFL + bRow;

    // Q tile (once per block)
    for (int i=tid;i<1024;i+=256){
        int r=i>>4, u=i&15;
        *(uint2*)(s4 + SQ + r*144 + u*8) =
            *((const uint2*)(g_qTb + ((size_t)(b<<12)+mbase+r)*64) + u);
    }
    if (tid<64) mMv[tid] = g_m[(b<<12)+mbase+tid];

    float acc2[4][4];
    #pragma unroll
    for (int mc=0;mc<4;mc++){ acc2[mc][0]=0.f; acc2[mc][1]=0.f; acc2[mc][2]=0.f; acc2[mc][3]=0.f; }

    for (int ch=0; ch<64; ch++){
        int nbase = ch<<6;
        __syncthreads();   // prev mma2 done; smem tiles free (also Qs ready on iter 0)

        // K tile [64 n][72] bf16
        for (int i=tid;i<1024;i+=256){
            int r=i>>4, u=i&15;
            *(uint2*)(s4 + SK + r*144 + u*8) =
                *((const uint2*)(g_kTb + ((size_t)(b<<12)+nbase+r)*64) + u);
        }
        // V tiles hi/lo [64 c][72]
        #pragma unroll
        for (int i0=0;i0<4;i0++){
            int idx = tid + (i0<<8);
            int c = idx>>4, p4 = idx&15;
            float4 v = *(const float4*)(g_v + (((size_t)(b<<6)+c)<<12) + nbase + 4*p4);
            __nv_bfloat16 h0=__float2bfloat16(v.x), h1=__float2bfloat16(v.y),
                          h2=__float2bfloat16(v.z), h3=__float2bfloat16(v.w);
            __nv_bfloat162 hA; hA.x=h0; hA.y=h1;
            __nv_bfloat162 hB; hB.x=h2; hB.y=h3;
            __nv_bfloat162 lA = __floats2bfloat162_rn(v.x-__bfloat162float(h0),
                                                      v.y-__bfloat162float(h1));
            __nv_bfloat162 lB = __floats2bfloat162_rn(v.z-__bfloat162float(h2),
                                                      v.w-__bfloat162float(h3));
            int off = c*144 + p4*8;
            *(__nv_bfloat162*)(s4+SVH+off)   = hA;
            *(__nv_bfloat162*)(s4+SVH+off+4) = hB;
            *(__nv_bfloat162*)(s4+SVL+off)   = lA;
            *(__nv_bfloat162*)(s4+SVL+off+4) = lB;
        }
        // Dinv tile [64 n][68] f32 (coalesced rows)
        #pragma unroll
        for (int i0=0;i0<4;i0++){
            int idx = tid + (i0<<8);
            int n = idx>>4, p4 = idx&15;
            float4 d = *(const float4*)(g_Dinv + (((size_t)(nbase+n))<<12) + mbase + 4*p4);
            *(float4*)(Ds + n*68 + 4*p4) = d;
        }
        if (tid<64){ irs[tid]=g_invrs[(b<<12)+nbase+tid]; mNv[tid]=g_m[(b<<12)+nbase+tid]; }
        __syncthreads();

        // ---- mma1: S = K x Q^T for this warp's 16 n rows x 32 m ----
        float a1[4][4];
        #pragma unroll
        for (int mc=0;mc<4;mc++){ a1[mc][0]=0.f; a1[mc][1]=0.f; a1[mc][2]=0.f; a1[mc][3]=0.f; }
        #pragma unroll
        for (int k=0;k<4;k++){
            uint32_t af[4], bf0[4], bf1[4];
            ldsm_x4(af,  aK + k*32);
            ldsm_x4(bf0, bQ + k*32);
            ldsm_x4(bf1, bQ + 16*144 + k*32);
            mma16816(a1[0], af, bf0[0], bf0[1]);
            mma16816(a1[1], af, bf0[2], bf0[3]);
            mma16816(a1[2], af, bf1[0], bf1[1]);
            mma16816(a1[3], af, bf1[2], bf1[3]);
        }
        // construct F, store hi/lo transposed [m][n]
        int nl0 = wn+g, nl1 = nl0+8;
        float ir0 = irs[nl0], ir1 = irs[nl1];
        float mn0 = mNv[nl0], mn1 = mNv[nl1];
        #pragma unroll
        for (int mc=0;mc<4;mc++){
            int ml = wm + mc*8 + 2*t;
            float2 d0 = *(const float2*)(Ds + nl0*68 + ml);
            float2 d1 = *(const float2*)(Ds + nl1*68 + ml);
            float mm0 = mMv[ml], mm1 = mMv[ml+1];
            float f0 = fexp(a1[mc][0])*ir0 + fexp(mn0*mm0)*d0.x;
            float f1 = fexp(a1[mc][1])*ir0 + fexp(mn0*mm1)*d0.y;
            float f2 = fexp(a1[mc][2])*ir1 + fexp(mn1*mm0)*d1.x;
            float f3 = fexp(a1[mc][3])*ir1 + fexp(mn1*mm1)*d1.y;
            __nv_bfloat16 h0=__float2bfloat16(f0), h1=__float2bfloat16(f1),
                          h2=__float2bfloat16(f2), h3=__float2bfloat16(f3);
            __nv_bfloat16* FH = (__nv_bfloat16*)(s4+SFH);
            __nv_bfloat16* FL = (__nv_bfloat16*)(s4+SFL);
            FH[ml*72     + nl0] = h0;
            FH[(ml+1)*72 + nl0] = h1;
            FH[ml*72     + nl1] = h2;
            FH[(ml+1)*72 + nl1] = h3;
            FL[ml*72     + nl0] = __float2bfloat16(f0-__bfloat162float(h0));
            FL[(ml+1)*72 + nl0] = __float2bfloat16(f1-__bfloat162float(h1));
            FL[ml*72     + nl1] = __float2bfloat16(f2-__bfloat162float(h2));
            FL[(ml+1)*72 + nl1] = __float2bfloat16(f3-__bfloat162float(h3));
        }
        __syncthreads();

        // ---- mma2: acc2 += V * F (hi*hi + lo*hi + hi*lo) ----
        #pragma unroll
        for (int k=0;k<4;k++){
            uint32_t ah[4], al[4], bh0[4], bh1[4], bl0[4], bl1[4];
            ldsm_x4(ah,  aVH + k*32);
            ldsm_x4(al,  aVL + k*32);
            ldsm_x4(bh0, bFH + k*32);
            ldsm_x4(bh1, bFH + 16*144 + k*32);
            ldsm_x4(bl0, bFL + k*32);
            ldsm_x4(bl1, bFL + 16*144 + k*32);
            mma16816(acc2[0], ah, bh0[0], bh0[1]);
            mma16816(acc2[1], ah, bh0[2], bh0[3]);
            mma16816(acc2[2], ah, bh1[0], bh1[1]);
            mma16816(acc2[3], ah, bh1[2], bh1[3]);
            mma16816(acc2[0], al, bh0[0], bh0[1]);
            mma16816(acc2[1], al, bh0[2], bh0[3]);
            mma16816(acc2[2], al, bh1[0], bh1[1]);
            mma16816(acc2[3], al, bh1[2], bh1[3]);
            mma16816(acc2[0], ah, bl0[0], bl0[1]);
            mma16816(acc2[1], ah, bl0[2], bl0[3]);
            mma16816(acc2[2], ah, bl1[0], bl1[1]);
            mma16816(acc2[3], ah, bl1[2], bl1[3]);
        }
    }

    // epilogue: RMW onto BN residual
    #pragma unroll
    for (int mc=0;mc<4;mc++){
        int cg = wn + g;
        int mg = mbase + wm + mc*8 + 2*t;
        float* d0 = out + (((size_t)(b<<6)+cg)<<12) + mg;
        float2 o0 = *(const float2*)d0;
        o0.x += acc2[mc][0]; o0.y += acc2[mc][1];
        *(float2*)d0 = o0;
        float* d1 = out + (((size_t)(b<<6)+cg+8)<<12) + mg;
        float2 o1 = *(const float2*)d1;
        o1.x += acc2[mc][2]; o1.y += acc2[mc][3];
        *(float2*)d1 = o1;
    }
}

// ---------------- host launcher -------------------------------------------------
extern "C" void kernel_launch(void* const* d_in, const int* in_sizes, int n_in,
                              void* d_out, int out_size)
{
    const float* x    = (const float*)d_in[0];
    const float* qw   = (const float*)d_in[1];
    const float* qb   = (const float*)d_in[2];
    const float* kw   = (const float*)d_in[3];
    const float* kb   = (const float*)d_in[4];
    const float* mw   = (const float*)d_in[5];
    const float* mb   = (const float*)d_in[6];
    const float* vw   = (const float*)d_in[7];
    const float* vb   = (const float*)d_in[8];
    const float* ww   = (const float*)d_in[9];
    const float* wb   = (const float*)d_in[10];
    const float* bng  = (const float*)d_in[11];
    const float* bnb  = (const float*)d_in[12];
    const float* bnrm = (const float*)d_in[13];
    const float* bnrv = (const float*)d_in[14];
    float* out = (float*)d_out;

    const int SM1 = 24960*4;
    const int SM3 = 36864;
    const int SM4 = 73472;
    cudaFuncSetAttribute(DNL_k1,  cudaFuncAttributeMaxDynamicSharedMemorySize, SM1);
    cudaFuncSetAttribute(DNL_k3r, cudaFuncAttributeMaxDynamicSharedMemorySize, SM3);
    cudaFuncSetAttribute(DNL_k4r, cudaFuncAttributeMaxDynamicSharedMemorySize, SM4);

    DNL_k0_zero<<<64, 256>>>();
    DNL_k1<<<dim3(32,4), 256, SM1>>>(x, qw,qb, kw,kb, mw,mb, vw,vb, ww,wb,
                                     bng,bnb,bnrm,bnrv, out);
    DNL_k2b<<<dim3(64,4), 256>>>();
    DNL_k3r<<<dim3(4,32,4), 256, SM3>>>();
    DNL_k3b<<<64, 256>>>();
    DNL_k3c<<<65536, 256>>>();
    DNL_k4r<<<dim3(4,64), 256, SM4>>>(out);
}

// round 9
// speedup vs baseline: 3.3834x; 1.1720x over previous
#include <cuda_runtime.h>
#include <cuda_bf16.h>
#include <stdint.h>

#define BB 4
#define NNq 4096

// ---------------- device scratch ----------------
__device__ float g_q[BB*64*NNq];
__device__ float g_k[BB*64*NNq];
__device__ float g_v[BB*64*NNq];
__device__ float g_m[BB*NNq];
__device__ __align__(16) __nv_bfloat16 g_qTb[(size_t)BB*NNq*64];  // [b][n][c] whitened
__device__ __align__(16) __nv_bfloat16 g_kTb[(size_t)BB*NNq*64];  // [b][n][c] whitened
__device__ __align__(16) __nv_bfloat16 g_vHi[(size_t)BB*64*NNq];  // [b][c][n]
__device__ __align__(16) __nv_bfloat16 g_vLo[(size_t)BB*64*NNq];  // [b][c][n]
__device__ float g_Dinv[(size_t)NNq*NNq];    // 64 MiB, symmetric
__device__ float g_rowsum[BB*NNq];
__device__ float g_invrs[BB*NNq];
__device__ float g_qsum[BB*64];
__device__ float g_ksum[BB*64];

// ---------------- helpers ----------------
__device__ __forceinline__ float fexp(float v){
    float y = v * 1.44269504088896341f;
    float t = y + 12582912.0f;
    int   e = __float_as_int(t) - 0x4B400000;
    float f = y - (t - 12582912.0f);
    float p = 0.00961804886f;
    p = p*f + 0.05550410866f;
    p = p*f + 0.24022650696f;
    p = p*f + 0.69314718056f;
    p = p*f + 1.0f;
    return __int_as_float(__float_as_int(p) + (e << 23));
}

__device__ __forceinline__ void mma16816(float c[4], const uint32_t a[4],
                                         uint32_t b0, uint32_t b1){
    asm volatile(
        "mma.sync.aligned.m16n8k16.row.col.f32.bf16.bf16.f32 "
        "{%0,%1,%2,%3}, {%4,%5,%6,%7}, {%8,%9}, {%0,%1,%2,%3};"
        : "+f"(c[0]), "+f"(c[1]), "+f"(c[2]), "+f"(c[3])
        : "r"(a[0]), "r"(a[1]), "r"(a[2]), "r"(a[3]), "r"(b0), "r"(b1));
}

__device__ __forceinline__ void ldsm_x4(uint32_t r[4], uint32_t addr){
    asm volatile("ldmatrix.sync.aligned.m8n8.x4.shared.b16 {%0,%1,%2,%3}, [%4];"
        : "=r"(r[0]), "=r"(r[1]), "=r"(r[2]), "=r"(r[3]) : "r"(addr));
}

#define CPA16(d, s) asm volatile("cp.async.cg.shared.global [%0], [%1], 16;" \
        :: "r"((uint32_t)(d)), "l"(s) : "memory")
#define CPCOMMIT()  asm volatile("cp.async.commit_group;" ::: "memory")
#define CPWAIT0()   asm volatile("cp.async.wait_group 0;" ::: "memory")

// ---------------- K0: zero accumulators ----------------
__global__ void DNL_k0_zero(){
    int i = blockIdx.x*blockDim.x + threadIdx.x;
    if (i < BB*NNq) g_rowsum[i] = 0.0f;
    if (i < BB*64){ g_qsum[i] = 0.0f; g_ksum[i] = 0.0f; }
}

// ---------------- K1: q,k,v,m and BN(wx) -> out; mean partial sums -------------
__device__ __forceinline__ void conv_acc(const float* __restrict__ wsm,
                                         const float* __restrict__ xs,
                                         const float* __restrict__ bias,
                                         int o0, int n0, float acc[4][8]){
    #pragma unroll
    for (int i=0;i<4;i++){
        float bv = bias[o0+i];
        #pragma unroll
        for (int j=0;j<8;j++) acc[i][j] = bv;
    }
    #pragma unroll 8
    for (int c=0;c<64;c++){
        float4 x0 = *(const float4*)(xs + (c<<7) + n0);
        float4 x1 = *(const float4*)(xs + (c<<7) + n0 + 4);
        #pragma unroll
        for (int i=0;i<4;i++){
            float w = wsm[(o0+i)*65 + c];
            acc[i][0] += w*x0.x; acc[i][1] += w*x0.y;
            acc[i][2] += w*x0.z; acc[i][3] += w*x0.w;
            acc[i][4] += w*x1.x; acc[i][5] += w*x1.y;
            acc[i][6] += w*x1.z; acc[i][7] += w*x1.w;
        }
    }
}

__global__ __launch_bounds__(256) void DNL_k1(
    const float* __restrict__ x,
    const float* __restrict__ qw, const float* __restrict__ qb,
    const float* __restrict__ kw, const float* __restrict__ kb,
    const float* __restrict__ mw, const float* __restrict__ mb,
    const float* __restrict__ vw, const float* __restrict__ vb,
    const float* __restrict__ ww, const float* __restrict__ wb,
    const float* __restrict__ bng, const float* __restrict__ bnb,
    const float* __restrict__ bnrm, const float* __restrict__ bnrv,
    float* __restrict__ out)
{
    extern __shared__ float sm[];
    float* xs  = sm;
    float* wq  = xs  + 64*128;
    float* wk  = wq  + 64*65;
    float* wv  = wk  + 64*65;
    float* wwt = wv  + 64*65;
    float* qs  = wwt + 64*65;
    float* ks  = qs  + 64;

    int b = blockIdx.y, nt = blockIdx.x;
    int nb = nt << 7;
    int tid = threadIdx.x;

    if (tid < 64){ qs[tid] = 0.0f; ks[tid] = 0.0f; }
    for (int idx = tid; idx < 64*128; idx += 256){
        int c = idx >> 7, pos = idx & 127;
        xs[idx] = x[(((b<<6)+c)<<12) + nb + pos];
    }
    for (int idx = tid; idx < 64*64; idx += 256){
        int o = idx >> 6, c = idx & 63;
        int so = o*65 + c;
        wq[so] = qw[idx]; wk[so] = kw[idx]; wv[so] = vw[idx]; wwt[so] = ww[idx];
    }
    __syncthreads();

    if (tid < 128){
        float a = mb[0];
        #pragma unroll 8
        for (int c=0;c<64;c++) a += mw[c]*xs[(c<<7) + tid];
        g_m[(b<<12) + nb + tid] = a;
    }

    int tx = tid & 15, ty = tid >> 4;
    int n0 = tx << 3, o0 = ty << 2;
    float acc[4][8];

    conv_acc(wq, xs, qb, o0, n0, acc);
    #pragma unroll
    for (int i=0;i<4;i++){
        float* dst = g_q + ((((size_t)(b<<6)+o0+i)<<12) + nb + n0);
        *(float4*)dst     = make_float4(acc[i][0],acc[i][1],acc[i][2],acc[i][3]);
        *(float4*)(dst+4) = make_float4(acc[i][4],acc[i][5],acc[i][6],acc[i][7]);
        float s = acc[i][0]+acc[i][1]+acc[i][2]+acc[i][3]
                 +acc[i][4]+acc[i][5]+acc[i][6]+acc[i][7];
        atomicAdd(&qs[o0+i], s);
    }
    conv_acc(wk, xs, kb, o0, n0, acc);
    #pragma unroll
    for (int i=0;i<4;i++){
        float* dst = g_k + ((((size_t)(b<<6)+o0+i)<<12) + nb + n0);
        *(float4*)dst     = make_float4(acc[i][0],acc[i][1],acc[i][2],acc[i][3]);
        *(float4*)(dst+4) = make_float4(acc[i][4],acc[i][5],acc[i][6],acc[i][7]);
        float s = acc[i][0]+acc[i][1]+acc[i][2]+acc[i][3]
                 +acc[i][4]+acc[i][5]+acc[i][6]+acc[i][7];
        atomicAdd(&ks[o0+i], s);
    }
    conv_acc(wv, xs, vb, o0, n0, acc);
    #pragma unroll
    for (int i=0;i<4;i++){
        float* dst = g_v + ((((size_t)(b<<6)+o0+i)<<12) + nb + n0);
        *(float4*)dst     = make_float4(acc[i][0],acc[i][1],acc[i][2],acc[i][3]);
        *(float4*)(dst+4) = make_float4(acc[i][4],acc[i][5],acc[i][6],acc[i][7]);
    }
    conv_acc(wwt, xs, wb, o0, n0, acc);
    #pragma unroll
    for (int i=0;i<4;i++){
        int o = o0 + i;
        float sc = bng[o] * rsqrtf(bnrv[o] + 1e-5f);
        float sh = bnb[o] - bnrm[o]*sc;
        float* dst = out + (((size_t)(b<<6)+o)<<12) + nb + n0;
        *(float4*)dst     = make_float4(acc[i][0]*sc+sh, acc[i][1]*sc+sh,
                                        acc[i][2]*sc+sh, acc[i][3]*sc+sh);
        *(float4*)(dst+4) = make_float4(acc[i][4]*sc+sh, acc[i][5]*sc+sh,
                                        acc[i][6]*sc+sh, acc[i][7]*sc+sh);
    }
    __syncthreads();
    if (tid < 64){
        atomicAdd(&g_qsum[(b<<6)+tid], qs[tid]);
        atomicAdd(&g_ksum[(b<<6)+tid], ks[tid]);
    }
}

// ---------------- K2b: whiten + transpose + bf16 -------------------------------
__global__ __launch_bounds__(256) void DNL_k2b(){
    __shared__ float sq[64*65], sk[64*65], mq[64], mk[64];
    int b = blockIdx.y, nt = blockIdx.x, tid = threadIdx.x;
    if (tid<64){ mq[tid]=g_qsum[(b<<6)+tid]*(1.f/NNq); mk[tid]=g_ksum[(b<<6)+tid]*(1.f/NNq); }
    for (int i=tid;i<4096;i+=256){
        int c=i>>6, n=i&63;
        sq[c*65+n]=g_q[(((size_t)(b<<6)+c)<<12)+(nt<<6)+n];
        sk[c*65+n]=g_k[(((size_t)(b<<6)+c)<<12)+(nt<<6)+n];
    }
    __syncthreads();
    for (int i=tid;i<2048;i+=256){
        int n=i>>5, c=(i&31)<<1;
        size_t row = (size_t)(b<<12)+(nt<<6)+n;
        __nv_bfloat162 hq = __floats2bfloat162_rn(sq[c*65+n]-mq[c], sq[(c+1)*65+n]-mq[c+1]);
        __nv_bfloat162 hk = __floats2bfloat162_rn(sk[c*65+n]-mk[c], sk[(c+1)*65+n]-mk[c+1]);
        *(__nv_bfloat162*)(g_qTb + row*64 + c) = hq;
        *(__nv_bfloat162*)(g_kTb + row*64 + c) = hk;
    }
}

// ---------------- K2v: split V into hi/lo bf16 ----------------------------------
__global__ __launch_bounds__(256) void DNL_k2v(){
    size_t i = (((size_t)blockIdx.x<<8) + threadIdx.x) << 1;   // 2 elems/thread
    float2 v = *(const float2*)(g_v + i);
    __nv_bfloat16 h0=__float2bfloat16(v.x), h1=__float2bfloat16(v.y);
    __nv_bfloat162 hi; hi.x=h0; hi.y=h1;
    __nv_bfloat162 lo = __floats2bfloat162_rn(v.x-__bfloat162float(h0),
                                              v.y-__bfloat162float(h1));
    *(__nv_bfloat162*)(g_vHi + i) = hi;
    *(__nv_bfloat162*)(g_vLo + i) = lo;
}

// ---------------- K3r: rowsums only, cp.async double-buffered Q -----------------
// grid (jh=4, it=32, b=4) = 512 blocks, 256 threads, dyn smem 55296 B
__global__ __launch_bounds__(256) void DNL_k3r(){
    extern __shared__ char s3[];
    uint32_t sA = (uint32_t)__cvta_generic_to_shared(s3);
    int jh=blockIdx.x, it=blockIdx.y, b=blockIdx.z;
    int tid=threadIdx.x;
    int w = tid>>5, lane = tid&31, g = lane>>2, t = lane&3;
    int wn = w<<4;

    uint32_t aAddr = sA + (uint32_t)((wn + (lane&7) + ((lane>>3)&1)*8)*144
                                     + ((lane>>4)&1)*16);
    uint32_t bRel  = (uint32_t)(((lane&7) + (lane>>4)*8)*144 + ((lane>>3)&1)*16);

    // prologue: K tile + Q chunk 0
    for (int i=tid;i<1024;i+=256){
        int r=i>>3, u=i&7;
        CPA16(sA + r*144 + u*16,
              g_kTb + ((size_t)(b<<12)+(it<<7)+r)*64 + u*8);
    }
    for (int i=tid;i<1024;i+=256){
        int r=i>>3, u=i&7;
        CPA16(sA + 18432 + r*144 + u*16,
              g_qTb + ((size_t)(b<<12)+(jh<<10)+r)*64 + u*8);
    }
    CPCOMMIT();

    float rs0=0.f, rs1=0.f;
    for (int mc2=0; mc2<8; mc2++){
        CPWAIT0();
        __syncthreads();
        if (mc2 < 7){
            uint32_t dst = sA + 18432 + (((mc2+1)&1) ? 18432u : 0u);
            for (int i=tid;i<1024;i+=256){
                int r=i>>3, u=i&7;
                CPA16(dst + r*144 + u*16,
                      g_qTb + ((size_t)(b<<12)+(jh<<10)+((mc2+1)<<7)+r)*64 + u*8);
            }
            CPCOMMIT();
        }
        uint32_t bAddr = sA + 18432 + ((mc2&1) ? 18432u : 0u) + bRel;

        float a[16][4];
        #pragma unroll
        for (int cs=0;cs<16;cs++){ a[cs][0]=0.f; a[cs][1]=0.f; a[cs][2]=0.f; a[cs][3]=0.f; }
        #pragma unroll
        for (int k=0;k<4;k++){
            uint32_t af[4];
            ldsm_x4(af, aAddr + k*32);
            #pragma unroll
            for (int u=0;u<8;u++){
                uint32_t bf[4];
                ldsm_x4(bf, bAddr + u*(16*144) + k*32);
                mma16816(a[2*u],   af, bf[0], bf[1]);
                mma16816(a[2*u+1], af, bf[2], bf[3]);
            }
        }
        #pragma unroll
        for (int cs=0;cs<16;cs++){
            rs0 += fexp(a[cs][0]) + fexp(a[cs][1]);
            rs1 += fexp(a[cs][2]) + fexp(a[cs][3]);
        }
    }
    rs0 += __shfl_xor_sync(0xffffffffu, rs0, 1);
    rs0 += __shfl_xor_sync(0xffffffffu, rs0, 2);
    rs1 += __shfl_xor_sync(0xffffffffu, rs1, 1);
    rs1 += __shfl_xor_sync(0xffffffffu, rs1, 2);
    if (t == 0){
        atomicAdd(&g_rowsum[(b<<12)+(it<<7)+wn+g],   rs0);
        atomicAdd(&g_rowsum[(b<<12)+(it<<7)+wn+g+8], rs1);
    }
}

// ---------------- K3b: reciprocal row sums --------------------------------------
__global__ void DNL_k3b(){
    int i = blockIdx.x*blockDim.x + threadIdx.x;
    if (i < BB*NNq) g_invrs[i] = 1.0f / g_rowsum[i];
}

// ---------------- K3c: Dinv via FFMA Newton reciprocal --------------------------
__global__ __launch_bounds__(256) void DNL_k3c(){
    size_t tt = ((size_t)blockIdx.x << 8) + threadIdx.x;   // 16M
    int n = (int)(tt >> 12), mm = (int)(tt & 4095);
    float s = fexp(g_m[n]*g_m[mm]) + fexp(g_m[4096+n]*g_m[4096+mm])
            + fexp(g_m[8192+n]*g_m[8192+mm]) + fexp(g_m[12288+n]*g_m[12288+mm]);
    float r = __int_as_float(0x7EF311C3 - __float_as_int(s));
    r = r*(2.0f - s*r);
    r = r*(2.0f - s*r);
    r = r*(2.0f - s*r);
    g_Dinv[tt] = r;
}

// ---------------- K4r: pipelined fused recompute S -> F -> out += V*F -----------
// grid (b=4 fastest, mt=64), 256 threads, dyn smem 101120 B
// layout: SQ 0(9216) | SFH 9216 | SFL 18432 | consts 27648 | stage0 28416 |
//         stage1 56064 | Ds 83712 (64x68 f32)
#define K4_SQ    0
#define K4_SFH   9216
#define K4_SFL   18432
#define K4_MM    27648
#define K4_IR    27904
#define K4_MN    28160
#define K4_ST0   28416
#define K4_ST1   56064
#define K4_DS    83712
#define K4_STK   0        // K within stage
#define K4_STVH  9216
#define K4_STVL  18432

__device__ __forceinline__ void k4_issue_stage(uint32_t dstBase, int b, int nbase,
                                               int tid){
    for (int i=tid;i<512;i+=256){
        int r=i>>3, u=i&7;
        CPA16(dstBase + K4_STK + r*144 + u*16,
              g_kTb + ((size_t)(b<<12)+nbase+r)*64 + u*8);
    }
    for (int i=tid;i<512;i+=256){
        int c=i>>3, u=i&7;
        CPA16(dstBase + K4_STVH + c*144 + u*16,
              g_vHi + (((size_t)(b<<6)+c)<<12) + nbase + u*8);
    }
    for (int i=tid;i<512;i+=256){
        int c=i>>3, u=i&7;
        CPA16(dstBase + K4_STVL + c*144 + u*16,
              g_vLo + (((size_t)(b<<6)+c)<<12) + nbase + u*8);
    }
}

__device__ __forceinline__ void k4_issue_ds(uint32_t sA, int b, int nbase, int mbase,
                                            int tid){
    for (int i=tid;i<1024;i+=256){
        int n=i>>4, u=i&15;
        CPA16(sA + K4_DS + n*272 + u*16,
              g_Dinv + (((size_t)(nbase+n))<<12) + mbase + u*4);
    }
    if (tid < 16)
        CPA16(sA + K4_IR + tid*16, g_invrs + (b<<12) + nbase + tid*4);
    else if (tid < 32)
        CPA16(sA + K4_MN + (tid-16)*16, g_m + (b<<12) + nbase + (tid-16)*4);
}

__global__ __launch_bounds__(256,2) void DNL_k4r(float* __restrict__ out){
    extern __shared__ char s4[];
    uint32_t sA = (uint32_t)__cvta_generic_to_shared(s4);
    float* mMv = (float*)(s4+K4_MM);
    float* irs = (float*)(s4+K4_IR);
    float* mNv = (float*)(s4+K4_MN);
    float* Ds  = (float*)(s4+K4_DS);   // [64][68] f32
    int b = blockIdx.x, mt = blockIdx.y;
    int mbase = mt<<6;
    int tid = threadIdx.x;
    int w = tid>>5, lane = tid&31, g = lane>>2, t = lane&3;
    int wn = (w&3)<<4;
    int wm = (w>>2)<<5;

    uint32_t aRow = (uint32_t)((wn + (lane&7) + ((lane>>3)&1)*8)*144
                               + ((lane>>4)&1)*16);
    uint32_t bRow = (uint32_t)((wm + (lane&7) + (lane>>4)*8)*144
                               + ((lane>>3)&1)*16);
    uint32_t bQ  = sA + K4_SQ  + bRow;
    uint32_t bFH = sA + K4_SFH + bRow;
    uint32_t bFL = sA + K4_SFL + bRow;

    // prologue
    for (int i=tid;i<512;i+=256){
        int r=i>>3, u=i&7;
        CPA16(sA + K4_SQ + r*144 + u*16,
              g_qTb + ((size_t)(b<<12)+mbase+r)*64 + u*8);
    }
    k4_issue_stage(sA + K4_ST0, b, 0, tid);
    k4_issue_ds(sA, b, 0, mbase, tid);
    CPCOMMIT();
    if (tid<64) mMv[tid] = g_m[(b<<12)+mbase+tid];

    float acc2[4][4];
    #pragma unroll
    for (int mc=0;mc<4;mc++){ acc2[mc][0]=0.f; acc2[mc][1]=0.f; acc2[mc][2]=0.f; acc2[mc][3]=0.f; }

    for (int ch=0; ch<64; ch++){
        int nbase = ch<<6;
        CPWAIT0();
        __syncthreads();   // data landed; all warps past mma2(ch-1)

        uint32_t stg = sA + ((ch&1) ? K4_ST1 : K4_ST0);
        if (ch < 63){
            k4_issue_stage(sA + (((ch+1)&1) ? K4_ST1 : K4_ST0), b, (ch+1)<<6, tid);
            CPCOMMIT();
        }

        // ---- mma1: S = K x Q^T ----
        float a1[4][4];
        #pragma unroll
        for (int mc=0;mc<4;mc++){ a1[mc][0]=0.f; a1[mc][1]=0.f; a1[mc][2]=0.f; a1[mc][3]=0.f; }
        uint32_t aK = stg + K4_STK + aRow;
        #pragma unroll
        for (int k=0;k<4;k++){
            uint32_t af[4], bf0[4], bf1[4];
            ldsm_x4(af,  aK + k*32);
            ldsm_x4(bf0, bQ + k*32);
            ldsm_x4(bf1, bQ + 16*144 + k*32);
            mma16816(a1[0], af, bf0[0], bf0[1]);
            mma16816(a1[1], af, bf0[2], bf0[3]);
            mma16816(a1[2], af, bf1[0], bf1[1]);
            mma16816(a1[3], af, bf1[2], bf1[3]);
        }
        // ---- construct F -> FH/FL (transposed [m][n]) ----
        int nl0 = wn+g, nl1 = nl0+8;
        float ir0 = irs[nl0], ir1 = irs[nl1];
        float mn0 = mNv[nl0], mn1 = mNv[nl1];
        #pragma unroll
        for (int mc=0;mc<4;mc++){
            int ml = wm + mc*8 + 2*t;
            float2 d0 = *(const float2*)(Ds + nl0*68 + ml);
            float2 d1 = *(const float2*)(Ds + nl1*68 + ml);
            float mm0 = mMv[ml], mm1 = mMv[ml+1];
            float f0 = fexp(a1[mc][0])*ir0 + fexp(mn0*mm0)*d0.x;
            float f1 = fexp(a1[mc][1])*ir0 + fexp(mn0*mm1)*d0.y;
            float f2 = fexp(a1[mc][2])*ir1 + fexp(mn1*mm0)*d1.x;
            float f3 = fexp(a1[mc][3])*ir1 + fexp(mn1*mm1)*d1.y;
            __nv_bfloat16 h0=__float2bfloat16(f0), h1=__float2bfloat16(f1),
                          h2=__float2bfloat16(f2), h3=__float2bfloat16(f3);
            __nv_bfloat16* FH = (__nv_bfloat16*)(s4+K4_SFH);
            __nv_bfloat16* FL = (__nv_bfloat16*)(s4+K4_SFL);
            FH[ml*72     + nl0] = h0;
            FH[(ml+1)*72 + nl0] = h1;
            FH[ml*72     + nl1] = h2;
            FH[(ml+1)*72 + nl1] = h3;
            FL[ml*72     + nl0] = __float2bfloat16(f0-__bfloat162float(h0));
            FL[(ml+1)*72 + nl0] = __float2bfloat16(f1-__bfloat162float(h1));
            FL[ml*72     + nl1] = __float2bfloat16(f2-__bfloat162float(h2));
            FL[(ml+1)*72 + nl1] = __float2bfloat16(f3-__bfloat162float(h3));
        }
        __syncthreads();   // F visible; Ds/irs/mNv consumed

        if (ch < 63){
            k4_issue_ds(sA, b, (ch+1)<<6, mbase, tid);
            CPCOMMIT();
        }

        // ---- mma2: acc2 += V * F ----
        uint32_t aVH = stg + K4_STVH + aRow;
        uint32_t aVL = stg + K4_STVL + aRow;
        #pragma unroll
        for (int k=0;k<4;k++){
            uint32_t ah[4], al[4], bh0[4], bh1[4], bl0[4], bl1[4];
            ldsm_x4(ah,  aVH + k*32);
            ldsm_x4(al,  aVL + k*32);
            ldsm_x4(bh0, bFH + k*32);
            ldsm_x4(bh1, bFH + 16*144 + k*32);
            ldsm_x4(bl0, bFL + k*32);
            ldsm_x4(bl1, bFL + 16*144 + k*32);
            mma16816(acc2[0], ah, bh0[0], bh0[1]);
            mma16816(acc2[1], ah, bh0[2], bh0[3]);
            mma16816(acc2[2], ah, bh1[0], bh1[1]);
            mma16816(acc2[3], ah, bh1[2], bh1[3]);
            mma16816(acc2[0], al, bh0[0], bh0[1]);
            mma16816(acc2[1], al, bh0[2], bh0[3]);
            mma16816(acc2[2], al, bh1[0], bh1[1]);
            mma16816(acc2[3], al, bh1[2], bh1[3]);
            mma16816(acc2[0], ah, bl0[0], bl0[1]);
            mma16816(acc2[1], ah, bl0[2], bl0[3]);
            mma16816(acc2[2], ah, bl1[0], bl1[1]);
            mma16816(acc2[3], ah, bl1[2], bl1[3]);
        }
    }

    // epilogue: RMW onto BN residual
    #pragma unroll
    for (int mc=0;mc<4;mc++){
        int cg = wn + g;
        int mg = mbase + wm + mc*8 + 2*t;
        float* d0 = out + (((size_t)(b<<6)+cg)<<12) + mg;
        float2 o0 = *(const float2*)d0;
        o0.x += acc2[mc][0]; o0.y += acc2[mc][1];
        *(float2*)d0 = o0;
        float* d1 = out + (((size_t)(b<<6)+cg+8)<<12) + mg;
        float2 o1 = *(const float2*)d1;
        o1.x += acc2[mc][2]; o1.y += acc2[mc][3];
        *(float2*)d1 = o1;
    }
}

// ---------------- host launcher -------------------------------------------------
extern "C" void kernel_launch(void* const* d_in, const int* in_sizes, int n_in,
                              void* d_out, int out_size)
{
    const float* x    = (const float*)d_in[0];
    const float* qw   = (const float*)d_in[1];
    const float* qb   = (const float*)d_in[2];
    const float* kw   = (const float*)d_in[3];
    const float* kb   = (const float*)d_in[4];
    const float* mw   = (const float*)d_in[5];
    const float* mb   = (const float*)d_in[6];
    const float* vw   = (const float*)d_in[7];
    const float* vb   = (const float*)d_in[8];
    const float* ww   = (const float*)d_in[9];
    const float* wb   = (const float*)d_in[10];
    const float* bng  = (const float*)d_in[11];
    const float* bnb  = (const float*)d_in[12];
    const float* bnrm = (const float*)d_in[13];
    const float* bnrv = (const float*)d_in[14];
    float* out = (float*)d_out;

    const int SM1 = 24960*4;
    const int SM3 = 55296;
    const int SM4 = 101120;
    cudaFuncSetAttribute(DNL_k1,  cudaFuncAttributeMaxDynamicSharedMemorySize, SM1);
    cudaFuncSetAttribute(DNL_k3r, cudaFuncAttributeMaxDynamicSharedMemorySize, SM3);
    cudaFuncSetAttribute(DNL_k4r, cudaFuncAttributeMaxDynamicSharedMemorySize, SM4);

    DNL_k0_zero<<<64, 256>>>();
    DNL_k1<<<dim3(32,4), 256, SM1>>>(x, qw,qb, kw,kb, mw,mb, vw,vb, ww,wb,
                                     bng,bnb,bnrm,bnrv, out);
    DNL_k2b<<<dim3(64,4), 256>>>();
    DNL_k2v<<<2048, 256>>>();
    DNL_k3r<<<dim3(4,32,4), 256, SM3>>>();
    DNL_k3b<<<64, 256>>>();
    DNL_k3c<<<65536, 256>>>();
    DNL_k4r<<<dim3(4,64), 256, SM4>>>(out);
}

// round 10
// speedup vs baseline: 3.9952x; 1.1808x over previous
#include <cuda_runtime.h>
#include <cuda_bf16.h>
#include <cuda_fp16.h>
#include <stdint.h>

#define BB 4
#define NNq 4096

// ---------------- device scratch ----------------
__device__ float g_q[BB*64*NNq];
__device__ float g_k[BB*64*NNq];
__device__ float g_v[BB*64*NNq];
__device__ float g_m[BB*NNq];
__device__ __align__(16) __nv_bfloat16 g_qTb[(size_t)BB*NNq*64];  // [b][n][c] whitened
__device__ __align__(16) __nv_bfloat16 g_kTb[(size_t)BB*NNq*64];  // [b][n][c] whitened
__device__ __align__(16) __half g_vF16[(size_t)BB*64*NNq];        // [b][c][n]
__device__ __align__(16) __half g_P16[(size_t)BB*NNq*NNq];        // 128 MiB, symmetric per b
__device__ float g_rowsum[BB*NNq];
__device__ float g_invrs[BB*NNq];
__device__ float g_qsum[BB*64];
__device__ float g_ksum[BB*64];

// ---------------- helpers ----------------
__device__ __forceinline__ float fexp(float v){
    float y = v * 1.44269504088896341f;
    float t = y + 12582912.0f;
    int   e = __float_as_int(t) - 0x4B400000;
    float f = y - (t - 12582912.0f);
    float p = 0.00961804886f;
    p = p*f + 0.05550410866f;
    p = p*f + 0.24022650696f;
    p = p*f + 0.69314718056f;
    p = p*f + 1.0f;
    return __int_as_float(__float_as_int(p) + (e << 23));
}

__device__ __forceinline__ void mma16816(float c[4], const uint32_t a[4],
                                         uint32_t b0, uint32_t b1){
    asm volatile(
        "mma.sync.aligned.m16n8k16.row.col.f32.bf16.bf16.f32 "
        "{%0,%1,%2,%3}, {%4,%5,%6,%7}, {%8,%9}, {%0,%1,%2,%3};"
        : "+f"(c[0]), "+f"(c[1]), "+f"(c[2]), "+f"(c[3])
        : "r"(a[0]), "r"(a[1]), "r"(a[2]), "r"(a[3]), "r"(b0), "r"(b1));
}
__device__ __forceinline__ void mma16816h(float c[4], const uint32_t a[4],
                                          uint32_t b0, uint32_t b1){
    asm volatile(
        "mma.sync.aligned.m16n8k16.row.col.f32.f16.f16.f32 "
        "{%0,%1,%2,%3}, {%4,%5,%6,%7}, {%8,%9}, {%0,%1,%2,%3};"
        : "+f"(c[0]), "+f"(c[1]), "+f"(c[2]), "+f"(c[3])
        : "r"(a[0]), "r"(a[1]), "r"(a[2]), "r"(a[3]), "r"(b0), "r"(b1));
}

__device__ __forceinline__ void ldsm_x4(uint32_t r[4], uint32_t addr){
    asm volatile("ldmatrix.sync.aligned.m8n8.x4.shared.b16 {%0,%1,%2,%3}, [%4];"
        : "=r"(r[0]), "=r"(r[1]), "=r"(r[2]), "=r"(r[3]) : "r"(addr));
}

#define CPA16(d, s) asm volatile("cp.async.cg.shared.global [%0], [%1], 16;" \
        :: "r"((uint32_t)(d)), "l"(s) : "memory")
#define CPCOMMIT()  asm volatile("cp.async.commit_group;" ::: "memory")
#define CPWAIT0()   asm volatile("cp.async.wait_group 0;" ::: "memory")

// ---------------- K0: zero accumulators ----------------
__global__ void DNL_k0_zero(){
    int i = blockIdx.x*blockDim.x + threadIdx.x;
    if (i < BB*NNq) g_rowsum[i] = 0.0f;
    if (i < BB*64){ g_qsum[i] = 0.0f; g_ksum[i] = 0.0f; }
}

// ---------------- K1: q,k,v,m and BN(wx) -> out; mean partial sums -------------
__device__ __forceinline__ void conv_acc(const float* __restrict__ wsm,
                                         const float* __restrict__ xs,
                                         const float* __restrict__ bias,
                                         int o0, int n0, float acc[4][8]){
    #pragma unroll
    for (int i=0;i<4;i++){
        float bv = bias[o0+i];
        #pragma unroll
        for (int j=0;j<8;j++) acc[i][j] = bv;
    }
    #pragma unroll 8
    for (int c=0;c<64;c++){
        float4 x0 = *(const float4*)(xs + (c<<7) + n0);
        float4 x1 = *(const float4*)(xs + (c<<7) + n0 + 4);
        #pragma unroll
        for (int i=0;i<4;i++){
            float w = wsm[(o0+i)*65 + c];
            acc[i][0] += w*x0.x; acc[i][1] += w*x0.y;
            acc[i][2] += w*x0.z; acc[i][3] += w*x0.w;
            acc[i][4] += w*x1.x; acc[i][5] += w*x1.y;
            acc[i][6] += w*x1.z; acc[i][7] += w*x1.w;
        }
    }
}

__global__ __launch_bounds__(256) void DNL_k1(
    const float* __restrict__ x,
    const float* __restrict__ qw, const float* __restrict__ qb,
    const float* __restrict__ kw, const float* __restrict__ kb,
    const float* __restrict__ mw, const float* __restrict__ mb,
    const float* __restrict__ vw, const float* __restrict__ vb,
    const float* __restrict__ ww, const float* __restrict__ wb,
    const float* __restrict__ bng, const float* __restrict__ bnb,
    const float* __restrict__ bnrm, const float* __restrict__ bnrv,
    float* __restrict__ out)
{
    extern __shared__ float sm[];
    float* xs  = sm;
    float* wq  = xs  + 64*128;
    float* wk  = wq  + 64*65;
    float* wv  = wk  + 64*65;
    float* wwt = wv  + 64*65;
    float* qs  = wwt + 64*65;
    float* ks  = qs  + 64;

    int b = blockIdx.y, nt = blockIdx.x;
    int nb = nt << 7;
    int tid = threadIdx.x;

    if (tid < 64){ qs[tid] = 0.0f; ks[tid] = 0.0f; }
    for (int idx = tid; idx < 64*128; idx += 256){
        int c = idx >> 7, pos = idx & 127;
        xs[idx] = x[(((b<<6)+c)<<12) + nb + pos];
    }
    for (int idx = tid; idx < 64*64; idx += 256){
        int o = idx >> 6, c = idx & 63;
        int so = o*65 + c;
        wq[so] = qw[idx]; wk[so] = kw[idx]; wv[so] = vw[idx]; wwt[so] = ww[idx];
    }
    __syncthreads();

    if (tid < 128){
        float a = mb[0];
        #pragma unroll 8
        for (int c=0;c<64;c++) a += mw[c]*xs[(c<<7) + tid];
        g_m[(b<<12) + nb + tid] = a;
    }

    int tx = tid & 15, ty = tid >> 4;
    int n0 = tx << 3, o0 = ty << 2;
    float acc[4][8];

    conv_acc(wq, xs, qb, o0, n0, acc);
    #pragma unroll
    for (int i=0;i<4;i++){
        float* dst = g_q + ((((size_t)(b<<6)+o0+i)<<12) + nb + n0);
        *(float4*)dst     = make_float4(acc[i][0],acc[i][1],acc[i][2],acc[i][3]);
        *(float4*)(dst+4) = make_float4(acc[i][4],acc[i][5],acc[i][6],acc[i][7]);
        float s = acc[i][0]+acc[i][1]+acc[i][2]+acc[i][3]
                 +acc[i][4]+acc[i][5]+acc[i][6]+acc[i][7];
        atomicAdd(&qs[o0+i], s);
    }
    conv_acc(wk, xs, kb, o0, n0, acc);
    #pragma unroll
    for (int i=0;i<4;i++){
        float* dst = g_k + ((((size_t)(b<<6)+o0+i)<<12) + nb + n0);
        *(float4*)dst     = make_float4(acc[i][0],acc[i][1],acc[i][2],acc[i][3]);
        *(float4*)(dst+4) = make_float4(acc[i][4],acc[i][5],acc[i][6],acc[i][7]);
        float s = acc[i][0]+acc[i][1]+acc[i][2]+acc[i][3]
                 +acc[i][4]+acc[i][5]+acc[i][6]+acc[i][7];
        atomicAdd(&ks[o0+i], s);
    }
    conv_acc(wv, xs, vb, o0, n0, acc);
    #pragma unroll
    for (int i=0;i<4;i++){
        float* dst = g_v + ((((size_t)(b<<6)+o0+i)<<12) + nb + n0);
        *(float4*)dst     = make_float4(acc[i][0],acc[i][1],acc[i][2],acc[i][3]);
        *(float4*)(dst+4) = make_float4(acc[i][4],acc[i][5],acc[i][6],acc[i][7]);
    }
    conv_acc(wwt, xs, wb, o0, n0, acc);
    #pragma unroll
    for (int i=0;i<4;i++){
        int o = o0 + i;
        float sc = bng[o] * rsqrtf(bnrv[o] + 1e-5f);
        float sh = bnb[o] - bnrm[o]*sc;
        float* dst = out + (((size_t)(b<<6)+o)<<12) + nb + n0;
        *(float4*)dst     = make_float4(acc[i][0]*sc+sh, acc[i][1]*sc+sh,
                                        acc[i][2]*sc+sh, acc[i][3]*sc+sh);
        *(float4*)(dst+4) = make_float4(acc[i][4]*sc+sh, acc[i][5]*sc+sh,
                                        acc[i][6]*sc+sh, acc[i][7]*sc+sh);
    }
    __syncthreads();
    if (tid < 64){
        atomicAdd(&g_qsum[(b<<6)+tid], qs[tid]);
        atomicAdd(&g_ksum[(b<<6)+tid], ks[tid]);
    }
}

// ---------------- K2b: whiten + transpose + bf16 -------------------------------
__global__ __launch_bounds__(256) void DNL_k2b(){
    __shared__ float sq[64*65], sk[64*65], mq[64], mk[64];
    int b = blockIdx.y, nt = blockIdx.x, tid = threadIdx.x;
    if (tid<64){ mq[tid]=g_qsum[(b<<6)+tid]*(1.f/NNq); mk[tid]=g_ksum[(b<<6)+tid]*(1.f/NNq); }
    for (int i=tid;i<4096;i+=256){
        int c=i>>6, n=i&63;
        sq[c*65+n]=g_q[(((size_t)(b<<6)+c)<<12)+(nt<<6)+n];
        sk[c*65+n]=g_k[(((size_t)(b<<6)+c)<<12)+(nt<<6)+n];
    }
    __syncthreads();
    for (int i=tid;i<2048;i+=256){
        int n=i>>5, c=(i&31)<<1;
        size_t row = (size_t)(b<<12)+(nt<<6)+n;
        __nv_bfloat162 hq = __floats2bfloat162_rn(sq[c*65+n]-mq[c], sq[(c+1)*65+n]-mq[c+1]);
        __nv_bfloat162 hk = __floats2bfloat162_rn(sk[c*65+n]-mk[c], sk[(c+1)*65+n]-mk[c+1]);
        *(__nv_bfloat162*)(g_qTb + row*64 + c) = hq;
        *(__nv_bfloat162*)(g_kTb + row*64 + c) = hk;
    }
}

// ---------------- K2v: V -> fp16 -------------------------------------------------
__global__ __launch_bounds__(256) void DNL_k2v(){
    size_t i = (((size_t)blockIdx.x<<8) + threadIdx.x) << 1;
    float2 v = *(const float2*)(g_v + i);
    *(__half2*)(g_vF16 + i) = __floats2half2_rn(v.x, v.y);
}

// ---------------- K3r: rowsums only, cp.async double-buffered Q -----------------
// grid (jh=4, it=32, b=4) = 512 blocks, 256 threads, dyn smem 55296 B
__global__ __launch_bounds__(256) void DNL_k3r(){
    extern __shared__ char s3[];
    uint32_t sA = (uint32_t)__cvta_generic_to_shared(s3);
    int jh=blockIdx.x, it=blockIdx.y, b=blockIdx.z;
    int tid=threadIdx.x;
    int w = tid>>5, lane = tid&31, g = lane>>2, t = lane&3;
    int wn = w<<4;

    uint32_t aAddr = sA + (uint32_t)((wn + (lane&7) + ((lane>>3)&1)*8)*144
                                     + ((lane>>4)&1)*16);
    uint32_t bRel  = (uint32_t)(((lane&7) + (lane>>4)*8)*144 + ((lane>>3)&1)*16);

    for (int i=tid;i<1024;i+=256){
        int r=i>>3, u=i&7;
        CPA16(sA + r*144 + u*16,
              g_kTb + ((size_t)(b<<12)+(it<<7)+r)*64 + u*8);
    }
    for (int i=tid;i<1024;i+=256){
        int r=i>>3, u=i&7;
        CPA16(sA + 18432 + r*144 + u*16,
              g_qTb + ((size_t)(b<<12)+(jh<<10)+r)*64 + u*8);
    }
    CPCOMMIT();

    float rs0=0.f, rs1=0.f;
    for (int mc2=0; mc2<8; mc2++){
        CPWAIT0();
        __syncthreads();
        if (mc2 < 7){
            uint32_t dst = sA + 18432 + (((mc2+1)&1) ? 18432u : 0u);
            for (int i=tid;i<1024;i+=256){
                int r=i>>3, u=i&7;
                CPA16(dst + r*144 + u*16,
                      g_qTb + ((size_t)(b<<12)+(jh<<10)+((mc2+1)<<7)+r)*64 + u*8);
            }
            CPCOMMIT();
        }
        uint32_t bAddr = sA + 18432 + ((mc2&1) ? 18432u : 0u) + bRel;

        float a[16][4];
        #pragma unroll
        for (int cs=0;cs<16;cs++){ a[cs][0]=0.f; a[cs][1]=0.f; a[cs][2]=0.f; a[cs][3]=0.f; }
        #pragma unroll
        for (int k=0;k<4;k++){
            uint32_t af[4];
            ldsm_x4(af, aAddr + k*32);
            #pragma unroll
            for (int u=0;u<8;u++){
                uint32_t bf[4];
                ldsm_x4(bf, bAddr + u*(16*144) + k*32);
                mma16816(a[2*u],   af, bf[0], bf[1]);
                mma16816(a[2*u+1], af, bf[2], bf[3]);
            }
        }
        #pragma unroll
        for (int cs=0;cs<16;cs++){
            rs0 += fexp(a[cs][0]) + fexp(a[cs][1]);
            rs1 += fexp(a[cs][2]) + fexp(a[cs][3]);
        }
    }
    rs0 += __shfl_xor_sync(0xffffffffu, rs0, 1);
    rs0 += __shfl_xor_sync(0xffffffffu, rs0, 2);
    rs1 += __shfl_xor_sync(0xffffffffu, rs1, 1);
    rs1 += __shfl_xor_sync(0xffffffffu, rs1, 2);
    if (t == 0){
        atomicAdd(&g_rowsum[(b<<12)+(it<<7)+wn+g],   rs0);
        atomicAdd(&g_rowsum[(b<<12)+(it<<7)+wn+g+8], rs1);
    }
}

// ---------------- K3b: reciprocal row sums --------------------------------------
__global__ void DNL_k3b(){
    int i = blockIdx.x*blockDim.x + threadIdx.x;
    if (i < BB*NNq) g_invrs[i] = 1.0f / g_rowsum[i];
}

// ---------------- K3c: P16[b][n][m] = exp(m_b[n]m_b[m]) / sum_b' ----------------
// grid 32768 x 256; 2 m per thread
__global__ __launch_bounds__(256) void DNL_k3c(){
    size_t tt = ((size_t)blockIdx.x << 8) + threadIdx.x;   // 8.4M
    int n  = (int)(tt >> 11);
    int m0 = (int)((tt & 2047) << 1);
    float a0=g_m[n], a1=g_m[4096+n], a2=g_m[8192+n], a3=g_m[12288+n];
    float p0=g_m[m0],       q0=g_m[m0+1];
    float p1=g_m[4096+m0],  q1=g_m[4097+m0];
    float p2=g_m[8192+m0],  q2=g_m[8193+m0];
    float p3=g_m[12288+m0], q3=g_m[12289+m0];
    float e00=fexp(a0*p0), e01=fexp(a0*q0);
    float e10=fexp(a1*p1), e11=fexp(a1*q1);
    float e20=fexp(a2*p2), e21=fexp(a2*q2);
    float e30=fexp(a3*p3), e31=fexp(a3*q3);
    float s0=e00+e10+e20+e30, s1=e01+e11+e21+e31;
    float r0 = __int_as_float(0x7EF311C3 - __float_as_int(s0));
    r0 = r0*(2.0f-s0*r0); r0 = r0*(2.0f-s0*r0); r0 = r0*(2.0f-s0*r0);
    float r1 = __int_as_float(0x7EF311C3 - __float_as_int(s1));
    r1 = r1*(2.0f-s1*r1); r1 = r1*(2.0f-s1*r1); r1 = r1*(2.0f-s1*r1);
    size_t base = ((size_t)n<<12) + m0;
    *(__half2*)(g_P16 + base)               = __floats2half2_rn(e00*r0, e01*r1);
    *(__half2*)(g_P16 + (1ULL<<24) + base)  = __floats2half2_rn(e10*r0, e11*r1);
    *(__half2*)(g_P16 + (2ULL<<24) + base)  = __floats2half2_rn(e20*r0, e21*r1);
    *(__half2*)(g_P16 + (3ULL<<24) + base)  = __floats2half2_rn(e30*r0, e31*r1);
}

// ---------------- K4r: pipelined fused S -> F(+P16) -> out += V*F ---------------
// grid (b=4 fastest, mt=64), 256 threads, dyn smem 83456 B
#define K4_SQ    0
#define K4_SFH   9216
#define K4_SFL   18432
#define K4_ST0   27648
#define K4_ST1   55552
#define K4_STK   0
#define K4_STV   9216
#define K4_STP   18432
#define K4_SIR   27648

__device__ __forceinline__ void k4_issue_stage(uint32_t dstBase, int b, int nbase,
                                               int mbase, int tid){
    for (int i=tid;i<512;i+=256){
        int r=i>>3, u=i&7;
        CPA16(dstBase + K4_STK + r*144 + u*16,
              g_kTb + ((size_t)(b<<12)+nbase+r)*64 + u*8);
    }
    for (int i=tid;i<512;i+=256){
        int c=i>>3, u=i&7;
        CPA16(dstBase + K4_STV + c*144 + u*16,
              g_vF16 + (((size_t)(b<<6)+c)<<12) + nbase + u*8);
    }
    for (int i=tid;i<512;i+=256){
        int r=i>>3, u=i&7;     // row r = local m; symmetric P -> n contiguous
        CPA16(dstBase + K4_STP + r*144 + u*16,
              g_P16 + ((size_t)b<<24) + ((size_t)(mbase+r)<<12) + nbase + u*8);
    }
    if (tid < 16)
        CPA16(dstBase + K4_SIR + tid*16, g_invrs + (b<<12) + nbase + tid*4);
}

__global__ __launch_bounds__(256,2) void DNL_k4r(float* __restrict__ out){
    extern __shared__ char s4[];
    uint32_t sA = (uint32_t)__cvta_generic_to_shared(s4);
    int b = blockIdx.x, mt = blockIdx.y;
    int mbase = mt<<6;
    int tid = threadIdx.x;
    int w = tid>>5, lane = tid&31, g = lane>>2, t = lane&3;
    int wn = (w&3)<<4;
    int wm = (w>>2)<<5;

    uint32_t aRow = (uint32_t)((wn + (lane&7) + ((lane>>3)&1)*8)*144
                               + ((lane>>4)&1)*16);
    uint32_t bRow = (uint32_t)((wm + (lane&7) + (lane>>4)*8)*144
                               + ((lane>>3)&1)*16);
    uint32_t bQ  = sA + K4_SQ  + bRow;
    uint32_t bFH = sA + K4_SFH + bRow;
    uint32_t bFL = sA + K4_SFL + bRow;

    // prologue
    for (int i=tid;i<512;i+=256){
        int r=i>>3, u=i&7;
        CPA16(sA + K4_SQ + r*144 + u*16,
              g_qTb + ((size_t)(b<<12)+mbase+r)*64 + u*8);
    }
    k4_issue_stage(sA + K4_ST0, b, 0, mbase, tid);
    CPCOMMIT();

    float acc2[4][4];
    #pragma unroll
    for (int mc=0;mc<4;mc++){ acc2[mc][0]=0.f; acc2[mc][1]=0.f; acc2[mc][2]=0.f; acc2[mc][3]=0.f; }

    for (int ch=0; ch<64; ch++){
        CPWAIT0();
        __syncthreads();   // data landed; all warps past mma2(ch-1)

        int stgOff = (ch&1) ? K4_ST1 : K4_ST0;
        uint32_t stgA = sA + stgOff;
        if (ch < 63){
            k4_issue_stage(sA + (((ch+1)&1) ? K4_ST1 : K4_ST0), b, (ch+1)<<6, mbase, tid);
            CPCOMMIT();
        }

        // ---- mma1: S = K x Q^T (bf16) ----
        float a1[4][4];
        #pragma unroll
        for (int mc=0;mc<4;mc++){ a1[mc][0]=0.f; a1[mc][1]=0.f; a1[mc][2]=0.f; a1[mc][3]=0.f; }
        uint32_t aK = stgA + K4_STK + aRow;
        #pragma unroll
        for (int k=0;k<4;k++){
            uint32_t af[4], bf0[4], bf1[4];
            ldsm_x4(af,  aK + k*32);
            ldsm_x4(bf0, bQ + k*32);
            ldsm_x4(bf1, bQ + 16*144 + k*32);
            mma16816(a1[0], af, bf0[0], bf0[1]);
            mma16816(a1[1], af, bf0[2], bf0[3]);
            mma16816(a1[2], af, bf1[0], bf1[1]);
            mma16816(a1[3], af, bf1[2], bf1[3]);
        }
        // ---- construct F = fexp(S)*irs + P16 -> FH/FL fp16 [m][n] ----
        const __half* Ps   = (const __half*)(s4 + stgOff + K4_STP);
        const float*  irsS = (const float*)(s4 + stgOff + K4_SIR);
        int nl0 = wn+g, nl1 = nl0+8;
        float ir0 = irsS[nl0], ir1 = irsS[nl1];
        __half* FH = (__half*)(s4+K4_SFH);
        __half* FL = (__half*)(s4+K4_SFL);
        #pragma unroll
        for (int mc=0;mc<4;mc++){
            int ml = wm + mc*8 + 2*t;
            float f0 = fexp(a1[mc][0])*ir0 + __half2float(Ps[ml*72     + nl0]);
            float f1 = fexp(a1[mc][1])*ir0 + __half2float(Ps[(ml+1)*72 + nl0]);
            float f2 = fexp(a1[mc][2])*ir1 + __half2float(Ps[ml*72     + nl1]);
            float f3 = fexp(a1[mc][3])*ir1 + __half2float(Ps[(ml+1)*72 + nl1]);
            __half h0=__float2half_rn(f0), h1=__float2half_rn(f1),
                   h2=__float2half_rn(f2), h3=__float2half_rn(f3);
            FH[ml*72     + nl0] = h0;
            FH[(ml+1)*72 + nl0] = h1;
            FH[ml*72     + nl1] = h2;
            FH[(ml+1)*72 + nl1] = h3;
            FL[ml*72     + nl0] = __float2half_rn(f0-__half2float(h0));
            FL[(ml+1)*72 + nl0] = __float2half_rn(f1-__half2float(h1));
            FL[ml*72     + nl1] = __float2half_rn(f2-__half2float(h2));
            FL[(ml+1)*72 + nl1] = __float2half_rn(f3-__half2float(h3));
        }
        __syncthreads();   // F visible

        // ---- mma2: acc2 += V16 * (FH + FL)  (fp16, 2 passes) ----
        uint32_t aV = stgA + K4_STV + aRow;
        #pragma unroll
        for (int k=0;k<4;k++){
            uint32_t ah[4], bh0[4], bh1[4], bl0[4], bl1[4];
            ldsm_x4(ah,  aV + k*32);
            ldsm_x4(bh0, bFH + k*32);
            ldsm_x4(bh1, bFH + 16*144 + k*32);
            ldsm_x4(bl0, bFL + k*32);
            ldsm_x4(bl1, bFL + 16*144 + k*32);
            mma16816h(acc2[0], ah, bh0[0], bh0[1]);
            mma16816h(acc2[1], ah, bh0[2], bh0[3]);
            mma16816h(acc2[2], ah, bh1[0], bh1[1]);
            mma16816h(acc2[3], ah, bh1[2], bh1[3]);
            mma16816h(acc2[0], ah, bl0[0], bl0[1]);
            mma16816h(acc2[1], ah, bl0[2], bl0[3]);
            mma16816h(acc2[2], ah, bl1[0], bl1[1]);
            mma16816h(acc2[3], ah, bl1[2], bl1[3]);
        }
    }

    // epilogue: RMW onto BN residual
    #pragma unroll
    for (int mc=0;mc<4;mc++){
        int cg = wn + g;
        int mg = mbase + wm + mc*8 + 2*t;
        float* d0 = out + (((size_t)(b<<6)+cg)<<12) + mg;
        float2 o0 = *(const float2*)d0;
        o0.x += acc2[mc][0]; o0.y += acc2[mc][1];
        *(float2*)d0 = o0;
        float* d1 = out + (((size_t)(b<<6)+cg+8)<<12) + mg;
        float2 o1 = *(const float2*)d1;
        o1.x += acc2[mc][2]; o1.y += acc2[mc][3];
        *(float2*)d1 = o1;
    }
}

// ---------------- host launcher -------------------------------------------------
extern "C" void kernel_launch(void* const* d_in, const int* in_sizes, int n_in,
                              void* d_out, int out_size)
{
    const float* x    = (const float*)d_in[0];
    const float* qw   = (const float*)d_in[1];
    const float* qb   = (const float*)d_in[2];
    const float* kw   = (const float*)d_in[3];
    const float* kb   = (const float*)d_in[4];
    const float* mw   = (const float*)d_in[5];
    const float* mb   = (const float*)d_in[6];
    const float* vw   = (const float*)d_in[7];
    const float* vb   = (const float*)d_in[8];
    const float* ww   = (const float*)d_in[9];
    const float* wb   = (const float*)d_in[10];
    const float* bng  = (const float*)d_in[11];
    const float* bnb  = (const float*)d_in[12];
    const float* bnrm = (const float*)d_in[13];
    const float* bnrv = (const float*)d_in[14];
    float* out = (float*)d_out;

    const int SM1 = 24960*4;
    const int SM3 = 55296;
    const int SM4 = 83456;
    cudaFuncSetAttribute(DNL_k1,  cudaFuncAttributeMaxDynamicSharedMemorySize, SM1);
    cudaFuncSetAttribute(DNL_k3r, cudaFuncAttributeMaxDynamicSharedMemorySize, SM3);
    cudaFuncSetAttribute(DNL_k4r, cudaFuncAttributeMaxDynamicSharedMemorySize, SM4);

    DNL_k0_zero<<<64, 256>>>();
    DNL_k1<<<dim3(32,4), 256, SM1>>>(x, qw,qb, kw,kb, mw,mb, vw,vb, ww,wb,
                                     bng,bnb,bnrm,bnrv, out);
    DNL_k2b<<<dim3(64,4), 256>>>();
    DNL_k2v<<<2048, 256>>>();
    DNL_k3r<<<dim3(4,32,4), 256, SM3>>>();
    DNL_k3b<<<64, 256>>>();
    DNL_k3c<<<32768, 256>>>();
    DNL_k4r<<<dim3(4,64), 256, SM4>>>(out);
}

// round 11
// speedup vs baseline: 4.4293x; 1.1087x over previous
#include <cuda_runtime.h>
#include <cuda_bf16.h>
#include <cuda_fp16.h>
#include <stdint.h>

#define BB 4
#define NNq 4096

// ---------------- device scratch ----------------
__device__ float g_q[BB*64*NNq];
__device__ float g_k[BB*64*NNq];
__device__ float g_m[BB*NNq];
__device__ __align__(16) __nv_bfloat16 g_qTb[(size_t)BB*NNq*64];  // [b][n][c] whitened
__device__ __align__(16) __nv_bfloat16 g_kTb[(size_t)BB*NNq*64];  // [b][n][c] whitened
__device__ __align__(16) __half g_vF16[(size_t)BB*64*NNq];        // [b][c][n]
__device__ __align__(16) __half g_P16[(size_t)BB*NNq*NNq];        // 128 MiB, symmetric per b
__device__ float g_rowsum[BB*NNq];
__device__ float g_invrs[BB*NNq];
__device__ float g_qsum[BB*64];
__device__ float g_ksum[BB*64];

// ---------------- helpers ----------------
__device__ __forceinline__ float fexp(float v){
    float y = v * 1.44269504088896341f;
    float t = y + 12582912.0f;
    int   e = __float_as_int(t) - 0x4B400000;
    float f = y - (t - 12582912.0f);
    float p = 0.00961804886f;
    p = p*f + 0.05550410866f;
    p = p*f + 0.24022650696f;
    p = p*f + 0.69314718056f;
    p = p*f + 1.0f;
    return __int_as_float(__float_as_int(p) + (e << 23));
}

__device__ __forceinline__ void mma16816(float c[4], const uint32_t a[4],
                                         uint32_t b0, uint32_t b1){
    asm volatile(
        "mma.sync.aligned.m16n8k16.row.col.f32.bf16.bf16.f32 "
        "{%0,%1,%2,%3}, {%4,%5,%6,%7}, {%8,%9}, {%0,%1,%2,%3};"
        : "+f"(c[0]), "+f"(c[1]), "+f"(c[2]), "+f"(c[3])
        : "r"(a[0]), "r"(a[1]), "r"(a[2]), "r"(a[3]), "r"(b0), "r"(b1));
}
__device__ __forceinline__ void mma16816h(float c[4], const uint32_t a[4],
                                          uint32_t b0, uint32_t b1){
    asm volatile(
        "mma.sync.aligned.m16n8k16.row.col.f32.f16.f16.f32 "
        "{%0,%1,%2,%3}, {%4,%5,%6,%7}, {%8,%9}, {%0,%1,%2,%3};"
        : "+f"(c[0]), "+f"(c[1]), "+f"(c[2]), "+f"(c[3])
        : "r"(a[0]), "r"(a[1]), "r"(a[2]), "r"(a[3]), "r"(b0), "r"(b1));
}

__device__ __forceinline__ void ldsm_x4(uint32_t r[4], uint32_t addr){
    asm volatile("ldmatrix.sync.aligned.m8n8.x4.shared.b16 {%0,%1,%2,%3}, [%4];"
        : "=r"(r[0]), "=r"(r[1]), "=r"(r[2]), "=r"(r[3]) : "r"(addr));
}

#define CPA16(d, s) asm volatile("cp.async.cg.shared.global [%0], [%1], 16;" \
        :: "r"((uint32_t)(d)), "l"(s) : "memory")
#define CPCOMMIT()  asm volatile("cp.async.commit_group;" ::: "memory")
#define CPWAIT0()   asm volatile("cp.async.wait_group 0;" ::: "memory")

// ---------------- K0: zero accumulators ----------------
__global__ void DNL_k0_zero(){
    int i = blockIdx.x*blockDim.x + threadIdx.x;
    if (i < BB*NNq) g_rowsum[i] = 0.0f;
    if (i < BB*64){ g_qsum[i] = 0.0f; g_ksum[i] = 0.0f; }
}

// ---------------- K1: q,k,v(fp16),m and BN(wx) -> out; mean partial sums -------
__device__ __forceinline__ void conv_acc(const float* __restrict__ wsm,
                                         const float* __restrict__ xs,
                                         const float* __restrict__ bias,
                                         int o0, int n0, float acc[4][8]){
    #pragma unroll
    for (int i=0;i<4;i++){
        float bv = bias[o0+i];
        #pragma unroll
        for (int j=0;j<8;j++) acc[i][j] = bv;
    }
    #pragma unroll 8
    for (int c=0;c<64;c++){
        float4 x0 = *(const float4*)(xs + (c<<7) + n0);
        float4 x1 = *(const float4*)(xs + (c<<7) + n0 + 4);
        #pragma unroll
        for (int i=0;i<4;i++){
            float w = wsm[(o0+i)*65 + c];
            acc[i][0] += w*x0.x; acc[i][1] += w*x0.y;
            acc[i][2] += w*x0.z; acc[i][3] += w*x0.w;
            acc[i][4] += w*x1.x; acc[i][5] += w*x1.y;
            acc[i][6] += w*x1.z; acc[i][7] += w*x1.w;
        }
    }
}

__global__ __launch_bounds__(256) void DNL_k1(
    const float* __restrict__ x,
    const float* __restrict__ qw, const float* __restrict__ qb,
    const float* __restrict__ kw, const float* __restrict__ kb,
    const float* __restrict__ mw, const float* __restrict__ mb,
    const float* __restrict__ vw, const float* __restrict__ vb,
    const float* __restrict__ ww, const float* __restrict__ wb,
    const float* __restrict__ bng, const float* __restrict__ bnb,
    const float* __restrict__ bnrm, const float* __restrict__ bnrv,
    float* __restrict__ out)
{
    extern __shared__ float sm[];
    float* xs  = sm;
    float* wq  = xs  + 64*128;
    float* wk  = wq  + 64*65;
    float* wv  = wk  + 64*65;
    float* wwt = wv  + 64*65;
    float* qs  = wwt + 64*65;
    float* ks  = qs  + 64;

    int b = blockIdx.y, nt = blockIdx.x;
    int nb = nt << 7;
    int tid = threadIdx.x;

    if (tid < 64){ qs[tid] = 0.0f; ks[tid] = 0.0f; }
    for (int idx = tid; idx < 64*128; idx += 256){
        int c = idx >> 7, pos = idx & 127;
        xs[idx] = x[(((b<<6)+c)<<12) + nb + pos];
    }
    for (int idx = tid; idx < 64*64; idx += 256){
        int o = idx >> 6, c = idx & 63;
        int so = o*65 + c;
        wq[so] = qw[idx]; wk[so] = kw[idx]; wv[so] = vw[idx]; wwt[so] = ww[idx];
    }
    __syncthreads();

    if (tid < 128){
        float a = mb[0];
        #pragma unroll 8
        for (int c=0;c<64;c++) a += mw[c]*xs[(c<<7) + tid];
        g_m[(b<<12) + nb + tid] = a;
    }

    int tx = tid & 15, ty = tid >> 4;
    int n0 = tx << 3, o0 = ty << 2;
    float acc[4][8];

    conv_acc(wq, xs, qb, o0, n0, acc);
    #pragma unroll
    for (int i=0;i<4;i++){
        float* dst = g_q + ((((size_t)(b<<6)+o0+i)<<12) + nb + n0);
        *(float4*)dst     = make_float4(acc[i][0],acc[i][1],acc[i][2],acc[i][3]);
        *(float4*)(dst+4) = make_float4(acc[i][4],acc[i][5],acc[i][6],acc[i][7]);
        float s = acc[i][0]+acc[i][1]+acc[i][2]+acc[i][3]
                 +acc[i][4]+acc[i][5]+acc[i][6]+acc[i][7];
        atomicAdd(&qs[o0+i], s);
    }
    conv_acc(wk, xs, kb, o0, n0, acc);
    #pragma unroll
    for (int i=0;i<4;i++){
        float* dst = g_k + ((((size_t)(b<<6)+o0+i)<<12) + nb + n0);
        *(float4*)dst     = make_float4(acc[i][0],acc[i][1],acc[i][2],acc[i][3]);
        *(float4*)(dst+4) = make_float4(acc[i][4],acc[i][5],acc[i][6],acc[i][7]);
        float s = acc[i][0]+acc[i][1]+acc[i][2]+acc[i][3]
                 +acc[i][4]+acc[i][5]+acc[i][6]+acc[i][7];
        atomicAdd(&ks[o0+i], s);
    }
    // V -> fp16 directly (no whitening needed)
    conv_acc(wv, xs, vb, o0, n0, acc);
    #pragma unroll
    for (int i=0;i<4;i++){
        __half* dst = g_vF16 + ((((size_t)(b<<6)+o0+i)<<12) + nb + n0);
        __half2 h0 = __floats2half2_rn(acc[i][0], acc[i][1]);
        __half2 h1 = __floats2half2_rn(acc[i][2], acc[i][3]);
        __half2 h2 = __floats2half2_rn(acc[i][4], acc[i][5]);
        __half2 h3 = __floats2half2_rn(acc[i][6], acc[i][7]);
        uint4 pk;
        pk.x = *(uint32_t*)&h0; pk.y = *(uint32_t*)&h1;
        pk.z = *(uint32_t*)&h2; pk.w = *(uint32_t*)&h3;
        *(uint4*)dst = pk;
    }
    conv_acc(wwt, xs, wb, o0, n0, acc);
    #pragma unroll
    for (int i=0;i<4;i++){
        int o = o0 + i;
        float sc = bng[o] * rsqrtf(bnrv[o] + 1e-5f);
        float sh = bnb[o] - bnrm[o]*sc;
        float* dst = out + (((size_t)(b<<6)+o)<<12) + nb + n0;
        *(float4*)dst     = make_float4(acc[i][0]*sc+sh, acc[i][1]*sc+sh,
                                        acc[i][2]*sc+sh, acc[i][3]*sc+sh);
        *(float4*)(dst+4) = make_float4(acc[i][4]*sc+sh, acc[i][5]*sc+sh,
                                        acc[i][6]*sc+sh, acc[i][7]*sc+sh);
    }
    __syncthreads();
    if (tid < 64){
        atomicAdd(&g_qsum[(b<<6)+tid], qs[tid]);
        atomicAdd(&g_ksum[(b<<6)+tid], ks[tid]);
    }
}

// ---------------- K2b: whiten + transpose + bf16 -------------------------------
__global__ __launch_bounds__(256) void DNL_k2b(){
    __shared__ float sq[64*65], sk[64*65], mq[64], mk[64];
    int b = blockIdx.y, nt = blockIdx.x, tid = threadIdx.x;
    if (tid<64){ mq[tid]=g_qsum[(b<<6)+tid]*(1.f/NNq); mk[tid]=g_ksum[(b<<6)+tid]*(1.f/NNq); }
    for (int i=tid;i<4096;i+=256){
        int c=i>>6, n=i&63;
        sq[c*65+n]=g_q[(((size_t)(b<<6)+c)<<12)+(nt<<6)+n];
        sk[c*65+n]=g_k[(((size_t)(b<<6)+c)<<12)+(nt<<6)+n];
    }
    __syncthreads();
    for (int i=tid;i<2048;i+=256){
        int n=i>>5, c=(i&31)<<1;
        size_t row = (size_t)(b<<12)+(nt<<6)+n;
        __nv_bfloat162 hq = __floats2bfloat162_rn(sq[c*65+n]-mq[c], sq[(c+1)*65+n]-mq[c+1]);
        __nv_bfloat162 hk = __floats2bfloat162_rn(sk[c*65+n]-mk[c], sk[(c+1)*65+n]-mk[c+1]);
        *(__nv_bfloat162*)(g_qTb + row*64 + c) = hq;
        *(__nv_bfloat162*)(g_kTb + row*64 + c) = hk;
    }
}

// ---------------- K3r: rowsums only, cp.async double-buffered Q -----------------
// grid (jh=4, it=32, b=4) = 512 blocks, 256 threads, dyn smem 55296 B
__global__ __launch_bounds__(256) void DNL_k3r(){
    extern __shared__ char s3[];
    uint32_t sA = (uint32_t)__cvta_generic_to_shared(s3);
    int jh=blockIdx.x, it=blockIdx.y, b=blockIdx.z;
    int tid=threadIdx.x;
    int w = tid>>5, lane = tid&31, g = lane>>2, t = lane&3;
    int wn = w<<4;

    uint32_t aAddr = sA + (uint32_t)((wn + (lane&7) + ((lane>>3)&1)*8)*144
                                     + ((lane>>4)&1)*16);
    uint32_t bRel  = (uint32_t)(((lane&7) + (lane>>4)*8)*144 + ((lane>>3)&1)*16);

    for (int i=tid;i<1024;i+=256){
        int r=i>>3, u=i&7;
        CPA16(sA + r*144 + u*16,
              g_kTb + ((size_t)(b<<12)+(it<<7)+r)*64 + u*8);
    }
    for (int i=tid;i<1024;i+=256){
        int r=i>>3, u=i&7;
        CPA16(sA + 18432 + r*144 + u*16,
              g_qTb + ((size_t)(b<<12)+(jh<<10)+r)*64 + u*8);
    }
    CPCOMMIT();

    float rs0=0.f, rs1=0.f;
    for (int mc2=0; mc2<8; mc2++){
        CPWAIT0();
        __syncthreads();
        if (mc2 < 7){
            uint32_t dst = sA + 18432 + (((mc2+1)&1) ? 18432u : 0u);
            for (int i=tid;i<1024;i+=256){
                int r=i>>3, u=i&7;
                CPA16(dst + r*144 + u*16,
                      g_qTb + ((size_t)(b<<12)+(jh<<10)+((mc2+1)<<7)+r)*64 + u*8);
            }
            CPCOMMIT();
        }
        uint32_t bAddr = sA + 18432 + ((mc2&1) ? 18432u : 0u) + bRel;

        float a[16][4];
        #pragma unroll
        for (int cs=0;cs<16;cs++){ a[cs][0]=0.f; a[cs][1]=0.f; a[cs][2]=0.f; a[cs][3]=0.f; }
        #pragma unroll
        for (int k=0;k<4;k++){
            uint32_t af[4];
            ldsm_x4(af, aAddr + k*32);
            #pragma unroll
            for (int u=0;u<8;u++){
                uint32_t bf[4];
                ldsm_x4(bf, bAddr + u*(16*144) + k*32);
                mma16816(a[2*u],   af, bf[0], bf[1]);
                mma16816(a[2*u+1], af, bf[2], bf[3]);
            }
        }
        #pragma unroll
        for (int cs=0;cs<16;cs++){
            rs0 += fexp(a[cs][0]) + fexp(a[cs][1]);
            rs1 += fexp(a[cs][2]) + fexp(a[cs][3]);
        }
    }
    rs0 += __shfl_xor_sync(0xffffffffu, rs0, 1);
    rs0 += __shfl_xor_sync(0xffffffffu, rs0, 2);
    rs1 += __shfl_xor_sync(0xffffffffu, rs1, 1);
    rs1 += __shfl_xor_sync(0xffffffffu, rs1, 2);
    if (t == 0){
        atomicAdd(&g_rowsum[(b<<12)+(it<<7)+wn+g],   rs0);
        atomicAdd(&g_rowsum[(b<<12)+(it<<7)+wn+g+8], rs1);
    }
}

// ---------------- K3b: reciprocal row sums --------------------------------------
__global__ void DNL_k3b(){
    int i = blockIdx.x*blockDim.x + threadIdx.x;
    if (i < BB*NNq) g_invrs[i] = 1.0f / g_rowsum[i];
}

// ---------------- K3c: P16[b][n][m] = exp(m_b[n]m_b[m]) / sum_b' ----------------
__global__ __launch_bounds__(256) void DNL_k3c(){
    size_t tt = ((size_t)blockIdx.x << 8) + threadIdx.x;   // 8.4M
    int n  = (int)(tt >> 11);
    int m0 = (int)((tt & 2047) << 1);
    float a0=g_m[n], a1=g_m[4096+n], a2=g_m[8192+n], a3=g_m[12288+n];
    float p0=g_m[m0],       q0=g_m[m0+1];
    float p1=g_m[4096+m0],  q1=g_m[4097+m0];
    float p2=g_m[8192+m0],  q2=g_m[8193+m0];
    float p3=g_m[12288+m0], q3=g_m[12289+m0];
    float e00=fexp(a0*p0), e01=fexp(a0*q0);
    float e10=fexp(a1*p1), e11=fexp(a1*q1);
    float e20=fexp(a2*p2), e21=fexp(a2*q2);
    float e30=fexp(a3*p3), e31=fexp(a3*q3);
    float s0=e00+e10+e20+e30, s1=e01+e11+e21+e31;
    float r0 = __int_as_float(0x7EF311C3 - __float_as_int(s0));
    r0 = r0*(2.0f-s0*r0); r0 = r0*(2.0f-s0*r0); r0 = r0*(2.0f-s0*r0);
    float r1 = __int_as_float(0x7EF311C3 - __float_as_int(s1));
    r1 = r1*(2.0f-s1*r1); r1 = r1*(2.0f-s1*r1); r1 = r1*(2.0f-s1*r1);
    size_t base = ((size_t)n<<12) + m0;
    *(__half2*)(g_P16 + base)               = __floats2half2_rn(e00*r0, e01*r1);
    *(__half2*)(g_P16 + (1ULL<<24) + base)  = __floats2half2_rn(e10*r0, e11*r1);
    *(__half2*)(g_P16 + (2ULL<<24) + base)  = __floats2half2_rn(e20*r0, e21*r1);
    *(__half2*)(g_P16 + (3ULL<<24) + base)  = __floats2half2_rn(e30*r0, e31*r1);
}

// ---------------- K4r: pipelined fused S -> F(+P16) -> out += V*F ---------------
// grid (b=4 fastest, mt=64), 256 threads, dyn smem 74240 B
#define K4_SQ    0
#define K4_SFH   9216
#define K4_ST0   18432
#define K4_ST1   46336
#define K4_STK   0
#define K4_STV   9216
#define K4_STP   18432
#define K4_SIR   27648
// stage size = 27904

__device__ __forceinline__ void k4_issue_stage(uint32_t dstBase, int b, int nbase,
                                               int mbase, int tid){
    for (int i=tid;i<512;i+=256){
        int r=i>>3, u=i&7;
        CPA16(dstBase + K4_STK + r*144 + u*16,
              g_kTb + ((size_t)(b<<12)+nbase+r)*64 + u*8);
    }
    for (int i=tid;i<512;i+=256){
        int c=i>>3, u=i&7;
        CPA16(dstBase + K4_STV + c*144 + u*16,
              g_vF16 + (((size_t)(b<<6)+c)<<12) + nbase + u*8);
    }
    for (int i=tid;i<512;i+=256){
        int r=i>>3, u=i&7;     // row r = local m; symmetric P -> n contiguous
        CPA16(dstBase + K4_STP + r*144 + u*16,
              g_P16 + ((size_t)b<<24) + ((size_t)(mbase+r)<<12) + nbase + u*8);
    }
    if (tid < 16)
        CPA16(dstBase + K4_SIR + tid*16, g_invrs + (b<<12) + nbase + tid*4);
}

__global__ __launch_bounds__(256,2) void DNL_k4r(float* __restrict__ out){
    extern __shared__ char s4[];
    uint32_t sA = (uint32_t)__cvta_generic_to_shared(s4);
    int b = blockIdx.x, mt = blockIdx.y;
    int mbase = mt<<6;
    int tid = threadIdx.x;
    int w = tid>>5, lane = tid&31, g = lane>>2, t = lane&3;
    int wn = (w&3)<<4;
    int wm = (w>>2)<<5;

    uint32_t aRow = (uint32_t)((wn + (lane&7) + ((lane>>3)&1)*8)*144
                               + ((lane>>4)&1)*16);
    uint32_t bRow = (uint32_t)((wm + (lane&7) + (lane>>4)*8)*144
                               + ((lane>>3)&1)*16);
    uint32_t bQ  = sA + K4_SQ  + bRow;
    uint32_t bFH = sA + K4_SFH + bRow;

    // prologue
    for (int i=tid;i<512;i+=256){
        int r=i>>3, u=i&7;
        CPA16(sA + K4_SQ + r*144 + u*16,
              g_qTb + ((size_t)(b<<12)+mbase+r)*64 + u*8);
    }
    k4_issue_stage(sA + K4_ST0, b, 0, mbase, tid);
    CPCOMMIT();

    float acc2[4][4];
    #pragma unroll
    for (int mc=0;mc<4;mc++){ acc2[mc][0]=0.f; acc2[mc][1]=0.f; acc2[mc][2]=0.f; acc2[mc][3]=0.f; }

    for (int ch=0; ch<64; ch++){
        CPWAIT0();
        __syncthreads();   // data landed; all warps past mma2(ch-1)

        int stgOff = (ch&1) ? K4_ST1 : K4_ST0;
        uint32_t stgA = sA + stgOff;
        if (ch < 63){
            k4_issue_stage(sA + (((ch+1)&1) ? K4_ST1 : K4_ST0), b, (ch+1)<<6, mbase, tid);
            CPCOMMIT();
        }

        // ---- mma1: S = K x Q^T (bf16) ----
        float a1[4][4];
        #pragma unroll
        for (int mc=0;mc<4;mc++){ a1[mc][0]=0.f; a1[mc][1]=0.f; a1[mc][2]=0.f; a1[mc][3]=0.f; }
        uint32_t aK = stgA + K4_STK + aRow;
        #pragma unroll
        for (int k=0;k<4;k++){
            uint32_t af[4], bf0[4], bf1[4];
            ldsm_x4(af,  aK + k*32);
            ldsm_x4(bf0, bQ + k*32);
            ldsm_x4(bf1, bQ + 16*144 + k*32);
            mma16816(a1[0], af, bf0[0], bf0[1]);
            mma16816(a1[1], af, bf0[2], bf0[3]);
            mma16816(a1[2], af, bf1[0], bf1[1]);
            mma16816(a1[3], af, bf1[2], bf1[3]);
        }
        // ---- construct F = fexp(S)*irs + P16 -> FH fp16 [m][n] ----
        const __half* Ps   = (const __half*)(s4 + stgOff + K4_STP);
        const float*  irsS = (const float*)(s4 + stgOff + K4_SIR);
        int nl0 = wn+g, nl1 = nl0+8;
        float ir0 = irsS[nl0], ir1 = irsS[nl1];
        __half* FH = (__half*)(s4+K4_SFH);
        #pragma unroll
        for (int mc=0;mc<4;mc++){
            int ml = wm + mc*8 + 2*t;
            float f0 = fexp(a1[mc][0])*ir0 + __half2float(Ps[ml*72     + nl0]);
            float f1 = fexp(a1[mc][1])*ir0 + __half2float(Ps[(ml+1)*72 + nl0]);
            float f2 = fexp(a1[mc][2])*ir1 + __half2float(Ps[ml*72     + nl1]);
            float f3 = fexp(a1[mc][3])*ir1 + __half2float(Ps[(ml+1)*72 + nl1]);
            FH[ml*72     + nl0] = __float2half_rn(f0);
            FH[(ml+1)*72 + nl0] = __float2half_rn(f1);
            FH[ml*72     + nl1] = __float2half_rn(f2);
            FH[(ml+1)*72 + nl1] = __float2half_rn(f3);
        }
        __syncthreads();   // F visible

        // ---- mma2: acc2 += V16 * FH  (fp16, single pass) ----
        uint32_t aV = stgA + K4_STV + aRow;
        #pragma unroll
        for (int k=0;k<4;k++){
            uint32_t ah[4], bh0[4], bh1[4];
            ldsm_x4(ah,  aV + k*32);
            ldsm_x4(bh0, bFH + k*32);
            ldsm_x4(bh1, bFH + 16*144 + k*32);
            mma16816h(acc2[0], ah, bh0[0], bh0[1]);
            mma16816h(acc2[1], ah, bh0[2], bh0[3]);
            mma16816h(acc2[2], ah, bh1[0], bh1[1]);
            mma16816h(acc2[3], ah, bh1[2], bh1[3]);
        }
    }

    // epilogue: RMW onto BN residual
    #pragma unroll
    for (int mc=0;mc<4;mc++){
        int cg = wn + g;
        int mg = mbase + wm + mc*8 + 2*t;
        float* d0 = out + (((size_t)(b<<6)+cg)<<12) + mg;
        float2 o0 = *(const float2*)d0;
        o0.x += acc2[mc][0]; o0.y += acc2[mc][1];
        *(float2*)d0 = o0;
        float* d1 = out + (((size_t)(b<<6)+cg+8)<<12) + mg;
        float2 o1 = *(const float2*)d1;
        o1.x += acc2[mc][2]; o1.y += acc2[mc][3];
        *(float2*)d1 = o1;
    }
}

// ---------------- host launcher -------------------------------------------------
extern "C" void kernel_launch(void* const* d_in, const int* in_sizes, int n_in,
                              void* d_out, int out_size)
{
    const float* x    = (const float*)d_in[0];
    const float* qw   = (const float*)d_in[1];
    const float* qb   = (const float*)d_in[2];
    const float* kw   = (const float*)d_in[3];
    const float* kb   = (const float*)d_in[4];
    const float* mw   = (const float*)d_in[5];
    const float* mb   = (const float*)d_in[6];
    const float* vw   = (const float*)d_in[7];
    const float* vb   = (const float*)d_in[8];
    const float* ww   = (const float*)d_in[9];
    const float* wb   = (const float*)d_in[10];
    const float* bng  = (const float*)d_in[11];
    const float* bnb  = (const float*)d_in[12];
    const float* bnrm = (const float*)d_in[13];
    const float* bnrv = (const float*)d_in[14];
    float* out = (float*)d_out;

    const int SM1 = 24960*4;
    const int SM3 = 55296;
    const int SM4 = 74240;
    cudaFuncSetAttribute(DNL_k1,  cudaFuncAttributeMaxDynamicSharedMemorySize, SM1);
    cudaFuncSetAttribute(DNL_k3r, cudaFuncAttributeMaxDynamicSharedMemorySize, SM3);
    cudaFuncSetAttribute(DNL_k4r, cudaFuncAttributeMaxDynamicSharedMemorySize, SM4);

    DNL_k0_zero<<<64, 256>>>();
    DNL_k1<<<dim3(32,4), 256, SM1>>>(x, qw,qb, kw,kb, mw,mb, vw,vb, ww,wb,
                                     bng,bnb,bnrm,bnrv, out);
    DNL_k2b<<<dim3(64,4), 256>>>();
    DNL_k3r<<<dim3(4,32,4), 256, SM3>>>();
    DNL_k3b<<<64, 256>>>();
    DNL_k3c<<<32768, 256>>>();
    DNL_k4r<<<dim3(4,64), 256, SM4>>>(out);
}